// round 1
// baseline (speedup 1.0000x reference)
#include <cuda_runtime.h>
#include <math.h>

#define BATCH   128
#define NWIN    16
#define NTOK    512
#define DIM     256
#define NH      8
#define HD      32
#define TABLE_E 3375   // 15^3
#define QKV_LD  768    // 3*DIM

// ---------------- scratch (device globals: allocation-free rule) ----------
__device__ float g_table[TABLE_E * NH];                    // 108 KB
__device__ float g_biasT[NH * NTOK * NTOK];                // 8 MB, layout [h][k][q]
__device__ float g_maskT[NWIN * NTOK * NTOK];              // 16 MB, layout [w][k][q]
__device__ float g_qkv[(size_t)BATCH * NTOK * QKV_LD];     // 201 MB, [b][n][768]
__device__ float g_att[(size_t)BATCH * NTOK * DIM];        // 67 MB,  [b][n][256]

// ---------------- CPB MLP: table[e][h] = sum_o relu(rpb_e . w1_o + b1_o)*w2[h][o]
__global__ void cpb_kernel(const float* __restrict__ rpb,
                           const float* __restrict__ w1,
                           const float* __restrict__ b1,
                           const float* __restrict__ w2) {
    int e = blockIdx.x;                 // 0..3374
    int h = threadIdx.x >> 5;           // warp -> head (block = 256 thr = 8 warps)
    int lane = threadIdx.x & 31;
    float r0 = rpb[e * 3 + 0], r1 = rpb[e * 3 + 1], r2 = rpb[e * 3 + 2];
    float sum = 0.f;
    for (int o = lane; o < 512; o += 32) {
        float hid = fmaf(r0, w1[o * 3 + 0],
                    fmaf(r1, w1[o * 3 + 1],
                    fmaf(r2, w1[o * 3 + 2], b1[o])));
        hid = fmaxf(hid, 0.f);
        sum = fmaf(hid, w2[h * 512 + o], sum);
    }
    #pragma unroll
    for (int off = 16; off; off >>= 1)
        sum += __shfl_xor_sync(0xffffffffu, sum, off);
    if (lane == 0) g_table[e * NH + h] = sum;
}

// ---------------- bias gather: g_biasT[h][k][q] = 16*sigmoid(table[rpb_idx[q][k]][h])
__global__ void bias_kernel(const int* __restrict__ rpb_idx) {
    int t = blockIdx.x * blockDim.x + threadIdx.x;   // t = k*512 + q
    if (t >= NTOK * NTOK) return;
    int q = t & (NTOK - 1);
    int k = t >> 9;
    int idx = rpb_idx[q * NTOK + k];
    #pragma unroll
    for (int h = 0; h < NH; h++) {
        float v = g_table[idx * NH + h];
        float sig = 1.f / (1.f + __expf(-v));
        g_biasT[(size_t)h * NTOK * NTOK + t] = 16.f * sig;
    }
}

// ---------------- mask transpose: g_maskT[w][k][q] = mask[w][q][k]
__global__ void mask_transpose_kernel(const float* __restrict__ mask) {
    __shared__ float tile[32][33];
    int w = blockIdx.z;
    int q0 = blockIdx.y * 32, k0 = blockIdx.x * 32;
    int tx = threadIdx.x, ty = threadIdx.y;   // 32 x 8
    const float* src = mask + (size_t)w * NTOK * NTOK;
    float* dst = g_maskT + (size_t)w * NTOK * NTOK;
    #pragma unroll
    for (int i = ty; i < 32; i += 8)
        tile[i][tx] = src[(q0 + i) * NTOK + k0 + tx];
    __syncthreads();
    #pragma unroll
    for (int i = ty; i < 32; i += 8)
        dst[(k0 + i) * NTOK + q0 + tx] = tile[tx][i];
}

// ---------------- SGEMM NT: C[M,N] = A[M,K] * B[N,K]^T (+bias[N])
// BM=BN=128, BK=8, 256 threads, 8x8 microtile
__global__ __launch_bounds__(256) void sgemm_nt(const float* __restrict__ A,
                                                const float* __restrict__ B,
                                                const float* __restrict__ bias,
                                                float* __restrict__ C,
                                                int M, int N, int K, int use_bias) {
    __shared__ float As[8][132];
    __shared__ float Bs[8][132];
    const int tid = threadIdx.x;
    const int tx = tid & 15;        // col group
    const int ty = tid >> 4;        // row group
    const int row0 = blockIdx.y * 128;
    const int col0 = blockIdx.x * 128;
    const int lrow = tid >> 1;            // 0..127
    const int lcol = (tid & 1) * 4;       // 0 or 4
    const float* Ap = A + (size_t)(row0 + lrow) * K + lcol;
    const float* Bp = B + (size_t)(col0 + lrow) * K + lcol;

    float acc[8][8];
    #pragma unroll
    for (int i = 0; i < 8; i++)
        #pragma unroll
        for (int j = 0; j < 8; j++) acc[i][j] = 0.f;

    for (int k0 = 0; k0 < K; k0 += 8) {
        float4 av = *(const float4*)(Ap + k0);
        float4 bv = *(const float4*)(Bp + k0);
        As[lcol + 0][lrow] = av.x; As[lcol + 1][lrow] = av.y;
        As[lcol + 2][lrow] = av.z; As[lcol + 3][lrow] = av.w;
        Bs[lcol + 0][lrow] = bv.x; Bs[lcol + 1][lrow] = bv.y;
        Bs[lcol + 2][lrow] = bv.z; Bs[lcol + 3][lrow] = bv.w;
        __syncthreads();
        #pragma unroll
        for (int kk = 0; kk < 8; kk++) {
            float a[8], b[8];
            #pragma unroll
            for (int i = 0; i < 4; i++) {
                a[i]     = As[kk][ty * 4 + i];
                a[4 + i] = As[kk][64 + ty * 4 + i];
            }
            #pragma unroll
            for (int j = 0; j < 4; j++) {
                b[j]     = Bs[kk][tx * 4 + j];
                b[4 + j] = Bs[kk][64 + tx * 4 + j];
            }
            #pragma unroll
            for (int i = 0; i < 8; i++)
                #pragma unroll
                for (int j = 0; j < 8; j++)
                    acc[i][j] = fmaf(a[i], b[j], acc[i][j]);
        }
        __syncthreads();
    }

    #pragma unroll
    for (int i = 0; i < 8; i++) {
        int r = row0 + ((i < 4) ? (ty * 4 + i) : (64 + ty * 4 + (i - 4)));
        #pragma unroll
        for (int jj = 0; jj < 2; jj++) {
            int c = col0 + ((jj == 0) ? (tx * 4) : (64 + tx * 4));
            float4 v;
            v.x = acc[i][jj * 4 + 0]; v.y = acc[i][jj * 4 + 1];
            v.z = acc[i][jj * 4 + 2]; v.w = acc[i][jj * 4 + 3];
            if (use_bias) {
                v.x += bias[c + 0]; v.y += bias[c + 1];
                v.z += bias[c + 2]; v.w += bias[c + 3];
            }
            *(float4*)(C + (size_t)r * N + c) = v;
        }
    }
}

// ---------------- attention: one block per (h, b), 512 threads, 1 q-row/thread
__global__ __launch_bounds__(512, 1) void attn_kernel() {
    extern __shared__ float smem[];
    float4* K4 = (float4*)smem;          // 512 keys x 8 float4
    float4* V4 = K4 + NTOK * 8;
    const int h = blockIdx.x;
    const int b = blockIdx.y;
    const int tid = threadIdx.x;
    const float* qkv_base = g_qkv + (size_t)b * NTOK * QKV_LD;

    // stage K, V for this (b, h)
    for (int i = tid; i < NTOK * 8; i += 512) {
        int j = i >> 3, c = i & 7;
        K4[i] = *(const float4*)(qkv_base + (size_t)j * QKV_LD + DIM     + h * HD + c * 4);
        V4[i] = *(const float4*)(qkv_base + (size_t)j * QKV_LD + 2 * DIM + h * HD + c * 4);
    }
    __syncthreads();

    const int r = tid;  // q row
    float4 q4[8];
    const float* qp = qkv_base + (size_t)r * QKV_LD + h * HD;
    #pragma unroll
    for (int c = 0; c < 8; c++) q4[c] = *(const float4*)(qp + c * 4);

    const float* bias_col = g_biasT + (size_t)h * NTOK * NTOK + r;          // +j*512
    const float* mask_col = g_maskT + (size_t)(b & (NWIN - 1)) * NTOK * NTOK + r;
    const float scale = 0.17677669529663687f;  // 1/sqrt(32)

    float m = -1e30f, l = 0.f;
    float acc[32];
    #pragma unroll
    for (int d = 0; d < 32; d++) acc[d] = 0.f;

    for (int j = 0; j < NTOK; j++) {
        const float4* kj = K4 + j * 8;
        float s0 = 0.f, s1 = 0.f, s2 = 0.f, s3 = 0.f;
        #pragma unroll
        for (int c = 0; c < 8; c++) {
            float4 kv = kj[c];
            s0 = fmaf(q4[c].x, kv.x, s0);
            s1 = fmaf(q4[c].y, kv.y, s1);
            s2 = fmaf(q4[c].z, kv.z, s2);
            s3 = fmaf(q4[c].w, kv.w, s3);
        }
        float s = (s0 + s1) + (s2 + s3);
        s = fmaf(s, scale, bias_col[j * NTOK] + mask_col[j * NTOK]);

        float p;
        if (s > m) {
            float corr = __expf(m - s);
            m = s;
            l = fmaf(l, corr, 1.f);
            p = 1.f;
            #pragma unroll
            for (int d = 0; d < 32; d++) acc[d] *= corr;
        } else {
            p = __expf(s - m);
            l += p;
        }
        const float4* vj = V4 + j * 8;
        #pragma unroll
        for (int c = 0; c < 8; c++) {
            float4 vv = vj[c];
            acc[c * 4 + 0] = fmaf(p, vv.x, acc[c * 4 + 0]);
            acc[c * 4 + 1] = fmaf(p, vv.y, acc[c * 4 + 1]);
            acc[c * 4 + 2] = fmaf(p, vv.z, acc[c * 4 + 2]);
            acc[c * 4 + 3] = fmaf(p, vv.w, acc[c * 4 + 3]);
        }
    }

    float inv = 1.f / l;
    float* op = g_att + ((size_t)b * NTOK + r) * DIM + h * HD;
    #pragma unroll
    for (int c = 0; c < 8; c++) {
        float4 o;
        o.x = acc[c * 4 + 0] * inv; o.y = acc[c * 4 + 1] * inv;
        o.z = acc[c * 4 + 2] * inv; o.w = acc[c * 4 + 3] * inv;
        *(float4*)(op + c * 4) = o;
    }
}

// ---------------- launch ----------------
extern "C" void kernel_launch(void* const* d_in, const int* in_sizes, int n_in,
                              void* d_out, int out_size) {
    const float* x      = (const float*)d_in[0];
    const float* mask   = (const float*)d_in[1];
    const float* qkv_w  = (const float*)d_in[2];
    const float* proj_w = (const float*)d_in[3];
    const float* proj_b = (const float*)d_in[4];
    const float* cpb_w1 = (const float*)d_in[5];
    const float* cpb_b1 = (const float*)d_in[6];
    const float* cpb_w2 = (const float*)d_in[7];
    const float* rpb    = (const float*)d_in[8];
    const int*   rpb_idx = (const int*)d_in[9];
    float* out = (float*)d_out;

    // resolve device-global addresses for GEMM in/out
    static float* p_qkv = nullptr;
    static float* p_att = nullptr;
    if (!p_qkv) {
        cudaGetSymbolAddress((void**)&p_qkv, g_qkv);
        cudaGetSymbolAddress((void**)&p_att, g_att);
        cudaFuncSetAttribute(attn_kernel,
                             cudaFuncAttributeMaxDynamicSharedMemorySize,
                             NTOK * HD * 2 * (int)sizeof(float));  // 128 KB
    }

    // 1) CPB table
    cpb_kernel<<<TABLE_E, 256>>>(rpb, cpb_w1, cpb_b1, cpb_w2);
    // 2) bias gather (transposed layout)
    bias_kernel<<<(NTOK * NTOK + 255) / 256, 256>>>(rpb_idx);
    // 3) mask transpose
    mask_transpose_kernel<<<dim3(16, 16, NWIN), dim3(32, 8)>>>(mask);
    // 4) QKV projection: (B*N, 256) x (768, 256)^T -> g_qkv
    {
        dim3 grid(QKV_LD / 128, (BATCH * NTOK) / 128);
        sgemm_nt<<<grid, 256>>>(x, qkv_w, nullptr, p_qkv,
                                BATCH * NTOK, QKV_LD, DIM, 0);
    }
    // 5) attention
    attn_kernel<<<dim3(NH, BATCH), 512, NTOK * HD * 2 * sizeof(float)>>>();
    // 6) output projection: (B*N, 256) x (256, 256)^T + b -> d_out
    {
        dim3 grid(DIM / 128, (BATCH * NTOK) / 128);
        sgemm_nt<<<grid, 256>>>(p_att, proj_w, proj_b, out,
                                BATCH * NTOK, DIM, DIM, 1);
    }
}

// round 3
// speedup vs baseline: 2.3600x; 2.3600x over previous
#include <cuda_runtime.h>
#include <cuda_fp16.h>
#include <math.h>
#include <stdint.h>

#define BATCH   128
#define NWIN    16
#define NTOK    512
#define DIM     256
#define NH      8
#define HD      32
#define TABLE_E 3375   // 15^3
#define QKV_LD  768    // 3*DIM
#define NN      (NTOK*NTOK)

// ---------------- scratch (device globals: allocation-free rule) ----------
__device__ float g_table[TABLE_E * NH];                    // 108 KB
__device__ float g_biasT[NH * NTOK * NTOK];                // 8 MB, layout [h][k][q]
__device__ float g_maskT[NWIN * NTOK * NTOK];              // 16 MB, layout [w][k][q]
__device__ float g_qkv[(size_t)BATCH * NTOK * QKV_LD];     // 201 MB, [b][n][768]
__device__ float g_att[(size_t)BATCH * NTOK * DIM];        // 67 MB,  [b][n][256]

// =====================  mma helpers (legacy mma.sync — compiles on sm_100) ===
__device__ __forceinline__ float to_tf32(float x) {
    uint32_t u;
    asm("cvt.rna.tf32.f32 %0, %1;" : "=r"(u) : "f"(x));
    return __uint_as_float(u);
}
__device__ __forceinline__ void mma_tf32(float* d, const float* a, float b0, float b1) {
    asm volatile(
        "mma.sync.aligned.m16n8k8.row.col.f32.tf32.tf32.f32 "
        "{%0,%1,%2,%3}, {%4,%5,%6,%7}, {%8,%9}, {%0,%1,%2,%3};"
        : "+f"(d[0]), "+f"(d[1]), "+f"(d[2]), "+f"(d[3])
        : "r"(__float_as_uint(a[0])), "r"(__float_as_uint(a[1])),
          "r"(__float_as_uint(a[2])), "r"(__float_as_uint(a[3])),
          "r"(__float_as_uint(b0)),   "r"(__float_as_uint(b1)));
}
__device__ __forceinline__ void mma_f16(float* d, const uint32_t* a,
                                        uint32_t b0, uint32_t b1) {
    asm volatile(
        "mma.sync.aligned.m16n8k16.row.col.f32.f16.f16.f32 "
        "{%0,%1,%2,%3}, {%4,%5,%6,%7}, {%8,%9}, {%0,%1,%2,%3};"
        : "+f"(d[0]), "+f"(d[1]), "+f"(d[2]), "+f"(d[3])
        : "r"(a[0]), "r"(a[1]), "r"(a[2]), "r"(a[3]), "r"(b0), "r"(b1));
}
__device__ __forceinline__ uint32_t pack_half2(float lo, float hi) {
    __half2 h = __floats2half2_rn(lo, hi);   // .x = lo (low half)
    return *(uint32_t*)&h;
}

// =====================  tf32 mma GEMM (NT): C[M,N] = A[M,K]*B[N,K]^T (+bias) ===
// 128x128 tile, BK=16, 256 threads (8 warps, 4x2), warp tile 32x64
__global__ __launch_bounds__(256, 2) void tc_gemm_mma(const float* __restrict__ A,
                                                      const float* __restrict__ B,
                                                      const float* __restrict__ bias,
                                                      float* __restrict__ C,
                                                      int M, int N, int K, int use_bias) {
    __shared__ float As[16][132];
    __shared__ float Bs[16][132];
    const int tid = threadIdx.x;
    const int wid = tid >> 5, lane = tid & 31;
    const int g = lane >> 2, t = lane & 3;
    const int wm = wid & 3, wn = wid >> 2;
    const int row0 = blockIdx.y * 128;
    const int col0 = blockIdx.x * 128;
    const int lrow = tid >> 1;
    const int lk = (tid & 1) * 4;

    const float* Ap = A + (size_t)(row0 + lrow) * K + lk;
    const float* Bp = B + (size_t)(col0 + lrow) * K + lk;

    float acc[2][8][4];
    #pragma unroll
    for (int mt = 0; mt < 2; mt++)
        #pragma unroll
        for (int jn = 0; jn < 8; jn++)
            #pragma unroll
            for (int r = 0; r < 4; r++) acc[mt][jn][r] = 0.f;

    float4 a0v = *(const float4*)(Ap + 0);
    float4 a1v = *(const float4*)(Ap + 8);
    float4 b0v = *(const float4*)(Bp + 0);
    float4 b1v = *(const float4*)(Bp + 8);

    for (int k0 = 0; k0 < K; k0 += 16) {
        As[lk + 0][lrow] = to_tf32(a0v.x); As[lk + 1][lrow] = to_tf32(a0v.y);
        As[lk + 2][lrow] = to_tf32(a0v.z); As[lk + 3][lrow] = to_tf32(a0v.w);
        As[lk + 8][lrow] = to_tf32(a1v.x); As[lk + 9][lrow] = to_tf32(a1v.y);
        As[lk +10][lrow] = to_tf32(a1v.z); As[lk +11][lrow] = to_tf32(a1v.w);
        Bs[lk + 0][lrow] = to_tf32(b0v.x); Bs[lk + 1][lrow] = to_tf32(b0v.y);
        Bs[lk + 2][lrow] = to_tf32(b0v.z); Bs[lk + 3][lrow] = to_tf32(b0v.w);
        Bs[lk + 8][lrow] = to_tf32(b1v.x); Bs[lk + 9][lrow] = to_tf32(b1v.y);
        Bs[lk +10][lrow] = to_tf32(b1v.z); Bs[lk +11][lrow] = to_tf32(b1v.w);
        __syncthreads();

        if (k0 + 16 < K) {
            a0v = *(const float4*)(Ap + k0 + 16);
            a1v = *(const float4*)(Ap + k0 + 24);
            b0v = *(const float4*)(Bp + k0 + 16);
            b1v = *(const float4*)(Bp + k0 + 24);
        }

        #pragma unroll
        for (int kk = 0; kk < 2; kk++) {
            float af[2][4];
            #pragma unroll
            for (int mt = 0; mt < 2; mt++) {
                int mr = wm * 32 + mt * 16;
                af[mt][0] = As[kk * 8 + t    ][mr + g];
                af[mt][1] = As[kk * 8 + t    ][mr + g + 8];
                af[mt][2] = As[kk * 8 + t + 4][mr + g];
                af[mt][3] = As[kk * 8 + t + 4][mr + g + 8];
            }
            float bf[8][2];
            #pragma unroll
            for (int jn = 0; jn < 8; jn++) {
                int nc = wn * 64 + jn * 8;
                bf[jn][0] = Bs[kk * 8 + t    ][nc + g];
                bf[jn][1] = Bs[kk * 8 + t + 4][nc + g];
            }
            #pragma unroll
            for (int mt = 0; mt < 2; mt++)
                #pragma unroll
                for (int jn = 0; jn < 8; jn++)
                    mma_tf32(acc[mt][jn], af[mt], bf[jn][0], bf[jn][1]);
        }
        __syncthreads();
    }

    #pragma unroll
    for (int mt = 0; mt < 2; mt++) {
        int r = row0 + wm * 32 + mt * 16;
        #pragma unroll
        for (int jn = 0; jn < 8; jn++) {
            int cc = col0 + wn * 64 + jn * 8 + 2 * t;
            float bx = 0.f, by = 0.f;
            if (use_bias) { bx = bias[cc]; by = bias[cc + 1]; }
            float2 v0 = { acc[mt][jn][0] + bx, acc[mt][jn][1] + by };
            float2 v1 = { acc[mt][jn][2] + bx, acc[mt][jn][3] + by };
            *(float2*)(C + (size_t)(r + g) * N + cc) = v0;
            *(float2*)(C + (size_t)(r + g + 8) * N + cc) = v1;
        }
    }
}

// =====================  fused mma attention ==============================
// block = (q-tile of 128, h, b); 8 warps x 16 q rows; K-chunks of 64 keys
__global__ __launch_bounds__(256, 2) void attn_mma_kernel() {
    __shared__ __align__(16) float Ks[64][36];     // keys x dims, tf32 bits
    __shared__ __align__(16) __half Vt[32][72];    // dims x keys, fp16
    const int qt = blockIdx.x, h = blockIdx.y, b = blockIdx.z;
    const int tid = threadIdx.x, wid = tid >> 5, lane = tid & 31;
    const int g = lane >> 2, t = lane & 3;
    const int q0 = qt * 128 + wid * 16;
    const float* base = g_qkv + (size_t)b * NTOK * QKV_LD;
    const float SCALE = 0.17677669529663687f;  // 1/sqrt(32)

    // Q fragments (scaled, tf32), 4 k-tiles of 8 dims
    float qa[4][4];
    {
        const float* q0p = base + (size_t)(q0 + g) * QKV_LD + h * HD;
        const float* q8p = q0p + 8 * QKV_LD;
        #pragma unroll
        for (int kt = 0; kt < 4; kt++) {
            qa[kt][0] = to_tf32(q0p[kt * 8 + t    ] * SCALE);
            qa[kt][1] = to_tf32(q8p[kt * 8 + t    ] * SCALE);
            qa[kt][2] = to_tf32(q0p[kt * 8 + t + 4] * SCALE);
            qa[kt][3] = to_tf32(q8p[kt * 8 + t + 4] * SCALE);
        }
    }

    float o[4][4];
    #pragma unroll
    for (int nd = 0; nd < 4; nd++)
        #pragma unroll
        for (int r = 0; r < 4; r++) o[nd][r] = 0.f;
    float m0 = -1e30f, m1 = -1e30f, l0 = 0.f, l1 = 0.f;

    const float* bias_h = g_biasT + (size_t)h * NN;
    const float* mask_w = g_maskT + (size_t)(b & (NWIN - 1)) * NN;

    for (int j0 = 0; j0 < NTOK; j0 += 64) {
        __syncthreads();
        // stage K chunk (tf32) and V chunk (fp16, transposed)
        #pragma unroll
        for (int it = 0; it < 2; it++) {
            int i = tid + it * 256;           // 0..511
            int key = i >> 3, d4 = (i & 7) * 4;
            const float* kp = base + (size_t)(j0 + key) * QKV_LD + DIM + h * HD + d4;
            float4 kv = *(const float4*)kp;
            Ks[key][d4 + 0] = to_tf32(kv.x);
            Ks[key][d4 + 1] = to_tf32(kv.y);
            Ks[key][d4 + 2] = to_tf32(kv.z);
            Ks[key][d4 + 3] = to_tf32(kv.w);
            float4 vv = *(const float4*)(kp + DIM);
            Vt[d4 + 0][key] = __float2half(vv.x);
            Vt[d4 + 1][key] = __float2half(vv.y);
            Vt[d4 + 2][key] = __float2half(vv.z);
            Vt[d4 + 3][key] = __float2half(vv.w);
        }
        __syncthreads();

        // S = Q K^T + bias + mask  (8 n-tiles of 8 keys)
        float s[8][4];
        #pragma unroll
        for (int jn = 0; jn < 8; jn++) {
            s[jn][0] = s[jn][1] = s[jn][2] = s[jn][3] = 0.f;
            #pragma unroll
            for (int kt = 0; kt < 4; kt++) {
                float b0 = Ks[jn * 8 + g][kt * 8 + t];
                float b1 = Ks[jn * 8 + g][kt * 8 + t + 4];
                mma_tf32(s[jn], qa[kt], b0, b1);
            }
            size_t krow = (size_t)(j0 + jn * 8 + 2 * t) * NTOK;
            const float* bp = bias_h + krow;
            const float* mp = mask_w + krow;
            s[jn][0] += bp[q0 + g]            + mp[q0 + g];
            s[jn][1] += bp[NTOK + q0 + g]     + mp[NTOK + q0 + g];
            s[jn][2] += bp[q0 + g + 8]        + mp[q0 + g + 8];
            s[jn][3] += bp[NTOK + q0 + g + 8] + mp[NTOK + q0 + g + 8];
        }

        // chunk row-max, online rescale
        float mx0 = s[0][0], mx1 = s[0][2];
        #pragma unroll
        for (int jn = 0; jn < 8; jn++) {
            mx0 = fmaxf(mx0, fmaxf(s[jn][0], s[jn][1]));
            mx1 = fmaxf(mx1, fmaxf(s[jn][2], s[jn][3]));
        }
        mx0 = fmaxf(mx0, __shfl_xor_sync(0xffffffffu, mx0, 1));
        mx0 = fmaxf(mx0, __shfl_xor_sync(0xffffffffu, mx0, 2));
        mx1 = fmaxf(mx1, __shfl_xor_sync(0xffffffffu, mx1, 1));
        mx1 = fmaxf(mx1, __shfl_xor_sync(0xffffffffu, mx1, 2));
        float nm0 = fmaxf(m0, mx0), nm1 = fmaxf(m1, mx1);
        float c0 = __expf(m0 - nm0), c1 = __expf(m1 - nm1);
        m0 = nm0; m1 = nm1;
        l0 *= c0;  l1 *= c1;
        #pragma unroll
        for (int nd = 0; nd < 4; nd++) {
            o[nd][0] *= c0; o[nd][1] *= c0;
            o[nd][2] *= c1; o[nd][3] *= c1;
        }

        // P = exp(S - m), pack to fp16 A-fragments (4 k16-tiles)
        uint32_t pa[4][4];
        #pragma unroll
        for (int j2 = 0; j2 < 4; j2++) {
            float pA0 = __expf(s[2*j2][0] - m0), pA1 = __expf(s[2*j2][1] - m0);
            float pA2 = __expf(s[2*j2][2] - m1), pA3 = __expf(s[2*j2][3] - m1);
            float pB0 = __expf(s[2*j2+1][0] - m0), pB1 = __expf(s[2*j2+1][1] - m0);
            float pB2 = __expf(s[2*j2+1][2] - m1), pB3 = __expf(s[2*j2+1][3] - m1);
            l0 += (pA0 + pA1) + (pB0 + pB1);
            l1 += (pA2 + pA3) + (pB2 + pB3);
            pa[j2][0] = pack_half2(pA0, pA1);
            pa[j2][1] = pack_half2(pA2, pA3);
            pa[j2][2] = pack_half2(pB0, pB1);
            pa[j2][3] = pack_half2(pB2, pB3);
        }

        // O += P V  (4 dim n-tiles x 4 key k-tiles)
        const uint32_t* Vt32 = (const uint32_t*)&Vt[0][0];
        #pragma unroll
        for (int nd = 0; nd < 4; nd++)
            #pragma unroll
            for (int j2 = 0; j2 < 4; j2++) {
                uint32_t b0 = Vt32[(nd * 8 + g) * 36 + j2 * 8 + t];
                uint32_t b1 = Vt32[(nd * 8 + g) * 36 + j2 * 8 + t + 4];
                mma_f16(o[nd], pa[j2], b0, b1);
            }
    }

    // reduce l across the 4-lane group, normalize, store
    l0 += __shfl_xor_sync(0xffffffffu, l0, 1);
    l0 += __shfl_xor_sync(0xffffffffu, l0, 2);
    l1 += __shfl_xor_sync(0xffffffffu, l1, 1);
    l1 += __shfl_xor_sync(0xffffffffu, l1, 2);
    float i0 = 1.f / l0, i1 = 1.f / l1;
    float* op0 = g_att + ((size_t)b * NTOK + q0 + g) * DIM + h * HD;
    float* op8 = op0 + 8 * DIM;
    #pragma unroll
    for (int nd = 0; nd < 4; nd++) {
        float2 v0 = { o[nd][0] * i0, o[nd][1] * i0 };
        float2 v1 = { o[nd][2] * i1, o[nd][3] * i1 };
        *(float2*)(op0 + nd * 8 + 2 * t) = v0;
        *(float2*)(op8 + nd * 8 + 2 * t) = v1;
    }
}

// ---------------- CPB MLP ----------------
__global__ void cpb_kernel(const float* __restrict__ rpb,
                           const float* __restrict__ w1,
                           const float* __restrict__ b1,
                           const float* __restrict__ w2) {
    int e = blockIdx.x;
    int h = threadIdx.x >> 5;
    int lane = threadIdx.x & 31;
    float r0 = rpb[e * 3 + 0], r1 = rpb[e * 3 + 1], r2 = rpb[e * 3 + 2];
    float sum = 0.f;
    for (int o = lane; o < 512; o += 32) {
        float hid = fmaf(r0, w1[o * 3 + 0],
                    fmaf(r1, w1[o * 3 + 1],
                    fmaf(r2, w1[o * 3 + 2], b1[o])));
        hid = fmaxf(hid, 0.f);
        sum = fmaf(hid, w2[h * 512 + o], sum);
    }
    #pragma unroll
    for (int off = 16; off; off >>= 1)
        sum += __shfl_xor_sync(0xffffffffu, sum, off);
    if (lane == 0) g_table[e * NH + h] = sum;
}

// ---------------- bias gather (transposed) ----------------
__global__ void bias_kernel(const int* __restrict__ rpb_idx) {
    int tt = blockIdx.x * blockDim.x + threadIdx.x;   // t = k*512 + q
    if (tt >= NN) return;
    int q = tt & (NTOK - 1);
    int k = tt >> 9;
    int idx = rpb_idx[q * NTOK + k];
    #pragma unroll
    for (int h = 0; h < NH; h++) {
        float v = g_table[idx * NH + h];
        float sig = 1.f / (1.f + __expf(-v));
        g_biasT[(size_t)h * NN + tt] = 16.f * sig;
    }
}

// ---------------- mask transpose ----------------
__global__ void mask_transpose_kernel(const float* __restrict__ mask) {
    __shared__ float tile[32][33];
    int w = blockIdx.z;
    int q0 = blockIdx.y * 32, k0 = blockIdx.x * 32;
    int tx = threadIdx.x, ty = threadIdx.y;
    const float* src = mask + (size_t)w * NN;
    float* dst = g_maskT + (size_t)w * NN;
    #pragma unroll
    for (int i = ty; i < 32; i += 8)
        tile[i][tx] = src[(q0 + i) * NTOK + k0 + tx];
    __syncthreads();
    #pragma unroll
    for (int i = ty; i < 32; i += 8)
        dst[(k0 + i) * NTOK + q0 + tx] = tile[tx][i];
}

// ---------------- launch ----------------
extern "C" void kernel_launch(void* const* d_in, const int* in_sizes, int n_in,
                              void* d_out, int out_size) {
    const float* x      = (const float*)d_in[0];
    const float* mask   = (const float*)d_in[1];
    const float* qkv_w  = (const float*)d_in[2];
    const float* proj_w = (const float*)d_in[3];
    const float* proj_b = (const float*)d_in[4];
    const float* cpb_w1 = (const float*)d_in[5];
    const float* cpb_b1 = (const float*)d_in[6];
    const float* cpb_w2 = (const float*)d_in[7];
    const float* rpb    = (const float*)d_in[8];
    const int*   rpb_idx = (const int*)d_in[9];
    float* out = (float*)d_out;

    static float* p_qkv = nullptr;
    static float* p_att = nullptr;
    if (!p_qkv) {
        cudaGetSymbolAddress((void**)&p_qkv, g_qkv);
        cudaGetSymbolAddress((void**)&p_att, g_att);
    }

    // 1) CPB table
    cpb_kernel<<<TABLE_E, 256>>>(rpb, cpb_w1, cpb_b1, cpb_w2);
    // 2) bias gather (transposed layout)
    bias_kernel<<<(NN + 255) / 256, 256>>>(rpb_idx);
    // 3) mask transpose
    mask_transpose_kernel<<<dim3(16, 16, NWIN), dim3(32, 8)>>>(mask);
    // 4) QKV projection (tf32 mma): (B*N,256) x (768,256)^T -> g_qkv
    {
        dim3 grid(QKV_LD / 128, (BATCH * NTOK) / 128);
        tc_gemm_mma<<<grid, 256>>>(x, qkv_w, nullptr, p_qkv,
                                   BATCH * NTOK, QKV_LD, DIM, 0);
    }
    // 5) fused mma attention
    attn_mma_kernel<<<dim3(NTOK / 128, NH, BATCH), 256>>>();
    // 6) output projection (tf32 mma) + bias -> d_out
    {
        dim3 grid(DIM / 128, (BATCH * NTOK) / 128);
        tc_gemm_mma<<<grid, 256>>>(p_att, proj_w, proj_b, out,
                                   BATCH * NTOK, DIM, DIM, 1);
    }
}

// round 5
// speedup vs baseline: 4.3140x; 1.8279x over previous
#include <cuda_runtime.h>
#include <cuda_fp16.h>
#include <math.h>
#include <stdint.h>

#define BATCH   128
#define NWIN    16
#define NTOK    512
#define DIM     256
#define NH      8
#define HD      32
#define TABLE_E 3375
#define QKV_LD  768
#define NN      (NTOK*NTOK)

// ---------------- scratch (device globals) ----------------
__device__ float  g_table[TABLE_E * NH];
__device__ float  g_maskT[NWIN * NN];                       // [w][k][q] fp32, 16 MB
__device__ float  g_comb[(size_t)NH * NWIN * NN];           // [h][w][k][q] fp32, 128 MB
__device__ __half g_xh[(size_t)BATCH * NTOK * DIM];         // x fp16
__device__ __half g_qkvw[QKV_LD * DIM];
__device__ __half g_projw[DIM * DIM];
__device__ __half g_qkv[(size_t)BATCH * NTOK * QKV_LD];     // qkv fp16, 100 MB
__device__ __half g_att[(size_t)BATCH * NTOK * DIM];        // att fp16

// =====================  helpers  =====================
__device__ __forceinline__ uint32_t pack_half2(float lo, float hi) {
    __half2 h = __floats2half2_rn(lo, hi);
    return *(uint32_t*)&h;
}
__device__ __forceinline__ void mma_f16(float* d, const uint32_t* a,
                                        uint32_t b0, uint32_t b1) {
    asm volatile(
        "mma.sync.aligned.m16n8k16.row.col.f32.f16.f16.f32 "
        "{%0,%1,%2,%3}, {%4,%5,%6,%7}, {%8,%9}, {%0,%1,%2,%3};"
        : "+f"(d[0]), "+f"(d[1]), "+f"(d[2]), "+f"(d[3])
        : "r"(a[0]), "r"(a[1]), "r"(a[2]), "r"(a[3]), "r"(b0), "r"(b1));
}
__device__ __forceinline__ void ldsm4(uint32_t* r, uint32_t addr) {
    asm volatile("ldmatrix.sync.aligned.m8n8.x4.shared.b16 {%0,%1,%2,%3}, [%4];"
                 : "=r"(r[0]), "=r"(r[1]), "=r"(r[2]), "=r"(r[3]) : "r"(addr));
}
__device__ __forceinline__ void ldsm4t(uint32_t* r, uint32_t addr) {
    asm volatile("ldmatrix.sync.aligned.m8n8.x4.trans.shared.b16 {%0,%1,%2,%3}, [%4];"
                 : "=r"(r[0]), "=r"(r[1]), "=r"(r[2]), "=r"(r[3]) : "r"(addr));
}
__device__ __forceinline__ uint32_t cvta_s(const void* p) {
    return (uint32_t)__cvta_generic_to_shared(p);
}
// swizzled byte offset in a [rows][32] fp16 tile (64B rows, 4x16B chunks)
__device__ __forceinline__ uint32_t swz(int r, int kchunk) {
    return (uint32_t)(r * 64 + ((kchunk ^ ((r >> 1) & 3)) << 4));
}

// ---------------- fp32 -> fp16 conversion (8 elems/thread) ----------------
__global__ void cvt_h8(const float* __restrict__ s, __half* __restrict__ d, int n8) {
    int i = blockIdx.x * blockDim.x + threadIdx.x;
    if (i >= n8) return;
    const float4* sp = (const float4*)s + (size_t)i * 2;
    float4 a = sp[0], b = sp[1];
    uint4 o;
    o.x = pack_half2(a.x, a.y); o.y = pack_half2(a.z, a.w);
    o.z = pack_half2(b.x, b.y); o.w = pack_half2(b.z, b.w);
    ((uint4*)d)[i] = o;
}

// =====================  fp16 mma GEMM (NT): C = A[M,K] * B[N,K]^T  =====
// BM=BN=128, BK=32, 256 thr (8 warps 4x2), warp tile 32x64, ldmatrix feeds
__global__ __launch_bounds__(256, 2) void gemm_h(const __half* __restrict__ A,
                                                 const __half* __restrict__ B,
                                                 const float* __restrict__ bias,
                                                 void* __restrict__ Cv,
                                                 int M, int N, int K, int fp32out) {
    __shared__ __align__(16) __half sA[2][128 * 32];
    __shared__ __align__(16) __half sB[2][128 * 32];
    const int tid = threadIdx.x, lane = tid & 31, wid = tid >> 5;
    const int g = lane >> 2, t = lane & 3;
    const int wm = wid & 3, wn = wid >> 2;
    const int row0 = blockIdx.y * 128, col0 = blockIdx.x * 128;

    const int lr = tid >> 2, lc = tid & 3;
    const __half* Ap = A + (size_t)(row0 + lr) * K + lc * 8;
    const __half* Bp = B + (size_t)(col0 + lr) * K + lc * 8;
    const size_t rstep = (size_t)64 * K;
    const uint32_t so0 = swz(lr, lc), so1 = swz(lr + 64, lc);

    float acc[2][8][4];
    #pragma unroll
    for (int mt = 0; mt < 2; mt++)
        #pragma unroll
        for (int jn = 0; jn < 8; jn++)
            #pragma unroll
            for (int r = 0; r < 4; r++) acc[mt][jn][r] = 0.f;

    uint4 va0 = *(const uint4*)(Ap);
    uint4 va1 = *(const uint4*)(Ap + rstep);
    uint4 vb0 = *(const uint4*)(Bp);
    uint4 vb1 = *(const uint4*)(Bp + rstep);
    *(uint4*)((char*)sA[0] + so0) = va0;
    *(uint4*)((char*)sA[0] + so1) = va1;
    *(uint4*)((char*)sB[0] + so0) = vb0;
    *(uint4*)((char*)sB[0] + so1) = vb1;
    __syncthreads();

    const int nk = K >> 5;
    for (int kt = 0; kt < nk; kt++) {
        const int s = kt & 1;
        if (kt + 1 < nk) {
            int ko = (kt + 1) * 32;
            va0 = *(const uint4*)(Ap + ko);
            va1 = *(const uint4*)(Ap + rstep + ko);
            vb0 = *(const uint4*)(Bp + ko);
            vb1 = *(const uint4*)(Bp + rstep + ko);
        }
        const uint32_t aB = cvta_s(sA[s]);
        const uint32_t bB = cvta_s(sB[s]);
        #pragma unroll
        for (int ks = 0; ks < 2; ks++) {
            uint32_t af[2][4];
            #pragma unroll
            for (int mt = 0; mt < 2; mt++) {
                int row = wm * 32 + mt * 16 + (lane & 15);
                int kch = ks * 2 + ((lane >> 4) & 1);
                ldsm4(af[mt], aB + swz(row, kch));
            }
            uint32_t bf[4][4];
            #pragma unroll
            for (int i = 0; i < 4; i++) {
                int rn = wn * 64 + i * 16 + ((lane >> 4) << 3) + (lane & 7);
                int kch = ks * 2 + ((lane & 8) >> 3);
                ldsm4(bf[i], bB + swz(rn, kch));
            }
            #pragma unroll
            for (int mt = 0; mt < 2; mt++)
                #pragma unroll
                for (int jn = 0; jn < 8; jn++)
                    mma_f16(acc[mt][jn], af[mt],
                            bf[jn >> 1][(jn & 1) * 2], bf[jn >> 1][(jn & 1) * 2 + 1]);
        }
        if (kt + 1 < nk) {
            int s1 = s ^ 1;
            *(uint4*)((char*)sA[s1] + so0) = va0;
            *(uint4*)((char*)sA[s1] + so1) = va1;
            *(uint4*)((char*)sB[s1] + so0) = vb0;
            *(uint4*)((char*)sB[s1] + so1) = vb1;
        }
        __syncthreads();
    }

    if (fp32out) {
        float* C = (float*)Cv;
        #pragma unroll
        for (int mt = 0; mt < 2; mt++) {
            int r = row0 + wm * 32 + mt * 16;
            #pragma unroll
            for (int jn = 0; jn < 8; jn++) {
                int cc = col0 + wn * 64 + jn * 8 + 2 * t;
                float bx = bias[cc], by = bias[cc + 1];
                float2 v0 = { acc[mt][jn][0] + bx, acc[mt][jn][1] + by };
                float2 v1 = { acc[mt][jn][2] + bx, acc[mt][jn][3] + by };
                *(float2*)(C + (size_t)(r + g) * N + cc) = v0;
                *(float2*)(C + (size_t)(r + g + 8) * N + cc) = v1;
            }
        }
    } else {
        __half* C = (__half*)Cv;
        #pragma unroll
        for (int mt = 0; mt < 2; mt++) {
            int r = row0 + wm * 32 + mt * 16;
            #pragma unroll
            for (int jn = 0; jn < 8; jn++) {
                int cc = col0 + wn * 64 + jn * 8 + 2 * t;
                *(uint32_t*)(C + (size_t)(r + g) * N + cc)
                    = pack_half2(acc[mt][jn][0], acc[mt][jn][1]);
                *(uint32_t*)(C + (size_t)(r + g + 8) * N + cc)
                    = pack_half2(acc[mt][jn][2], acc[mt][jn][3]);
            }
        }
    }
}

// =====================  fused fp16 mma attention  ==============================
// block = (q-tile 128, h, b); 8 warps x 16 q rows; 64-key chunks, double-buffered
__global__ __launch_bounds__(256, 2) void attn_h() {
    __shared__ __align__(16) __half Ks[2][64 * 32];
    __shared__ __align__(16) __half Vs[2][64 * 32];
    const int qt = blockIdx.x, h = blockIdx.y, b = blockIdx.z;
    const int tid = threadIdx.x, lane = tid & 31, wid = tid >> 5;
    const int g = lane >> 2, t = lane & 3;
    const int q0 = qt * 128 + wid * 16;
    const __half* base = g_qkv + (size_t)b * NTOK * QKV_LD;
    const float SCALE = 0.17677669529663687f;

    const int skey = tid >> 2, sch = tid & 3;
    const __half* kp = base + (size_t)skey * QKV_LD + DIM + h * HD + sch * 8;
    const __half* vp = kp + DIM;
    const uint32_t soff = swz(skey, sch);
    uint4 vk = *(const uint4*)kp;
    uint4 vv = *(const uint4*)vp;
    *(uint4*)((char*)Ks[0] + soff) = vk;
    *(uint4*)((char*)Vs[0] + soff) = vv;

    uint32_t qa[2][4];
    {
        const __half* qp0 = base + (size_t)(q0 + g) * QKV_LD + h * HD;
        const __half* qp8 = qp0 + (size_t)8 * QKV_LD;
        #pragma unroll
        for (int ks = 0; ks < 2; ks++) {
            qa[ks][0] = *(const uint32_t*)(qp0 + ks * 16 + 2 * t);
            qa[ks][1] = *(const uint32_t*)(qp8 + ks * 16 + 2 * t);
            qa[ks][2] = *(const uint32_t*)(qp0 + ks * 16 + 8 + 2 * t);
            qa[ks][3] = *(const uint32_t*)(qp8 + ks * 16 + 8 + 2 * t);
        }
    }
    __syncthreads();

    float o[4][4];
    #pragma unroll
    for (int nd = 0; nd < 4; nd++)
        #pragma unroll
        for (int r = 0; r < 4; r++) o[nd][r] = 0.f;
    float m0 = -1e30f, m1 = -1e30f, l0 = 0.f, l1 = 0.f;

    // precombined fp32 bias+mask: [h][w][k][q]
    const float* comb = g_comb
        + ((size_t)h * NWIN + (b & (NWIN - 1))) * NN;

    for (int c = 0; c < 8; c++) {
        const int s = c & 1;
        const int j0 = c * 64;
        if (c < 7) {
            const __half* kn = kp + (size_t)(c + 1) * 64 * QKV_LD;
            vk = *(const uint4*)kn;
            vv = *(const uint4*)(kn + DIM);
        }

        // ---- S = Q K^T ----
        float sc[8][4];
        #pragma unroll
        for (int jn = 0; jn < 8; jn++)
            sc[jn][0] = sc[jn][1] = sc[jn][2] = sc[jn][3] = 0.f;
        const uint32_t kB = cvta_s(Ks[s]);
        #pragma unroll
        for (int ks = 0; ks < 2; ks++) {
            uint32_t kb[4][4];
            #pragma unroll
            for (int i = 0; i < 4; i++) {
                int rn = i * 16 + ((lane >> 4) << 3) + (lane & 7);
                int kch = ks * 2 + ((lane & 8) >> 3);
                ldsm4(kb[i], kB + swz(rn, kch));
            }
            #pragma unroll
            for (int jn = 0; jn < 8; jn++)
                mma_f16(sc[jn], qa[ks],
                        kb[jn >> 1][(jn & 1) * 2], kb[jn >> 1][(jn & 1) * 2 + 1]);
        }
        // scale + combined bias/mask (fp32)
        #pragma unroll
        for (int jn = 0; jn < 8; jn++) {
            size_t krow = (size_t)(j0 + jn * 8 + 2 * t) * NTOK;
            const float* cp = comb + krow;
            sc[jn][0] = fmaf(sc[jn][0], SCALE, cp[q0 + g]);
            sc[jn][1] = fmaf(sc[jn][1], SCALE, cp[NTOK + q0 + g]);
            sc[jn][2] = fmaf(sc[jn][2], SCALE, cp[q0 + g + 8]);
            sc[jn][3] = fmaf(sc[jn][3], SCALE, cp[NTOK + q0 + g + 8]);
        }

        // ---- online softmax (rows g / g+8) ----
        float mx0 = sc[0][0], mx1 = sc[0][2];
        #pragma unroll
        for (int jn = 0; jn < 8; jn++) {
            mx0 = fmaxf(mx0, fmaxf(sc[jn][0], sc[jn][1]));
            mx1 = fmaxf(mx1, fmaxf(sc[jn][2], sc[jn][3]));
        }
        mx0 = fmaxf(mx0, __shfl_xor_sync(0xffffffffu, mx0, 1));
        mx0 = fmaxf(mx0, __shfl_xor_sync(0xffffffffu, mx0, 2));
        mx1 = fmaxf(mx1, __shfl_xor_sync(0xffffffffu, mx1, 1));
        mx1 = fmaxf(mx1, __shfl_xor_sync(0xffffffffu, mx1, 2));
        float nm0 = fmaxf(m0, mx0), nm1 = fmaxf(m1, mx1);
        float c0 = __expf(m0 - nm0), c1 = __expf(m1 - nm1);
        m0 = nm0; m1 = nm1;
        l0 *= c0; l1 *= c1;
        #pragma unroll
        for (int nd = 0; nd < 4; nd++) {
            o[nd][0] *= c0; o[nd][1] *= c0;
            o[nd][2] *= c1; o[nd][3] *= c1;
        }

        // ---- P = exp(S-m) packed as A-frags ----
        uint32_t pa[4][4];
        #pragma unroll
        for (int kk = 0; kk < 4; kk++) {
            float pA0 = __expf(sc[2*kk][0] - m0), pA1 = __expf(sc[2*kk][1] - m0);
            float pA2 = __expf(sc[2*kk][2] - m1), pA3 = __expf(sc[2*kk][3] - m1);
            float pB0 = __expf(sc[2*kk+1][0] - m0), pB1 = __expf(sc[2*kk+1][1] - m0);
            float pB2 = __expf(sc[2*kk+1][2] - m1), pB3 = __expf(sc[2*kk+1][3] - m1);
            l0 += (pA0 + pA1) + (pB0 + pB1);
            l1 += (pA2 + pA3) + (pB2 + pB3);
            pa[kk][0] = pack_half2(pA0, pA1);
            pa[kk][1] = pack_half2(pA2, pA3);
            pa[kk][2] = pack_half2(pB0, pB1);
            pa[kk][3] = pack_half2(pB2, pB3);
        }

        // ---- O += P V ----
        const uint32_t vB = cvta_s(Vs[s]);
        #pragma unroll
        for (int ndp = 0; ndp < 2; ndp++)
            #pragma unroll
            for (int kk = 0; kk < 4; kk++) {
                uint32_t vb[4];
                int key = kk * 16 + (lane & 15);
                int kch = ndp * 2 + (lane >> 4);
                ldsm4t(vb, vB + swz(key, kch));
                mma_f16(o[ndp * 2],     pa[kk], vb[0], vb[1]);
                mma_f16(o[ndp * 2 + 1], pa[kk], vb[2], vb[3]);
            }

        if (c < 7) {
            int s1 = s ^ 1;
            *(uint4*)((char*)Ks[s1] + soff) = vk;
            *(uint4*)((char*)Vs[s1] + soff) = vv;
        }
        __syncthreads();
    }

    l0 += __shfl_xor_sync(0xffffffffu, l0, 1);
    l0 += __shfl_xor_sync(0xffffffffu, l0, 2);
    l1 += __shfl_xor_sync(0xffffffffu, l1, 1);
    l1 += __shfl_xor_sync(0xffffffffu, l1, 2);
    float i0 = 1.f / l0, i1 = 1.f / l1;
    __half* op0 = g_att + ((size_t)b * NTOK + q0 + g) * DIM + h * HD;
    __half* op8 = op0 + (size_t)8 * DIM;
    #pragma unroll
    for (int nd = 0; nd < 4; nd++) {
        *(uint32_t*)(op0 + nd * 8 + 2 * t) = pack_half2(o[nd][0] * i0, o[nd][1] * i0);
        *(uint32_t*)(op8 + nd * 8 + 2 * t) = pack_half2(o[nd][2] * i1, o[nd][3] * i1);
    }
}

// ---------------- CPB MLP ----------------
__global__ void cpb_kernel(const float* __restrict__ rpb,
                           const float* __restrict__ w1,
                           const float* __restrict__ b1,
                           const float* __restrict__ w2) {
    int e = blockIdx.x;
    int h = threadIdx.x >> 5;
    int lane = threadIdx.x & 31;
    float r0 = rpb[e * 3 + 0], r1 = rpb[e * 3 + 1], r2 = rpb[e * 3 + 2];
    float sum = 0.f;
    for (int o = lane; o < 512; o += 32) {
        float hid = fmaf(r0, w1[o * 3 + 0],
                    fmaf(r1, w1[o * 3 + 1],
                    fmaf(r2, w1[o * 3 + 2], b1[o])));
        hid = fmaxf(hid, 0.f);
        sum = fmaf(hid, w2[h * 512 + o], sum);
    }
    #pragma unroll
    for (int off = 16; off; off >>= 1)
        sum += __shfl_xor_sync(0xffffffffu, sum, off);
    if (lane == 0) g_table[e * NH + h] = sum;
}

// ---------------- mask transpose (fp32) ----------------
__global__ void mask_transpose_kernel(const float* __restrict__ mask) {
    __shared__ float tile[32][33];
    int w = blockIdx.z;
    int q0 = blockIdx.y * 32, k0 = blockIdx.x * 32;
    int tx = threadIdx.x, ty = threadIdx.y;
    const float* src = mask + (size_t)w * NN;
    float* dst = g_maskT + (size_t)w * NN;
    #pragma unroll
    for (int i = ty; i < 32; i += 8)
        tile[i][tx] = src[(q0 + i) * NTOK + k0 + tx];
    __syncthreads();
    #pragma unroll
    for (int i = ty; i < 32; i += 8)
        dst[(k0 + i) * NTOK + q0 + tx] = tile[tx][i];
}

// ---------------- combined bias+mask: comb[h][w][k][q] (fp32) ----------------
__global__ void comb_kernel(const int* __restrict__ rpb_idx) {
    int tt = blockIdx.x * blockDim.x + threadIdx.x;   // tt = k*512 + q
    if (tt >= NN) return;
    int q = tt & (NTOK - 1);
    int k = tt >> 9;
    int idx = rpb_idx[q * NTOK + k];
    float bias[NH];
    #pragma unroll
    for (int h = 0; h < NH; h++) {
        float v = g_table[idx * NH + h];
        bias[h] = 16.f / (1.f + __expf(-v));
    }
    #pragma unroll
    for (int w = 0; w < NWIN; w++) {
        float mv = g_maskT[(size_t)w * NN + tt];
        #pragma unroll
        for (int h = 0; h < NH; h++)
            g_comb[((size_t)h * NWIN + w) * NN + tt] = bias[h] + mv;
    }
}

// ---------------- launch ----------------
extern "C" void kernel_launch(void* const* d_in, const int* in_sizes, int n_in,
                              void* d_out, int out_size) {
    const float* x      = (const float*)d_in[0];
    const float* mask   = (const float*)d_in[1];
    const float* qkv_w  = (const float*)d_in[2];
    const float* proj_w = (const float*)d_in[3];
    const float* proj_b = (const float*)d_in[4];
    const float* cpb_w1 = (const float*)d_in[5];
    const float* cpb_b1 = (const float*)d_in[6];
    const float* cpb_w2 = (const float*)d_in[7];
    const float* rpb    = (const float*)d_in[8];
    const int*   rpb_idx = (const int*)d_in[9];
    float* out = (float*)d_out;

    static __half *p_xh = nullptr, *p_qkvw = nullptr, *p_projw = nullptr,
                  *p_qkv = nullptr, *p_att = nullptr;
    if (!p_xh) {
        cudaGetSymbolAddress((void**)&p_xh, g_xh);
        cudaGetSymbolAddress((void**)&p_qkvw, g_qkvw);
        cudaGetSymbolAddress((void**)&p_projw, g_projw);
        cudaGetSymbolAddress((void**)&p_qkv, g_qkv);
        cudaGetSymbolAddress((void**)&p_att, g_att);
    }

    // conversions to fp16
    {
        int nx8 = (BATCH * NTOK * DIM) / 8;
        cvt_h8<<<(nx8 + 255) / 256, 256>>>(x, p_xh, nx8);
        int nw8 = (QKV_LD * DIM) / 8;
        cvt_h8<<<(nw8 + 255) / 256, 256>>>(qkv_w, p_qkvw, nw8);
        int np8 = (DIM * DIM) / 8;
        cvt_h8<<<(np8 + 255) / 256, 256>>>(proj_w, p_projw, np8);
    }
    // CPB table, mask transpose, combined bias+mask
    cpb_kernel<<<TABLE_E, 256>>>(rpb, cpb_w1, cpb_b1, cpb_w2);
    mask_transpose_kernel<<<dim3(16, 16, NWIN), dim3(32, 8)>>>(mask);
    comb_kernel<<<(NN + 255) / 256, 256>>>(rpb_idx);
    // QKV projection (fp16 mma, fp16 out)
    {
        dim3 grid(QKV_LD / 128, (BATCH * NTOK) / 128);
        gemm_h<<<grid, 256>>>(p_xh, p_qkvw, nullptr, p_qkv,
                              BATCH * NTOK, QKV_LD, DIM, 0);
    }
    // fused attention
    attn_h<<<dim3(NTOK / 128, NH, BATCH), 256>>>();
    // output projection (fp16 mma, fp32 out + bias)
    {
        dim3 grid(DIM / 128, (BATCH * NTOK) / 128);
        gemm_h<<<grid, 256>>>(p_att, p_projw, proj_b, out,
                              BATCH * NTOK, DIM, DIM, 1);
    }
}

// round 6
// speedup vs baseline: 4.5786x; 1.0614x over previous
#include <cuda_runtime.h>
#include <cuda_fp16.h>
#include <math.h>
#include <stdint.h>

#define BATCH   128
#define NWIN    16
#define NTOK    512
#define DIM     256
#define NH      8
#define HD      32
#define TABLE_E 3375
#define QKV_LD  768
#define NN      (NTOK*NTOK)
#define LOG2E   1.4426950408889634f

// ---------------- scratch (device globals) ----------------
__device__ float  g_table[TABLE_E * NH];
__device__ float  g_maskT[NWIN * NN];                       // [w][k][q] * LOG2E, 16 MB
__device__ float  g_biasC[NH * NN];                         // [h][k][q] * LOG2E, 8 MB
__device__ int    g_maskflag;
__device__ __half g_xh[(size_t)BATCH * NTOK * DIM];
__device__ __half g_qkvw[QKV_LD * DIM];
__device__ __half g_projw[DIM * DIM];
__device__ __half g_qkv[(size_t)BATCH * NTOK * QKV_LD];
__device__ __half g_att[(size_t)BATCH * NTOK * DIM];

// =====================  helpers  =====================
__device__ __forceinline__ uint32_t pack_half2(float lo, float hi) {
    __half2 h = __floats2half2_rn(lo, hi);
    return *(uint32_t*)&h;
}
__device__ __forceinline__ void mma_f16(float* d, const uint32_t* a,
                                        uint32_t b0, uint32_t b1) {
    asm volatile(
        "mma.sync.aligned.m16n8k16.row.col.f32.f16.f16.f32 "
        "{%0,%1,%2,%3}, {%4,%5,%6,%7}, {%8,%9}, {%0,%1,%2,%3};"
        : "+f"(d[0]), "+f"(d[1]), "+f"(d[2]), "+f"(d[3])
        : "r"(a[0]), "r"(a[1]), "r"(a[2]), "r"(a[3]), "r"(b0), "r"(b1));
}
__device__ __forceinline__ void ldsm4(uint32_t* r, uint32_t addr) {
    asm volatile("ldmatrix.sync.aligned.m8n8.x4.shared.b16 {%0,%1,%2,%3}, [%4];"
                 : "=r"(r[0]), "=r"(r[1]), "=r"(r[2]), "=r"(r[3]) : "r"(addr));
}
__device__ __forceinline__ void ldsm4t(uint32_t* r, uint32_t addr) {
    asm volatile("ldmatrix.sync.aligned.m8n8.x4.trans.shared.b16 {%0,%1,%2,%3}, [%4];"
                 : "=r"(r[0]), "=r"(r[1]), "=r"(r[2]), "=r"(r[3]) : "r"(addr));
}
__device__ __forceinline__ uint32_t cvta_s(const void* p) {
    return (uint32_t)__cvta_generic_to_shared(p);
}
__device__ __forceinline__ uint32_t swz(int r, int kchunk) {
    return (uint32_t)(r * 64 + ((kchunk ^ ((r >> 1) & 3)) << 4));
}

// ---------------- merged fp32->fp16 conversion + flag reset ----------------
#define N8X ((BATCH * NTOK * DIM) / 8)
#define N8W ((QKV_LD * DIM) / 8)
#define N8P ((DIM * DIM) / 8)
__global__ void cvt_all(const float* __restrict__ x,
                        const float* __restrict__ qw,
                        const float* __restrict__ pw) {
    int i = blockIdx.x * blockDim.x + threadIdx.x;
    if (i == 0) g_maskflag = 0;
    const float* s;
    __half* d;
    int j;
    if (i < N8X)                { s = x;  d = g_xh;    j = i; }
    else if (i < N8X + N8W)     { s = qw; d = g_qkvw;  j = i - N8X; }
    else if (i < N8X + N8W+N8P) { s = pw; d = g_projw; j = i - N8X - N8W; }
    else return;
    const float4* sp = (const float4*)s + (size_t)j * 2;
    float4 a = sp[0], b = sp[1];
    uint4 o;
    o.x = pack_half2(a.x, a.y); o.y = pack_half2(a.z, a.w);
    o.z = pack_half2(b.x, b.y); o.w = pack_half2(b.z, b.w);
    ((uint4*)d)[j] = o;
}

// ---------------- CPB MLP ----------------
__global__ void cpb_kernel(const float* __restrict__ rpb,
                           const float* __restrict__ w1,
                           const float* __restrict__ b1,
                           const float* __restrict__ w2) {
    int e = blockIdx.x;
    int h = threadIdx.x >> 5;
    int lane = threadIdx.x & 31;
    float r0 = rpb[e * 3 + 0], r1 = rpb[e * 3 + 1], r2 = rpb[e * 3 + 2];
    float sum = 0.f;
    for (int o = lane; o < 512; o += 32) {
        float hid = fmaf(r0, w1[o * 3 + 0],
                    fmaf(r1, w1[o * 3 + 1],
                    fmaf(r2, w1[o * 3 + 2], b1[o])));
        hid = fmaxf(hid, 0.f);
        sum = fmaf(hid, w2[h * 512 + o], sum);
    }
    #pragma unroll
    for (int off = 16; off; off >>= 1)
        sum += __shfl_xor_sync(0xffffffffu, sum, off);
    if (lane == 0) g_table[e * NH + h] = sum;
}

// ---------------- mask transpose (*LOG2E) + nonzero flag ----------------
__global__ void mask_transpose_kernel(const float* __restrict__ mask) {
    __shared__ float tile[32][33];
    int w = blockIdx.z;
    int q0 = blockIdx.y * 32, k0 = blockIdx.x * 32;
    int tx = threadIdx.x, ty = threadIdx.y;
    const float* src = mask + (size_t)w * NN;
    float* dst = g_maskT + (size_t)w * NN;
    bool nz = false;
    #pragma unroll
    for (int i = ty; i < 32; i += 8) {
        float v = src[(q0 + i) * NTOK + k0 + tx];
        nz |= (v != 0.f);
        tile[i][tx] = v * LOG2E;
    }
    __syncthreads();
    #pragma unroll
    for (int i = ty; i < 32; i += 8)
        dst[(k0 + i) * NTOK + q0 + tx] = tile[tx][i];
    if (__syncthreads_or(nz) && tx == 0 && ty == 0)
        atomicOr(&g_maskflag, 1);
}

// ---------------- bias gather (transposed, fp32, *LOG2E) ----------------
__global__ void bias_kernel(const int* __restrict__ rpb_idx) {
    int tt = blockIdx.x * blockDim.x + threadIdx.x;   // tt = k*512 + q
    if (tt >= NN) return;
    int q = tt & (NTOK - 1);
    int k = tt >> 9;
    int idx = rpb_idx[q * NTOK + k];
    #pragma unroll
    for (int h = 0; h < NH; h++) {
        float v = g_table[idx * NH + h];
        g_biasC[(size_t)h * NN + tt] = (16.f * LOG2E) / (1.f + __expf(-v));
    }
}

// =====================  fp16 mma GEMM (NT)  =====
__global__ __launch_bounds__(256, 2) void gemm_h(const __half* __restrict__ A,
                                                 const __half* __restrict__ B,
                                                 const float* __restrict__ bias,
                                                 void* __restrict__ Cv,
                                                 int M, int N, int K, int fp32out) {
    __shared__ __align__(16) __half sA[2][128 * 32];
    __shared__ __align__(16) __half sB[2][128 * 32];
    const int tid = threadIdx.x, lane = tid & 31, wid = tid >> 5;
    const int g = lane >> 2, t = lane & 3;
    const int wm = wid & 3, wn = wid >> 2;
    const int row0 = blockIdx.y * 128, col0 = blockIdx.x * 128;

    const int lr = tid >> 2, lc = tid & 3;
    const __half* Ap = A + (size_t)(row0 + lr) * K + lc * 8;
    const __half* Bp = B + (size_t)(col0 + lr) * K + lc * 8;
    const size_t rstep = (size_t)64 * K;
    const uint32_t so0 = swz(lr, lc), so1 = swz(lr + 64, lc);

    float acc[2][8][4];
    #pragma unroll
    for (int mt = 0; mt < 2; mt++)
        #pragma unroll
        for (int jn = 0; jn < 8; jn++)
            #pragma unroll
            for (int r = 0; r < 4; r++) acc[mt][jn][r] = 0.f;

    uint4 va0 = *(const uint4*)(Ap);
    uint4 va1 = *(const uint4*)(Ap + rstep);
    uint4 vb0 = *(const uint4*)(Bp);
    uint4 vb1 = *(const uint4*)(Bp + rstep);
    *(uint4*)((char*)sA[0] + so0) = va0;
    *(uint4*)((char*)sA[0] + so1) = va1;
    *(uint4*)((char*)sB[0] + so0) = vb0;
    *(uint4*)((char*)sB[0] + so1) = vb1;
    __syncthreads();

    const int nk = K >> 5;
    for (int kt = 0; kt < nk; kt++) {
        const int s = kt & 1;
        if (kt + 1 < nk) {
            int ko = (kt + 1) * 32;
            va0 = *(const uint4*)(Ap + ko);
            va1 = *(const uint4*)(Ap + rstep + ko);
            vb0 = *(const uint4*)(Bp + ko);
            vb1 = *(const uint4*)(Bp + rstep + ko);
        }
        const uint32_t aB = cvta_s(sA[s]);
        const uint32_t bB = cvta_s(sB[s]);
        #pragma unroll
        for (int ks = 0; ks < 2; ks++) {
            uint32_t af[2][4];
            #pragma unroll
            for (int mt = 0; mt < 2; mt++) {
                int row = wm * 32 + mt * 16 + (lane & 15);
                int kch = ks * 2 + ((lane >> 4) & 1);
                ldsm4(af[mt], aB + swz(row, kch));
            }
            uint32_t bf[4][4];
            #pragma unroll
            for (int i = 0; i < 4; i++) {
                int rn = wn * 64 + i * 16 + ((lane >> 4) << 3) + (lane & 7);
                int kch = ks * 2 + ((lane & 8) >> 3);
                ldsm4(bf[i], bB + swz(rn, kch));
            }
            #pragma unroll
            for (int mt = 0; mt < 2; mt++)
                #pragma unroll
                for (int jn = 0; jn < 8; jn++)
                    mma_f16(acc[mt][jn], af[mt],
                            bf[jn >> 1][(jn & 1) * 2], bf[jn >> 1][(jn & 1) * 2 + 1]);
        }
        if (kt + 1 < nk) {
            int s1 = s ^ 1;
            *(uint4*)((char*)sA[s1] + so0) = va0;
            *(uint4*)((char*)sA[s1] + so1) = va1;
            *(uint4*)((char*)sB[s1] + so0) = vb0;
            *(uint4*)((char*)sB[s1] + so1) = vb1;
        }
        __syncthreads();
    }

    if (fp32out) {
        float* C = (float*)Cv;
        #pragma unroll
        for (int mt = 0; mt < 2; mt++) {
            int r = row0 + wm * 32 + mt * 16;
            #pragma unroll
            for (int jn = 0; jn < 8; jn++) {
                int cc = col0 + wn * 64 + jn * 8 + 2 * t;
                float bx = bias[cc], by = bias[cc + 1];
                float2 v0 = { acc[mt][jn][0] + bx, acc[mt][jn][1] + by };
                float2 v1 = { acc[mt][jn][2] + bx, acc[mt][jn][3] + by };
                *(float2*)(C + (size_t)(r + g) * N + cc) = v0;
                *(float2*)(C + (size_t)(r + g + 8) * N + cc) = v1;
            }
        }
    } else {
        __half* C = (__half*)Cv;
        #pragma unroll
        for (int mt = 0; mt < 2; mt++) {
            int r = row0 + wm * 32 + mt * 16;
            #pragma unroll
            for (int jn = 0; jn < 8; jn++) {
                int cc = col0 + wn * 64 + jn * 8 + 2 * t;
                *(uint32_t*)(C + (size_t)(r + g) * N + cc)
                    = pack_half2(acc[mt][jn][0], acc[mt][jn][1]);
                *(uint32_t*)(C + (size_t)(r + g + 8) * N + cc)
                    = pack_half2(acc[mt][jn][2], acc[mt][jn][3]);
            }
        }
    }
}

// =====================  fused fp16 mma attention (base-2 softmax) ==========
// grid = (b, h, qt)  — b fastest so concurrent blocks share bias slabs
__global__ __launch_bounds__(256, 2) void attn_h() {
    __shared__ __align__(16) __half Ks[2][64 * 32];
    __shared__ __align__(16) __half Vs[2][64 * 32];
    const int b = blockIdx.x, h = blockIdx.y, qt = blockIdx.z;
    const int tid = threadIdx.x, lane = tid & 31, wid = tid >> 5;
    const int g = lane >> 2, t = lane & 3;
    const int q0 = qt * 128 + wid * 16;
    const __half* base = g_qkv + (size_t)b * NTOK * QKV_LD;
    const float SCALE2 = 0.17677669529663687f * LOG2E;
    const bool use_mask = (g_maskflag != 0);

    const int skey = tid >> 2, sch = tid & 3;
    const __half* kp = base + (size_t)skey * QKV_LD + DIM + h * HD + sch * 8;
    const __half* vp = kp + DIM;
    const uint32_t soff = swz(skey, sch);
    uint4 vk = *(const uint4*)kp;
    uint4 vv = *(const uint4*)vp;
    *(uint4*)((char*)Ks[0] + soff) = vk;
    *(uint4*)((char*)Vs[0] + soff) = vv;

    uint32_t qa[2][4];
    {
        const __half* qp0 = base + (size_t)(q0 + g) * QKV_LD + h * HD;
        const __half* qp8 = qp0 + (size_t)8 * QKV_LD;
        #pragma unroll
        for (int ks = 0; ks < 2; ks++) {
            qa[ks][0] = *(const uint32_t*)(qp0 + ks * 16 + 2 * t);
            qa[ks][1] = *(const uint32_t*)(qp8 + ks * 16 + 2 * t);
            qa[ks][2] = *(const uint32_t*)(qp0 + ks * 16 + 8 + 2 * t);
            qa[ks][3] = *(const uint32_t*)(qp8 + ks * 16 + 8 + 2 * t);
        }
    }
    __syncthreads();

    float o[4][4];
    #pragma unroll
    for (int nd = 0; nd < 4; nd++)
        #pragma unroll
        for (int r = 0; r < 4; r++) o[nd][r] = 0.f;
    float m0 = -1e30f, m1 = -1e30f, l0 = 0.f, l1 = 0.f;

    const float* biasC = g_biasC + (size_t)h * NN;
    const float* maskT = g_maskT + (size_t)(b & (NWIN - 1)) * NN;

    for (int c = 0; c < 8; c++) {
        const int s = c & 1;
        const int j0 = c * 64;
        if (c < 7) {
            const __half* kn = kp + (size_t)(c + 1) * 64 * QKV_LD;
            vk = *(const uint4*)kn;
            vv = *(const uint4*)(kn + DIM);
        }

        // ---- S = Q K^T ----
        float sc[8][4];
        #pragma unroll
        for (int jn = 0; jn < 8; jn++)
            sc[jn][0] = sc[jn][1] = sc[jn][2] = sc[jn][3] = 0.f;
        const uint32_t kB = cvta_s(Ks[s]);
        #pragma unroll
        for (int ks = 0; ks < 2; ks++) {
            uint32_t kb[4][4];
            #pragma unroll
            for (int i = 0; i < 4; i++) {
                int rn = i * 16 + ((lane >> 4) << 3) + (lane & 7);
                int kch = ks * 2 + ((lane & 8) >> 3);
                ldsm4(kb[i], kB + swz(rn, kch));
            }
            #pragma unroll
            for (int jn = 0; jn < 8; jn++)
                mma_f16(sc[jn], qa[ks],
                        kb[jn >> 1][(jn & 1) * 2], kb[jn >> 1][(jn & 1) * 2 + 1]);
        }
        // scale + bias (+ mask if present); all base-2 scaled
        #pragma unroll
        for (int jn = 0; jn < 8; jn++) {
            size_t krow = (size_t)(j0 + jn * 8 + 2 * t) * NTOK;
            const float* bp = biasC + krow;
            float a0 = bp[q0 + g],        a1 = bp[NTOK + q0 + g];
            float a2 = bp[q0 + g + 8],    a3 = bp[NTOK + q0 + g + 8];
            if (use_mask) {
                const float* mp = maskT + krow;
                a0 += mp[q0 + g];        a1 += mp[NTOK + q0 + g];
                a2 += mp[q0 + g + 8];    a3 += mp[NTOK + q0 + g + 8];
            }
            sc[jn][0] = fmaf(sc[jn][0], SCALE2, a0);
            sc[jn][1] = fmaf(sc[jn][1], SCALE2, a1);
            sc[jn][2] = fmaf(sc[jn][2], SCALE2, a2);
            sc[jn][3] = fmaf(sc[jn][3], SCALE2, a3);
        }

        // ---- online softmax (base 2), rows g / g+8 ----
        float mx0 = sc[0][0], mx1 = sc[0][2];
        #pragma unroll
        for (int jn = 0; jn < 8; jn++) {
            mx0 = fmaxf(mx0, fmaxf(sc[jn][0], sc[jn][1]));
            mx1 = fmaxf(mx1, fmaxf(sc[jn][2], sc[jn][3]));
        }
        mx0 = fmaxf(mx0, __shfl_xor_sync(0xffffffffu, mx0, 1));
        mx0 = fmaxf(mx0, __shfl_xor_sync(0xffffffffu, mx0, 2));
        mx1 = fmaxf(mx1, __shfl_xor_sync(0xffffffffu, mx1, 1));
        mx1 = fmaxf(mx1, __shfl_xor_sync(0xffffffffu, mx1, 2));
        float nm0 = fmaxf(m0, mx0), nm1 = fmaxf(m1, mx1);
        float c0 = exp2f(m0 - nm0), c1 = exp2f(m1 - nm1);
        m0 = nm0; m1 = nm1;
        l0 *= c0; l1 *= c1;
        #pragma unroll
        for (int nd = 0; nd < 4; nd++) {
            o[nd][0] *= c0; o[nd][1] *= c0;
            o[nd][2] *= c1; o[nd][3] *= c1;
        }

        // ---- P = 2^(S-m) packed as A-frags ----
        uint32_t pa[4][4];
        #pragma unroll
        for (int kk = 0; kk < 4; kk++) {
            float pA0 = exp2f(sc[2*kk][0] - m0), pA1 = exp2f(sc[2*kk][1] - m0);
            float pA2 = exp2f(sc[2*kk][2] - m1), pA3 = exp2f(sc[2*kk][3] - m1);
            float pB0 = exp2f(sc[2*kk+1][0] - m0), pB1 = exp2f(sc[2*kk+1][1] - m0);
            float pB2 = exp2f(sc[2*kk+1][2] - m1), pB3 = exp2f(sc[2*kk+1][3] - m1);
            l0 += (pA0 + pA1) + (pB0 + pB1);
            l1 += (pA2 + pA3) + (pB2 + pB3);
            pa[kk][0] = pack_half2(pA0, pA1);
            pa[kk][1] = pack_half2(pA2, pA3);
            pa[kk][2] = pack_half2(pB0, pB1);
            pa[kk][3] = pack_half2(pB2, pB3);
        }

        // ---- O += P V ----
        const uint32_t vB = cvta_s(Vs[s]);
        #pragma unroll
        for (int ndp = 0; ndp < 2; ndp++)
            #pragma unroll
            for (int kk = 0; kk < 4; kk++) {
                uint32_t vb[4];
                int key = kk * 16 + (lane & 15);
                int kch = ndp * 2 + (lane >> 4);
                ldsm4t(vb, vB + swz(key, kch));
                mma_f16(o[ndp * 2],     pa[kk], vb[0], vb[1]);
                mma_f16(o[ndp * 2 + 1], pa[kk], vb[2], vb[3]);
            }

        if (c < 7) {
            int s1 = s ^ 1;
            *(uint4*)((char*)Ks[s1] + soff) = vk;
            *(uint4*)((char*)Vs[s1] + soff) = vv;
        }
        __syncthreads();
    }

    l0 += __shfl_xor_sync(0xffffffffu, l0, 1);
    l0 += __shfl_xor_sync(0xffffffffu, l0, 2);
    l1 += __shfl_xor_sync(0xffffffffu, l1, 1);
    l1 += __shfl_xor_sync(0xffffffffu, l1, 2);
    float i0 = 1.f / l0, i1 = 1.f / l1;
    __half* op0 = g_att + ((size_t)b * NTOK + q0 + g) * DIM + h * HD;
    __half* op8 = op0 + (size_t)8 * DIM;
    #pragma unroll
    for (int nd = 0; nd < 4; nd++) {
        *(uint32_t*)(op0 + nd * 8 + 2 * t) = pack_half2(o[nd][0] * i0, o[nd][1] * i0);
        *(uint32_t*)(op8 + nd * 8 + 2 * t) = pack_half2(o[nd][2] * i1, o[nd][3] * i1);
    }
}

// ---------------- launch ----------------
extern "C" void kernel_launch(void* const* d_in, const int* in_sizes, int n_in,
                              void* d_out, int out_size) {
    const float* x      = (const float*)d_in[0];
    const float* mask   = (const float*)d_in[1];
    const float* qkv_w  = (const float*)d_in[2];
    const float* proj_w = (const float*)d_in[3];
    const float* proj_b = (const float*)d_in[4];
    const float* cpb_w1 = (const float*)d_in[5];
    const float* cpb_b1 = (const float*)d_in[6];
    const float* cpb_w2 = (const float*)d_in[7];
    const float* rpb    = (const float*)d_in[8];
    const int*   rpb_idx = (const int*)d_in[9];
    float* out = (float*)d_out;

    static __half *p_xh = nullptr, *p_qkvw = nullptr, *p_projw = nullptr,
                  *p_qkv = nullptr, *p_att = nullptr;
    if (!p_xh) {
        cudaGetSymbolAddress((void**)&p_xh, g_xh);
        cudaGetSymbolAddress((void**)&p_qkvw, g_qkvw);
        cudaGetSymbolAddress((void**)&p_projw, g_projw);
        cudaGetSymbolAddress((void**)&p_qkv, g_qkv);
        cudaGetSymbolAddress((void**)&p_att, g_att);
    }

    // launch order chosen so attn_h is launch index 5 (ncu -s 5 -c 1)
    // 0) merged conversions (+ mask flag reset)
    {
        int total = N8X + N8W + N8P;
        cvt_all<<<(total + 255) / 256, 256>>>(x, qkv_w, proj_w);
    }
    // 1) CPB table
    cpb_kernel<<<TABLE_E, 256>>>(rpb, cpb_w1, cpb_b1, cpb_w2);
    // 2) mask transpose (*LOG2E) + flag
    mask_transpose_kernel<<<dim3(16, 16, NWIN), dim3(32, 8)>>>(mask);
    // 3) bias gather (fp32 *LOG2E)
    bias_kernel<<<(NN + 255) / 256, 256>>>(rpb_idx);
    // 4) QKV projection
    {
        dim3 grid(QKV_LD / 128, (BATCH * NTOK) / 128);
        gemm_h<<<grid, 256>>>(p_xh, p_qkvw, nullptr, p_qkv,
                              BATCH * NTOK, QKV_LD, DIM, 0);
    }
    // 5) fused attention
    attn_h<<<dim3(BATCH, NH, NTOK / 128), 256>>>();
    // 6) output projection
    {
        dim3 grid(DIM / 128, (BATCH * NTOK) / 128);
        gemm_h<<<grid, 256>>>(p_att, p_projw, proj_b, out,
                              BATCH * NTOK, DIM, DIM, 1);
    }
}

// round 7
// speedup vs baseline: 4.6681x; 1.0195x over previous
#include <cuda_runtime.h>
#include <cuda_fp16.h>
#include <math.h>
#include <stdint.h>

#define BATCH   128
#define NWIN    16
#define NTOK    512
#define DIM     256
#define NH      8
#define HD      32
#define TABLE_E 3375
#define QKV_LD  768
#define NN      (NTOK*NTOK)
#define LOG2E   1.4426950408889634f
#define NFRAG   65536   // float4 fragments per (h or w) slab

// ---------------- scratch (device globals) ----------------
__device__ float  g_table[TABLE_E * NH];
__device__ float4 g_biasF[NH * NFRAG];      // fragment-layout bias *LOG2E, 8.4 MB
__device__ float4 g_maskF[NWIN * NFRAG];    // fragment-layout mask *LOG2E, 16.8 MB
__device__ int    g_maskflag;
__device__ __half g_xh[(size_t)BATCH * NTOK * DIM];
__device__ __half g_qkvw[QKV_LD * DIM];
__device__ __half g_projw[DIM * DIM];
__device__ __half g_qkv[(size_t)BATCH * NTOK * QKV_LD];
__device__ __half g_att[(size_t)BATCH * NTOK * DIM];

// =====================  helpers  =====================
__device__ __forceinline__ uint32_t pack_half2(float lo, float hi) {
    __half2 h = __floats2half2_rn(lo, hi);
    return *(uint32_t*)&h;
}
__device__ __forceinline__ void mma_f16(float* d, const uint32_t* a,
                                        uint32_t b0, uint32_t b1) {
    asm volatile(
        "mma.sync.aligned.m16n8k16.row.col.f32.f16.f16.f32 "
        "{%0,%1,%2,%3}, {%4,%5,%6,%7}, {%8,%9}, {%0,%1,%2,%3};"
        : "+f"(d[0]), "+f"(d[1]), "+f"(d[2]), "+f"(d[3])
        : "r"(a[0]), "r"(a[1]), "r"(a[2]), "r"(a[3]), "r"(b0), "r"(b1));
}
__device__ __forceinline__ void ldsm4(uint32_t* r, uint32_t addr) {
    asm volatile("ldmatrix.sync.aligned.m8n8.x4.shared.b16 {%0,%1,%2,%3}, [%4];"
                 : "=r"(r[0]), "=r"(r[1]), "=r"(r[2]), "=r"(r[3]) : "r"(addr));
}
__device__ __forceinline__ void ldsm4t(uint32_t* r, uint32_t addr) {
    asm volatile("ldmatrix.sync.aligned.m8n8.x4.trans.shared.b16 {%0,%1,%2,%3}, [%4];"
                 : "=r"(r[0]), "=r"(r[1]), "=r"(r[2]), "=r"(r[3]) : "r"(addr));
}
__device__ __forceinline__ uint32_t cvta_s(const void* p) {
    return (uint32_t)__cvta_generic_to_shared(p);
}
__device__ __forceinline__ uint32_t swz(int r, int kchunk) {
    return (uint32_t)(r * 64 + ((kchunk ^ ((r >> 1) & 3)) << 4));
}
__device__ __forceinline__ void cp16(uint32_t smem, const void* g) {
    asm volatile("cp.async.cg.shared.global [%0], [%1], 16;"
                 :: "r"(smem), "l"(g) : "memory");
}
__device__ __forceinline__ void cp_commit() {
    asm volatile("cp.async.commit_group;" ::: "memory");
}
__device__ __forceinline__ void cp_wait0() {
    asm volatile("cp.async.wait_group 0;" ::: "memory");
}

// ---------------- merged fp32->fp16 conversion + flag reset ----------------
#define N8X ((BATCH * NTOK * DIM) / 8)
#define N8W ((QKV_LD * DIM) / 8)
#define N8P ((DIM * DIM) / 8)
__global__ void cvt_all(const float* __restrict__ x,
                        const float* __restrict__ qw,
                        const float* __restrict__ pw) {
    int i = blockIdx.x * blockDim.x + threadIdx.x;
    if (i == 0) g_maskflag = 0;
    const float* s;
    __half* d;
    int j;
    if (i < N8X)                  { s = x;  d = g_xh;    j = i; }
    else if (i < N8X + N8W)       { s = qw; d = g_qkvw;  j = i - N8X; }
    else if (i < N8X + N8W + N8P) { s = pw; d = g_projw; j = i - N8X - N8W; }
    else return;
    const float4* sp = (const float4*)s + (size_t)j * 2;
    float4 a = sp[0], b = sp[1];
    uint4 o;
    o.x = pack_half2(a.x, a.y); o.y = pack_half2(a.z, a.w);
    o.z = pack_half2(b.x, b.y); o.w = pack_half2(b.z, b.w);
    ((uint4*)d)[j] = o;
}

// ---------------- CPB MLP ----------------
__global__ void cpb_kernel(const float* __restrict__ rpb,
                           const float* __restrict__ w1,
                           const float* __restrict__ b1,
                           const float* __restrict__ w2) {
    int e = blockIdx.x;
    int h = threadIdx.x >> 5;
    int lane = threadIdx.x & 31;
    float r0 = rpb[e * 3 + 0], r1 = rpb[e * 3 + 1], r2 = rpb[e * 3 + 2];
    float sum = 0.f;
    for (int o = lane; o < 512; o += 32) {
        float hid = fmaf(r0, w1[o * 3 + 0],
                    fmaf(r1, w1[o * 3 + 1],
                    fmaf(r2, w1[o * 3 + 2], b1[o])));
        hid = fmaxf(hid, 0.f);
        sum = fmaf(hid, w2[h * 512 + o], sum);
    }
    #pragma unroll
    for (int off = 16; off; off >>= 1)
        sum += __shfl_xor_sync(0xffffffffu, sum, off);
    if (lane == 0) g_table[e * NH + h] = sum;
}

// fragment decode: i -> (qt,wid,c,jn,t,g); element (k,q) pairs per float4
// slot x=(k0  ,q0) y=(k0+1,q0) z=(k0  ,q0+8) w=(k0+1,q0+8)
// ---------------- mask -> fragment layout (*LOG2E) + nonzero flag ----------
__global__ void maskF_kernel(const float* __restrict__ mask) {
    int i = blockIdx.x * blockDim.x + threadIdx.x;
    int w = blockIdx.y;
    int g = i & 7, t = (i >> 3) & 3, jn = (i >> 5) & 7, c = (i >> 8) & 7;
    int wid = (i >> 11) & 7, qt = i >> 14;
    int q0 = qt * 128 + wid * 16 + g;
    int k0 = c * 64 + jn * 8 + 2 * t;
    const float* mw = mask + (size_t)w * NN;
    float4 v;
    v.x = mw[q0 * NTOK + k0];
    v.y = mw[q0 * NTOK + k0 + 1];
    v.z = mw[(q0 + 8) * NTOK + k0];
    v.w = mw[(q0 + 8) * NTOK + k0 + 1];
    bool nz = (v.x != 0.f) | (v.y != 0.f) | (v.z != 0.f) | (v.w != 0.f);
    v.x *= LOG2E; v.y *= LOG2E; v.z *= LOG2E; v.w *= LOG2E;
    g_maskF[(size_t)w * NFRAG + i] = v;
    if (__syncthreads_or(nz) && threadIdx.x == 0)
        atomicOr(&g_maskflag, 1);
}

// ---------------- bias -> fragment layout (*LOG2E) ----------------
__global__ void biasF_kernel(const int* __restrict__ rpb_idx) {
    int i = blockIdx.x * blockDim.x + threadIdx.x;
    if (i >= NFRAG) return;
    int g = i & 7, t = (i >> 3) & 3, jn = (i >> 5) & 7, c = (i >> 8) & 7;
    int wid = (i >> 11) & 7, qt = i >> 14;
    int q0 = qt * 128 + wid * 16 + g;
    int k0 = c * 64 + jn * 8 + 2 * t;
    int i00 = rpb_idx[q0 * NTOK + k0];
    int i10 = rpb_idx[q0 * NTOK + k0 + 1];
    int i01 = rpb_idx[(q0 + 8) * NTOK + k0];
    int i11 = rpb_idx[(q0 + 8) * NTOK + k0 + 1];
    const float S = 16.f * LOG2E;
    #pragma unroll
    for (int h = 0; h < NH; h++) {
        float4 v;
        v.x = S / (1.f + __expf(-g_table[i00 * NH + h]));
        v.y = S / (1.f + __expf(-g_table[i10 * NH + h]));
        v.z = S / (1.f + __expf(-g_table[i01 * NH + h]));
        v.w = S / (1.f + __expf(-g_table[i11 * NH + h]));
        g_biasF[h * NFRAG + i] = v;
    }
}

// =====================  fp16 mma GEMM (NT), cp.async staged  =====
__global__ __launch_bounds__(256, 2) void gemm_h(const __half* __restrict__ A,
                                                 const __half* __restrict__ B,
                                                 const float* __restrict__ bias,
                                                 void* __restrict__ Cv,
                                                 int M, int N, int K, int fp32out) {
    __shared__ __align__(16) __half sA[2][128 * 32];
    __shared__ __align__(16) __half sB[2][128 * 32];
    const int tid = threadIdx.x, lane = tid & 31, wid = tid >> 5;
    const int g = lane >> 2, t = lane & 3;
    const int wm = wid & 3, wn = wid >> 2;
    const int row0 = blockIdx.y * 128, col0 = blockIdx.x * 128;

    const int lr = tid >> 2, lc = tid & 3;
    const __half* Ap = A + (size_t)(row0 + lr) * K + lc * 8;
    const __half* Bp = B + (size_t)(col0 + lr) * K + lc * 8;
    const size_t rstep = (size_t)64 * K;
    const uint32_t so0 = swz(lr, lc), so1 = swz(lr + 64, lc);
    const uint32_t aS[2] = { cvta_s(sA[0]), cvta_s(sA[1]) };
    const uint32_t bS[2] = { cvta_s(sB[0]), cvta_s(sB[1]) };

    float acc[2][8][4];
    #pragma unroll
    for (int mt = 0; mt < 2; mt++)
        #pragma unroll
        for (int jn = 0; jn < 8; jn++)
            #pragma unroll
            for (int r = 0; r < 4; r++) acc[mt][jn][r] = 0.f;

    // prologue: stage chunk 0
    cp16(aS[0] + so0, Ap);
    cp16(aS[0] + so1, Ap + rstep);
    cp16(bS[0] + so0, Bp);
    cp16(bS[0] + so1, Bp + rstep);
    cp_commit();

    const int nk = K >> 5;
    for (int kt = 0; kt < nk; kt++) {
        const int s = kt & 1;
        cp_wait0();
        __syncthreads();
        if (kt + 1 < nk) {
            int ko = (kt + 1) * 32;
            cp16(aS[s ^ 1] + so0, Ap + ko);
            cp16(aS[s ^ 1] + so1, Ap + rstep + ko);
            cp16(bS[s ^ 1] + so0, Bp + ko);
            cp16(bS[s ^ 1] + so1, Bp + rstep + ko);
            cp_commit();
        }
        #pragma unroll
        for (int ks = 0; ks < 2; ks++) {
            uint32_t af[2][4];
            #pragma unroll
            for (int mt = 0; mt < 2; mt++) {
                int row = wm * 32 + mt * 16 + (lane & 15);
                int kch = ks * 2 + ((lane >> 4) & 1);
                ldsm4(af[mt], aS[s] + swz(row, kch));
            }
            uint32_t bf[4][4];
            #pragma unroll
            for (int i = 0; i < 4; i++) {
                int rn = wn * 64 + i * 16 + ((lane >> 4) << 3) + (lane & 7);
                int kch = ks * 2 + ((lane & 8) >> 3);
                ldsm4(bf[i], bS[s] + swz(rn, kch));
            }
            #pragma unroll
            for (int mt = 0; mt < 2; mt++)
                #pragma unroll
                for (int jn = 0; jn < 8; jn++)
                    mma_f16(acc[mt][jn], af[mt],
                            bf[jn >> 1][(jn & 1) * 2], bf[jn >> 1][(jn & 1) * 2 + 1]);
        }
    }

    if (fp32out) {
        float* C = (float*)Cv;
        #pragma unroll
        for (int mt = 0; mt < 2; mt++) {
            int r = row0 + wm * 32 + mt * 16;
            #pragma unroll
            for (int jn = 0; jn < 8; jn++) {
                int cc = col0 + wn * 64 + jn * 8 + 2 * t;
                float bx = bias[cc], by = bias[cc + 1];
                float2 v0 = { acc[mt][jn][0] + bx, acc[mt][jn][1] + by };
                float2 v1 = { acc[mt][jn][2] + bx, acc[mt][jn][3] + by };
                *(float2*)(C + (size_t)(r + g) * N + cc) = v0;
                *(float2*)(C + (size_t)(r + g + 8) * N + cc) = v1;
            }
        }
    } else {
        __half* C = (__half*)Cv;
        #pragma unroll
        for (int mt = 0; mt < 2; mt++) {
            int r = row0 + wm * 32 + mt * 16;
            #pragma unroll
            for (int jn = 0; jn < 8; jn++) {
                int cc = col0 + wn * 64 + jn * 8 + 2 * t;
                *(uint32_t*)(C + (size_t)(r + g) * N + cc)
                    = pack_half2(acc[mt][jn][0], acc[mt][jn][1]);
                *(uint32_t*)(C + (size_t)(r + g + 8) * N + cc)
                    = pack_half2(acc[mt][jn][2], acc[mt][jn][3]);
            }
        }
    }
}

// =====================  fused fp16 mma attention (base-2, fragment bias) ====
__global__ __launch_bounds__(256, 2) void attn_h() {
    __shared__ __align__(16) __half Ks[2][64 * 32];
    __shared__ __align__(16) __half Vs[2][64 * 32];
    const int b = blockIdx.x, h = blockIdx.y, qt = blockIdx.z;
    const int tid = threadIdx.x, lane = tid & 31, wid = tid >> 5;
    const int g = lane >> 2, t = lane & 3;
    const int q0 = qt * 128 + wid * 16;
    const __half* base = g_qkv + (size_t)b * NTOK * QKV_LD;
    const float SCALE2 = 0.17677669529663687f * LOG2E;
    const bool use_mask = (g_maskflag != 0);

    const int skey = tid >> 2, sch = tid & 3;
    const __half* kp = base + (size_t)skey * QKV_LD + DIM + h * HD + sch * 8;
    const __half* vp = kp + DIM;
    const uint32_t soff = swz(skey, sch);
    const uint32_t kS[2] = { cvta_s(Ks[0]), cvta_s(Ks[1]) };
    const uint32_t vS[2] = { cvta_s(Vs[0]), cvta_s(Vs[1]) };

    // prologue: stage chunk 0
    cp16(kS[0] + soff, kp);
    cp16(vS[0] + soff, vp);
    cp_commit();

    uint32_t qa[2][4];
    {
        const __half* qp0 = base + (size_t)(q0 + g) * QKV_LD + h * HD;
        const __half* qp8 = qp0 + (size_t)8 * QKV_LD;
        #pragma unroll
        for (int ks = 0; ks < 2; ks++) {
            qa[ks][0] = *(const uint32_t*)(qp0 + ks * 16 + 2 * t);
            qa[ks][1] = *(const uint32_t*)(qp8 + ks * 16 + 2 * t);
            qa[ks][2] = *(const uint32_t*)(qp0 + ks * 16 + 8 + 2 * t);
            qa[ks][3] = *(const uint32_t*)(qp8 + ks * 16 + 8 + 2 * t);
        }
    }

    float o[4][4];
    #pragma unroll
    for (int nd = 0; nd < 4; nd++)
        #pragma unroll
        for (int r = 0; r < 4; r++) o[nd][r] = 0.f;
    float m0 = -1e30f, m1 = -1e30f, l0 = 0.f, l1 = 0.f;

    // fragment-layout bias/mask pointers for this (h|w, qt, wid, t, g)
    const float4* bp4 = g_biasF + (((size_t)h * 4 + qt) * 8 + wid) * 2048 + t * 8 + g;
    const float4* mp4 = g_maskF + (((size_t)(b & (NWIN - 1)) * 4 + qt) * 8 + wid) * 2048
                                + t * 8 + g;

    for (int c = 0; c < 8; c++) {
        const int s = c & 1;
        cp_wait0();
        __syncthreads();
        if (c < 7) {
            const __half* kn = kp + (size_t)(c + 1) * 64 * QKV_LD;
            cp16(kS[s ^ 1] + soff, kn);
            cp16(vS[s ^ 1] + soff, kn + DIM);
            cp_commit();
        }

        // ---- S = Q K^T ----
        float sc[8][4];
        #pragma unroll
        for (int jn = 0; jn < 8; jn++)
            sc[jn][0] = sc[jn][1] = sc[jn][2] = sc[jn][3] = 0.f;
        #pragma unroll
        for (int ks = 0; ks < 2; ks++) {
            uint32_t kb[4][4];
            #pragma unroll
            for (int i = 0; i < 4; i++) {
                int rn = i * 16 + ((lane >> 4) << 3) + (lane & 7);
                int kch = ks * 2 + ((lane & 8) >> 3);
                ldsm4(kb[i], kS[s] + swz(rn, kch));
            }
            #pragma unroll
            for (int jn = 0; jn < 8; jn++)
                mma_f16(sc[jn], qa[ks],
                        kb[jn >> 1][(jn & 1) * 2], kb[jn >> 1][(jn & 1) * 2 + 1]);
        }
        // scale + fragment bias (+ mask if present)
        const float4* bc = bp4 + c * 256;
        const float4* mc = mp4 + c * 256;
        #pragma unroll
        for (int jn = 0; jn < 8; jn++) {
            float4 bv = bc[jn * 32];
            if (use_mask) {
                float4 mv = mc[jn * 32];
                bv.x += mv.x; bv.y += mv.y; bv.z += mv.z; bv.w += mv.w;
            }
            sc[jn][0] = fmaf(sc[jn][0], SCALE2, bv.x);
            sc[jn][1] = fmaf(sc[jn][1], SCALE2, bv.y);
            sc[jn][2] = fmaf(sc[jn][2], SCALE2, bv.z);
            sc[jn][3] = fmaf(sc[jn][3], SCALE2, bv.w);
        }

        // ---- online softmax (base 2) ----
        float mx0 = sc[0][0], mx1 = sc[0][2];
        #pragma unroll
        for (int jn = 0; jn < 8; jn++) {
            mx0 = fmaxf(mx0, fmaxf(sc[jn][0], sc[jn][1]));
            mx1 = fmaxf(mx1, fmaxf(sc[jn][2], sc[jn][3]));
        }
        mx0 = fmaxf(mx0, __shfl_xor_sync(0xffffffffu, mx0, 1));
        mx0 = fmaxf(mx0, __shfl_xor_sync(0xffffffffu, mx0, 2));
        mx1 = fmaxf(mx1, __shfl_xor_sync(0xffffffffu, mx1, 1));
        mx1 = fmaxf(mx1, __shfl_xor_sync(0xffffffffu, mx1, 2));
        float nm0 = fmaxf(m0, mx0), nm1 = fmaxf(m1, mx1);
        float c0 = exp2f(m0 - nm0), c1 = exp2f(m1 - nm1);
        m0 = nm0; m1 = nm1;
        l0 *= c0; l1 *= c1;
        #pragma unroll
        for (int nd = 0; nd < 4; nd++) {
            o[nd][0] *= c0; o[nd][1] *= c0;
            o[nd][2] *= c1; o[nd][3] *= c1;
        }

        // ---- P = 2^(S-m) ----
        uint32_t pa[4][4];
        #pragma unroll
        for (int kk = 0; kk < 4; kk++) {
            float pA0 = exp2f(sc[2*kk][0] - m0), pA1 = exp2f(sc[2*kk][1] - m0);
            float pA2 = exp2f(sc[2*kk][2] - m1), pA3 = exp2f(sc[2*kk][3] - m1);
            float pB0 = exp2f(sc[2*kk+1][0] - m0), pB1 = exp2f(sc[2*kk+1][1] - m0);
            float pB2 = exp2f(sc[2*kk+1][2] - m1), pB3 = exp2f(sc[2*kk+1][3] - m1);
            l0 += (pA0 + pA1) + (pB0 + pB1);
            l1 += (pA2 + pA3) + (pB2 + pB3);
            pa[kk][0] = pack_half2(pA0, pA1);
            pa[kk][1] = pack_half2(pA2, pA3);
            pa[kk][2] = pack_half2(pB0, pB1);
            pa[kk][3] = pack_half2(pB2, pB3);
        }

        // ---- O += P V ----
        #pragma unroll
        for (int ndp = 0; ndp < 2; ndp++)
            #pragma unroll
            for (int kk = 0; kk < 4; kk++) {
                uint32_t vb[4];
                int key = kk * 16 + (lane & 15);
                int kch = ndp * 2 + (lane >> 4);
                ldsm4t(vb, vS[s] + swz(key, kch));
                mma_f16(o[ndp * 2],     pa[kk], vb[0], vb[1]);
                mma_f16(o[ndp * 2 + 1], pa[kk], vb[2], vb[3]);
            }
        __syncthreads();
    }

    l0 += __shfl_xor_sync(0xffffffffu, l0, 1);
    l0 += __shfl_xor_sync(0xffffffffu, l0, 2);
    l1 += __shfl_xor_sync(0xffffffffu, l1, 1);
    l1 += __shfl_xor_sync(0xffffffffu, l1, 2);
    float i0 = 1.f / l0, i1 = 1.f / l1;
    __half* op0 = g_att + ((size_t)b * NTOK + q0 + g) * DIM + h * HD;
    __half* op8 = op0 + (size_t)8 * DIM;
    #pragma unroll
    for (int nd = 0; nd < 4; nd++) {
        *(uint32_t*)(op0 + nd * 8 + 2 * t) = pack_half2(o[nd][0] * i0, o[nd][1] * i0);
        *(uint32_t*)(op8 + nd * 8 + 2 * t) = pack_half2(o[nd][2] * i1, o[nd][3] * i1);
    }
}

// ---------------- launch ----------------
extern "C" void kernel_launch(void* const* d_in, const int* in_sizes, int n_in,
                              void* d_out, int out_size) {
    const float* x      = (const float*)d_in[0];
    const float* mask   = (const float*)d_in[1];
    const float* qkv_w  = (const float*)d_in[2];
    const float* proj_w = (const float*)d_in[3];
    const float* proj_b = (const float*)d_in[4];
    const float* cpb_w1 = (const float*)d_in[5];
    const float* cpb_b1 = (const float*)d_in[6];
    const float* cpb_w2 = (const float*)d_in[7];
    const float* rpb    = (const float*)d_in[8];
    const int*   rpb_idx = (const int*)d_in[9];
    float* out = (float*)d_out;

    static __half *p_xh = nullptr, *p_qkvw = nullptr, *p_projw = nullptr,
                  *p_qkv = nullptr, *p_att = nullptr;
    if (!p_xh) {
        cudaGetSymbolAddress((void**)&p_xh, g_xh);
        cudaGetSymbolAddress((void**)&p_qkvw, g_qkvw);
        cudaGetSymbolAddress((void**)&p_projw, g_projw);
        cudaGetSymbolAddress((void**)&p_qkv, g_qkv);
        cudaGetSymbolAddress((void**)&p_att, g_att);
    }

    // 0) merged conversions (+ mask flag reset)
    {
        int total = N8X + N8W + N8P;
        cvt_all<<<(total + 255) / 256, 256>>>(x, qkv_w, proj_w);
    }
    // 1) CPB table
    cpb_kernel<<<TABLE_E, 256>>>(rpb, cpb_w1, cpb_b1, cpb_w2);
    // 2) mask -> fragment layout + flag
    maskF_kernel<<<dim3(NFRAG / 256, NWIN), 256>>>(mask);
    // 3) bias -> fragment layout
    biasF_kernel<<<NFRAG / 256, 256>>>(rpb_idx);
    // 4) QKV projection
    {
        dim3 grid(QKV_LD / 128, (BATCH * NTOK) / 128);
        gemm_h<<<grid, 256>>>(p_xh, p_qkvw, nullptr, p_qkv,
                              BATCH * NTOK, QKV_LD, DIM, 0);
    }
    // 5) fused attention
    attn_h<<<dim3(BATCH, NH, NTOK / 128), 256>>>();
    // 6) output projection
    {
        dim3 grid(DIM / 128, (BATCH * NTOK) / 128);
        gemm_h<<<grid, 256>>>(p_att, p_projw, proj_b, out,
                              BATCH * NTOK, DIM, DIM, 1);
    }
}

// round 8
// speedup vs baseline: 4.8126x; 1.0310x over previous
#include <cuda_runtime.h>
#include <cuda_fp16.h>
#include <math.h>
#include <stdint.h>

#define BATCH   128
#define NWIN    16
#define NTOK    512
#define DIM     256
#define NH      8
#define HD      32
#define TABLE_E 3375
#define QKV_LD  768
#define NN      (NTOK*NTOK)
#define LOG2E   1.4426950408889634f
#define NFRAG   65536   // float4 fragments per (h or w) slab

// ---------------- scratch (device globals) ----------------
__device__ float  g_table[TABLE_E * NH];
__device__ float4 g_biasF[NH * NFRAG];      // fragment-layout bias *LOG2E
__device__ float4 g_maskF[NWIN * NFRAG];    // fragment-layout mask *LOG2E
__device__ int    g_maskflag;
__device__ __half g_xh[(size_t)BATCH * NTOK * DIM];
__device__ __half g_qkvw[QKV_LD * DIM];
__device__ __half g_projw[DIM * DIM];
__device__ __half g_qkv[(size_t)BATCH * NTOK * QKV_LD];
__device__ __half g_att[(size_t)BATCH * NTOK * DIM];

// =====================  helpers  =====================
__device__ __forceinline__ uint32_t pack_half2(float lo, float hi) {
    __half2 h = __floats2half2_rn(lo, hi);
    return *(uint32_t*)&h;
}
__device__ __forceinline__ void mma_f16(float* d, const uint32_t* a,
                                        uint32_t b0, uint32_t b1) {
    asm volatile(
        "mma.sync.aligned.m16n8k16.row.col.f32.f16.f16.f32 "
        "{%0,%1,%2,%3}, {%4,%5,%6,%7}, {%8,%9}, {%0,%1,%2,%3};"
        : "+f"(d[0]), "+f"(d[1]), "+f"(d[2]), "+f"(d[3])
        : "r"(a[0]), "r"(a[1]), "r"(a[2]), "r"(a[3]), "r"(b0), "r"(b1));
}
__device__ __forceinline__ void ldsm4(uint32_t* r, uint32_t addr) {
    asm volatile("ldmatrix.sync.aligned.m8n8.x4.shared.b16 {%0,%1,%2,%3}, [%4];"
                 : "=r"(r[0]), "=r"(r[1]), "=r"(r[2]), "=r"(r[3]) : "r"(addr));
}
__device__ __forceinline__ void ldsm4t(uint32_t* r, uint32_t addr) {
    asm volatile("ldmatrix.sync.aligned.m8n8.x4.trans.shared.b16 {%0,%1,%2,%3}, [%4];"
                 : "=r"(r[0]), "=r"(r[1]), "=r"(r[2]), "=r"(r[3]) : "r"(addr));
}
__device__ __forceinline__ uint32_t cvta_s(const void* p) {
    return (uint32_t)__cvta_generic_to_shared(p);
}
// 64B-row swizzle (attention K/V tiles: 32 halves/row, 4 chunks)
__device__ __forceinline__ uint32_t swz(int r, int kchunk) {
    return (uint32_t)(r * 64 + ((kchunk ^ ((r >> 1) & 3)) << 4));
}
// 128B-row swizzle (gemm tiles: 64 halves/row, 8 chunks)
__device__ __forceinline__ uint32_t swz128(int r, int kchunk) {
    return (uint32_t)(r * 128 + ((kchunk ^ (r & 7)) << 4));
}
__device__ __forceinline__ void cp16(uint32_t smem, const void* g) {
    asm volatile("cp.async.cg.shared.global [%0], [%1], 16;"
                 :: "r"(smem), "l"(g) : "memory");
}
__device__ __forceinline__ void cp_commit() {
    asm volatile("cp.async.commit_group;" ::: "memory");
}
__device__ __forceinline__ void cp_wait0() {
    asm volatile("cp.async.wait_group 0;" ::: "memory");
}

// ---------------- prep0: fp32->fp16 conversions + CPB MLP (grid-partitioned)
#define N8X ((BATCH * NTOK * DIM) / 8)
#define N8W ((QKV_LD * DIM) / 8)
#define N8P ((DIM * DIM) / 8)
#define N8T (N8X + N8W + N8P)
#define NCVT_BLK ((N8T + 255) / 256)
__global__ void prep0(const float* __restrict__ x,
                      const float* __restrict__ qw,
                      const float* __restrict__ pw,
                      const float* __restrict__ rpb,
                      const float* __restrict__ w1,
                      const float* __restrict__ b1,
                      const float* __restrict__ w2) {
    int bx = blockIdx.x;
    if (bx < NCVT_BLK) {
        int i = bx * 256 + threadIdx.x;
        if (i == 0) g_maskflag = 0;
        const float* s;
        __half* d;
        int j;
        if (i < N8X)                  { s = x;  d = g_xh;    j = i; }
        else if (i < N8X + N8W)       { s = qw; d = g_qkvw;  j = i - N8X; }
        else if (i < N8T)             { s = pw; d = g_projw; j = i - N8X - N8W; }
        else return;
        const float4* sp = (const float4*)s + (size_t)j * 2;
        float4 a = sp[0], b = sp[1];
        uint4 o;
        o.x = pack_half2(a.x, a.y); o.y = pack_half2(a.z, a.w);
        o.z = pack_half2(b.x, b.y); o.w = pack_half2(b.z, b.w);
        ((uint4*)d)[j] = o;
    } else {
        int e = bx - NCVT_BLK;            // 0..TABLE_E-1
        int h = threadIdx.x >> 5;
        int lane = threadIdx.x & 31;
        float r0 = rpb[e * 3 + 0], r1 = rpb[e * 3 + 1], r2 = rpb[e * 3 + 2];
        float sum = 0.f;
        for (int o = lane; o < 512; o += 32) {
            float hid = fmaf(r0, w1[o * 3 + 0],
                        fmaf(r1, w1[o * 3 + 1],
                        fmaf(r2, w1[o * 3 + 2], b1[o])));
            hid = fmaxf(hid, 0.f);
            sum = fmaf(hid, w2[h * 512 + o], sum);
        }
        #pragma unroll
        for (int off = 16; off; off >>= 1)
            sum += __shfl_xor_sync(0xffffffffu, sum, off);
        if (lane == 0) g_table[e * NH + h] = sum;
    }
}

// ---------------- prep1: maskF (blocks 0..4095) + biasF (4096..4351) --------
// fragment decode: i -> (qt,wid,c,jn,t,g); float4 = {(k0,q0),(k0+1,q0),(k0,q0+8),(k0+1,q0+8)}
__global__ void prep1(const float* __restrict__ mask,
                      const int* __restrict__ rpb_idx) {
    int bx = blockIdx.x;
    if (bx < 4096) {
        int w = bx >> 8;
        int i = (bx & 255) * 256 + threadIdx.x;
        int g = i & 7, t = (i >> 3) & 3, jn = (i >> 5) & 7, c = (i >> 8) & 7;
        int wid = (i >> 11) & 7, qt = i >> 14;
        int q0 = qt * 128 + wid * 16 + g;
        int k0 = c * 64 + jn * 8 + 2 * t;
        const float* mw = mask + (size_t)w * NN;
        float4 v;
        v.x = mw[q0 * NTOK + k0];
        v.y = mw[q0 * NTOK + k0 + 1];
        v.z = mw[(q0 + 8) * NTOK + k0];
        v.w = mw[(q0 + 8) * NTOK + k0 + 1];
        bool nz = (v.x != 0.f) | (v.y != 0.f) | (v.z != 0.f) | (v.w != 0.f);
        v.x *= LOG2E; v.y *= LOG2E; v.z *= LOG2E; v.w *= LOG2E;
        g_maskF[(size_t)w * NFRAG + i] = v;
        if (__syncthreads_or(nz) && threadIdx.x == 0)
            atomicOr(&g_maskflag, 1);
    } else {
        int i = (bx - 4096) * 256 + threadIdx.x;
        int g = i & 7, t = (i >> 3) & 3, jn = (i >> 5) & 7, c = (i >> 8) & 7;
        int wid = (i >> 11) & 7, qt = i >> 14;
        int q0 = qt * 128 + wid * 16 + g;
        int k0 = c * 64 + jn * 8 + 2 * t;
        int i00 = rpb_idx[q0 * NTOK + k0];
        int i10 = rpb_idx[q0 * NTOK + k0 + 1];
        int i01 = rpb_idx[(q0 + 8) * NTOK + k0];
        int i11 = rpb_idx[(q0 + 8) * NTOK + k0 + 1];
        const float S = 16.f * LOG2E;
        #pragma unroll
        for (int h = 0; h < NH; h++) {
            float4 v;
            v.x = S / (1.f + __expf(-g_table[i00 * NH + h]));
            v.y = S / (1.f + __expf(-g_table[i10 * NH + h]));
            v.z = S / (1.f + __expf(-g_table[i01 * NH + h]));
            v.w = S / (1.f + __expf(-g_table[i11 * NH + h]));
            g_biasF[h * NFRAG + i] = v;
        }
    }
}

// =====================  fp16 mma GEMM (NT), 64x64 warp tiles, BK=64  =====
// 128 threads (4 warps, 2x2), 128x128 block tile, dynamic smem 64 KB
#define GSMEM (4 * 16384)
__global__ __launch_bounds__(128, 2) void gemm_h(const __half* __restrict__ A,
                                                 const __half* __restrict__ B,
                                                 const float* __restrict__ bias,
                                                 void* __restrict__ Cv,
                                                 int M, int N, int K, int fp32out) {
    extern __shared__ __align__(16) char gsm[];
    const int tid = threadIdx.x, lane = tid & 31, wid = tid >> 5;
    const int g = lane >> 2, t = lane & 3;
    const int wm = wid & 1, wn = wid >> 1;
    const int row0 = blockIdx.y * 128, col0 = blockIdx.x * 128;

    // staging map: thread covers chunk column lc (16B), rows lr0 + i*16
    const int lr0 = tid >> 3, lc = tid & 7;
    const __half* Ap = A + (size_t)(row0 + lr0) * K + lc * 8;
    const __half* Bp = B + (size_t)(col0 + lr0) * K + lc * 8;
    const size_t rstep = (size_t)16 * K;
    uint32_t aS[2] = { cvta_s(gsm), cvta_s(gsm) + 16384 };
    uint32_t bS[2] = { cvta_s(gsm) + 32768, cvta_s(gsm) + 49152 };
    uint32_t soffs[8];
    #pragma unroll
    for (int i = 0; i < 8; i++) soffs[i] = swz128(lr0 + i * 16, lc);

    float acc[4][8][4];
    #pragma unroll
    for (int mt = 0; mt < 4; mt++)
        #pragma unroll
        for (int jn = 0; jn < 8; jn++)
            #pragma unroll
            for (int r = 0; r < 4; r++) acc[mt][jn][r] = 0.f;

    // prologue: stage chunk 0
    #pragma unroll
    for (int i = 0; i < 8; i++) {
        cp16(aS[0] + soffs[i], Ap + i * rstep);
        cp16(bS[0] + soffs[i], Bp + i * rstep);
    }
    cp_commit();

    const int nk = K >> 6;   // BK=64
    for (int kt = 0; kt < nk; kt++) {
        const int s = kt & 1;
        cp_wait0();
        __syncthreads();
        if (kt + 1 < nk) {
            int ko = (kt + 1) * 64;
            #pragma unroll
            for (int i = 0; i < 8; i++) {
                cp16(aS[s ^ 1] + soffs[i], Ap + i * rstep + ko);
                cp16(bS[s ^ 1] + soffs[i], Bp + i * rstep + ko);
            }
            cp_commit();
        }
        #pragma unroll
        for (int ks = 0; ks < 4; ks++) {
            uint32_t af[4][4];
            #pragma unroll
            for (int mt = 0; mt < 4; mt++) {
                int row = wm * 64 + mt * 16 + (lane & 15);
                int kch = ks * 2 + (lane >> 4);
                ldsm4(af[mt], aS[s] + swz128(row, kch));
            }
            uint32_t bf[4][4];
            #pragma unroll
            for (int i = 0; i < 4; i++) {
                int rn = wn * 64 + i * 16 + ((lane >> 4) << 3) + (lane & 7);
                int kch = ks * 2 + ((lane & 8) >> 3);
                ldsm4(bf[i], bS[s] + swz128(rn, kch));
            }
            #pragma unroll
            for (int mt = 0; mt < 4; mt++)
                #pragma unroll
                for (int jn = 0; jn < 8; jn++)
                    mma_f16(acc[mt][jn], af[mt],
                            bf[jn >> 1][(jn & 1) * 2], bf[jn >> 1][(jn & 1) * 2 + 1]);
        }
        __syncthreads();
    }

    if (fp32out) {
        float* C = (float*)Cv;
        #pragma unroll
        for (int mt = 0; mt < 4; mt++) {
            int r = row0 + wm * 64 + mt * 16;
            #pragma unroll
            for (int jn = 0; jn < 8; jn++) {
                int cc = col0 + wn * 64 + jn * 8 + 2 * t;
                float bx = bias[cc], by = bias[cc + 1];
                float2 v0 = { acc[mt][jn][0] + bx, acc[mt][jn][1] + by };
                float2 v1 = { acc[mt][jn][2] + bx, acc[mt][jn][3] + by };
                *(float2*)(C + (size_t)(r + g) * N + cc) = v0;
                *(float2*)(C + (size_t)(r + g + 8) * N + cc) = v1;
            }
        }
    } else {
        __half* C = (__half*)Cv;
        #pragma unroll
        for (int mt = 0; mt < 4; mt++) {
            int r = row0 + wm * 64 + mt * 16;
            #pragma unroll
            for (int jn = 0; jn < 8; jn++) {
                int cc = col0 + wn * 64 + jn * 8 + 2 * t;
                *(uint32_t*)(C + (size_t)(r + g) * N + cc)
                    = pack_half2(acc[mt][jn][0], acc[mt][jn][1]);
                *(uint32_t*)(C + (size_t)(r + g + 8) * N + cc)
                    = pack_half2(acc[mt][jn][2], acc[mt][jn][3]);
            }
        }
    }
}

// =====================  fused fp16 mma attention (base-2, fragment bias) ====
__global__ __launch_bounds__(256, 2) void attn_h() {
    __shared__ __align__(16) __half Ks[2][64 * 32];
    __shared__ __align__(16) __half Vs[2][64 * 32];
    const int b = blockIdx.x, h = blockIdx.y, qt = blockIdx.z;
    const int tid = threadIdx.x, lane = tid & 31, wid = tid >> 5;
    const int g = lane >> 2, t = lane & 3;
    const int q0 = qt * 128 + wid * 16;
    const __half* base = g_qkv + (size_t)b * NTOK * QKV_LD;
    const float SCALE2 = 0.17677669529663687f * LOG2E;
    const bool use_mask = (g_maskflag != 0);

    const int skey = tid >> 2, sch = tid & 3;
    const __half* kp = base + (size_t)skey * QKV_LD + DIM + h * HD + sch * 8;
    const __half* vp = kp + DIM;
    const uint32_t soff = swz(skey, sch);
    const uint32_t kS[2] = { cvta_s(Ks[0]), cvta_s(Ks[1]) };
    const uint32_t vS[2] = { cvta_s(Vs[0]), cvta_s(Vs[1]) };

    cp16(kS[0] + soff, kp);
    cp16(vS[0] + soff, vp);
    cp_commit();

    uint32_t qa[2][4];
    {
        const __half* qp0 = base + (size_t)(q0 + g) * QKV_LD + h * HD;
        const __half* qp8 = qp0 + (size_t)8 * QKV_LD;
        #pragma unroll
        for (int ks = 0; ks < 2; ks++) {
            qa[ks][0] = *(const uint32_t*)(qp0 + ks * 16 + 2 * t);
            qa[ks][1] = *(const uint32_t*)(qp8 + ks * 16 + 2 * t);
            qa[ks][2] = *(const uint32_t*)(qp0 + ks * 16 + 8 + 2 * t);
            qa[ks][3] = *(const uint32_t*)(qp8 + ks * 16 + 8 + 2 * t);
        }
    }

    float o[4][4];
    #pragma unroll
    for (int nd = 0; nd < 4; nd++)
        #pragma unroll
        for (int r = 0; r < 4; r++) o[nd][r] = 0.f;
    float m0 = -1e30f, m1 = -1e30f, l0 = 0.f, l1 = 0.f;

    const float4* bp4 = g_biasF + (((size_t)h * 4 + qt) * 8 + wid) * 2048 + t * 8 + g;
    const float4* mp4 = g_maskF + (((size_t)(b & (NWIN - 1)) * 4 + qt) * 8 + wid) * 2048
                                + t * 8 + g;

    for (int c = 0; c < 8; c++) {
        const int s = c & 1;
        cp_wait0();
        __syncthreads();
        if (c < 7) {
            const __half* kn = kp + (size_t)(c + 1) * 64 * QKV_LD;
            cp16(kS[s ^ 1] + soff, kn);
            cp16(vS[s ^ 1] + soff, kn + DIM);
            cp_commit();
        }

        float sc[8][4];
        #pragma unroll
        for (int jn = 0; jn < 8; jn++)
            sc[jn][0] = sc[jn][1] = sc[jn][2] = sc[jn][3] = 0.f;
        #pragma unroll
        for (int ks = 0; ks < 2; ks++) {
            uint32_t kb[4][4];
            #pragma unroll
            for (int i = 0; i < 4; i++) {
                int rn = i * 16 + ((lane >> 4) << 3) + (lane & 7);
                int kch = ks * 2 + ((lane & 8) >> 3);
                ldsm4(kb[i], kS[s] + swz(rn, kch));
            }
            #pragma unroll
            for (int jn = 0; jn < 8; jn++)
                mma_f16(sc[jn], qa[ks],
                        kb[jn >> 1][(jn & 1) * 2], kb[jn >> 1][(jn & 1) * 2 + 1]);
        }
        const float4* bc = bp4 + c * 256;
        const float4* mc = mp4 + c * 256;
        #pragma unroll
        for (int jn = 0; jn < 8; jn++) {
            float4 bv = bc[jn * 32];
            if (use_mask) {
                float4 mv = mc[jn * 32];
                bv.x += mv.x; bv.y += mv.y; bv.z += mv.z; bv.w += mv.w;
            }
            sc[jn][0] = fmaf(sc[jn][0], SCALE2, bv.x);
            sc[jn][1] = fmaf(sc[jn][1], SCALE2, bv.y);
            sc[jn][2] = fmaf(sc[jn][2], SCALE2, bv.z);
            sc[jn][3] = fmaf(sc[jn][3], SCALE2, bv.w);
        }

        float mx0 = sc[0][0], mx1 = sc[0][2];
        #pragma unroll
        for (int jn = 0; jn < 8; jn++) {
            mx0 = fmaxf(mx0, fmaxf(sc[jn][0], sc[jn][1]));
            mx1 = fmaxf(mx1, fmaxf(sc[jn][2], sc[jn][3]));
        }
        mx0 = fmaxf(mx0, __shfl_xor_sync(0xffffffffu, mx0, 1));
        mx0 = fmaxf(mx0, __shfl_xor_sync(0xffffffffu, mx0, 2));
        mx1 = fmaxf(mx1, __shfl_xor_sync(0xffffffffu, mx1, 1));
        mx1 = fmaxf(mx1, __shfl_xor_sync(0xffffffffu, mx1, 2));
        float nm0 = fmaxf(m0, mx0), nm1 = fmaxf(m1, mx1);
        float c0 = exp2f(m0 - nm0), c1 = exp2f(m1 - nm1);
        m0 = nm0; m1 = nm1;
        l0 *= c0; l1 *= c1;
        #pragma unroll
        for (int nd = 0; nd < 4; nd++) {
            o[nd][0] *= c0; o[nd][1] *= c0;
            o[nd][2] *= c1; o[nd][3] *= c1;
        }

        uint32_t pa[4][4];
        #pragma unroll
        for (int kk = 0; kk < 4; kk++) {
            float pA0 = exp2f(sc[2*kk][0] - m0), pA1 = exp2f(sc[2*kk][1] - m0);
            float pA2 = exp2f(sc[2*kk][2] - m1), pA3 = exp2f(sc[2*kk][3] - m1);
            float pB0 = exp2f(sc[2*kk+1][0] - m0), pB1 = exp2f(sc[2*kk+1][1] - m0);
            float pB2 = exp2f(sc[2*kk+1][2] - m1), pB3 = exp2f(sc[2*kk+1][3] - m1);
            l0 += (pA0 + pA1) + (pB0 + pB1);
            l1 += (pA2 + pA3) + (pB2 + pB3);
            pa[kk][0] = pack_half2(pA0, pA1);
            pa[kk][1] = pack_half2(pA2, pA3);
            pa[kk][2] = pack_half2(pB0, pB1);
            pa[kk][3] = pack_half2(pB2, pB3);
        }

        #pragma unroll
        for (int ndp = 0; ndp < 2; ndp++)
            #pragma unroll
            for (int kk = 0; kk < 4; kk++) {
                uint32_t vb[4];
                int key = kk * 16 + (lane & 15);
                int kch = ndp * 2 + (lane >> 4);
                ldsm4t(vb, vS[s] + swz(key, kch));
                mma_f16(o[ndp * 2],     pa[kk], vb[0], vb[1]);
                mma_f16(o[ndp * 2 + 1], pa[kk], vb[2], vb[3]);
            }
        __syncthreads();
    }

    l0 += __shfl_xor_sync(0xffffffffu, l0, 1);
    l0 += __shfl_xor_sync(0xffffffffu, l0, 2);
    l1 += __shfl_xor_sync(0xffffffffu, l1, 1);
    l1 += __shfl_xor_sync(0xffffffffu, l1, 2);
    float i0 = 1.f / l0, i1 = 1.f / l1;
    __half* op0 = g_att + ((size_t)b * NTOK + q0 + g) * DIM + h * HD;
    __half* op8 = op0 + (size_t)8 * DIM;
    #pragma unroll
    for (int nd = 0; nd < 4; nd++) {
        *(uint32_t*)(op0 + nd * 8 + 2 * t) = pack_half2(o[nd][0] * i0, o[nd][1] * i0);
        *(uint32_t*)(op8 + nd * 8 + 2 * t) = pack_half2(o[nd][2] * i1, o[nd][3] * i1);
    }
}

// ---------------- launch ----------------
extern "C" void kernel_launch(void* const* d_in, const int* in_sizes, int n_in,
                              void* d_out, int out_size) {
    const float* x      = (const float*)d_in[0];
    const float* mask   = (const float*)d_in[1];
    const float* qkv_w  = (const float*)d_in[2];
    const float* proj_w = (const float*)d_in[3];
    const float* proj_b = (const float*)d_in[4];
    const float* cpb_w1 = (const float*)d_in[5];
    const float* cpb_b1 = (const float*)d_in[6];
    const float* cpb_w2 = (const float*)d_in[7];
    const float* rpb    = (const float*)d_in[8];
    const int*   rpb_idx = (const int*)d_in[9];
    float* out = (float*)d_out;

    static __half *p_xh = nullptr, *p_qkvw = nullptr, *p_projw = nullptr,
                  *p_qkv = nullptr, *p_att = nullptr;
    if (!p_xh) {
        cudaGetSymbolAddress((void**)&p_xh, g_xh);
        cudaGetSymbolAddress((void**)&p_qkvw, g_qkvw);
        cudaGetSymbolAddress((void**)&p_projw, g_projw);
        cudaGetSymbolAddress((void**)&p_qkv, g_qkv);
        cudaGetSymbolAddress((void**)&p_att, g_att);
        cudaFuncSetAttribute(gemm_h,
                             cudaFuncAttributeMaxDynamicSharedMemorySize, GSMEM);
    }

    // 0) conversions + CPB table (fused)
    prep0<<<NCVT_BLK + TABLE_E, 256>>>(x, qkv_w, proj_w,
                                       rpb, cpb_w1, cpb_b1, cpb_w2);
    // 1) maskF + biasF (fused; biasF depends on table from launch 0)
    prep1<<<4096 + NFRAG / 256, 256>>>(mask, rpb_idx);
    // 2) QKV projection
    {
        dim3 grid(QKV_LD / 128, (BATCH * NTOK) / 128);
        gemm_h<<<grid, 128, GSMEM>>>(p_xh, p_qkvw, nullptr, p_qkv,
                                     BATCH * NTOK, QKV_LD, DIM, 0);
    }
    // 3) fused attention  (stream index 3 -> ncu capture)
    attn_h<<<dim3(BATCH, NH, NTOK / 128), 256>>>();
    // 4) output projection
    {
        dim3 grid(DIM / 128, (BATCH * NTOK) / 128);
        gemm_h<<<grid, 128, GSMEM>>>(p_att, p_projw, proj_b, out,
                                     BATCH * NTOK, DIM, DIM, 1);
    }
}

// round 9
// speedup vs baseline: 5.1758x; 1.0755x over previous
#include <cuda_runtime.h>
#include <cuda_fp16.h>
#include <math.h>
#include <stdint.h>

#define BATCH   128
#define NWIN    16
#define NTOK    512
#define DIM     256
#define NH      8
#define HD      32
#define TABLE_E 3375
#define QKV_LD  768
#define NN      (NTOK*NTOK)
#define LOG2E   1.4426950408889634f
#define NFRAG   65536   // float4 fragments per (h or w) slab

// ---------------- scratch (device globals) ----------------
__device__ float  g_table[TABLE_E * NH];
__device__ float4 g_biasF[NH * NFRAG];      // fragment-layout bias *LOG2E
__device__ float4 g_maskF[NWIN * NFRAG];    // fragment-layout mask *LOG2E
__device__ int    g_maskflag;
__device__ __half g_xh[(size_t)BATCH * NTOK * DIM];
__device__ __half g_qkvw[QKV_LD * DIM];
__device__ __half g_projw[DIM * DIM];
__device__ __half g_qkv[(size_t)BATCH * NTOK * QKV_LD];
__device__ __half g_att[(size_t)BATCH * NTOK * DIM];

// =====================  helpers  =====================
__device__ __forceinline__ uint32_t pack_half2(float lo, float hi) {
    __half2 h = __floats2half2_rn(lo, hi);
    return *(uint32_t*)&h;
}
__device__ __forceinline__ void mma_f16(float* d, const uint32_t* a,
                                        uint32_t b0, uint32_t b1) {
    asm volatile(
        "mma.sync.aligned.m16n8k16.row.col.f32.f16.f16.f32 "
        "{%0,%1,%2,%3}, {%4,%5,%6,%7}, {%8,%9}, {%0,%1,%2,%3};"
        : "+f"(d[0]), "+f"(d[1]), "+f"(d[2]), "+f"(d[3])
        : "r"(a[0]), "r"(a[1]), "r"(a[2]), "r"(a[3]), "r"(b0), "r"(b1));
}
__device__ __forceinline__ void ldsm4(uint32_t* r, uint32_t addr) {
    asm volatile("ldmatrix.sync.aligned.m8n8.x4.shared.b16 {%0,%1,%2,%3}, [%4];"
                 : "=r"(r[0]), "=r"(r[1]), "=r"(r[2]), "=r"(r[3]) : "r"(addr));
}
__device__ __forceinline__ void ldsm4t(uint32_t* r, uint32_t addr) {
    asm volatile("ldmatrix.sync.aligned.m8n8.x4.trans.shared.b16 {%0,%1,%2,%3}, [%4];"
                 : "=r"(r[0]), "=r"(r[1]), "=r"(r[2]), "=r"(r[3]) : "r"(addr));
}
__device__ __forceinline__ uint32_t cvta_s(const void* p) {
    return (uint32_t)__cvta_generic_to_shared(p);
}
// 64B-row swizzle (attention K/V tiles: 32 halves/row, 4 chunks)
__device__ __forceinline__ uint32_t swz(int r, int kchunk) {
    return (uint32_t)(r * 64 + ((kchunk ^ ((r >> 1) & 3)) << 4));
}
// 128B-row swizzle (gemm tiles: 64 halves/row, 8 chunks)
__device__ __forceinline__ uint32_t swz128(int r, int kchunk) {
    return (uint32_t)(r * 128 + ((kchunk ^ (r & 7)) << 4));
}
__device__ __forceinline__ void cp16(uint32_t smem, const void* g) {
    asm volatile("cp.async.cg.shared.global [%0], [%1], 16;"
                 :: "r"(smem), "l"(g) : "memory");
}
__device__ __forceinline__ void cp_commit() {
    asm volatile("cp.async.commit_group;" ::: "memory");
}
__device__ __forceinline__ void cp_wait0() {
    asm volatile("cp.async.wait_group 0;" ::: "memory");
}

// ---------------- prep0: fp32->fp16 conversions + CPB MLP (grid-partitioned)
#define N8X ((BATCH * NTOK * DIM) / 8)
#define N8W ((QKV_LD * DIM) / 8)
#define N8P ((DIM * DIM) / 8)
#define N8T (N8X + N8W + N8P)
#define NCVT_BLK ((N8T + 255) / 256)
__global__ void prep0(const float* __restrict__ x,
                      const float* __restrict__ qw,
                      const float* __restrict__ pw,
                      const float* __restrict__ rpb,
                      const float* __restrict__ w1,
                      const float* __restrict__ b1,
                      const float* __restrict__ w2) {
    int bx = blockIdx.x;
    if (bx < NCVT_BLK) {
        int i = bx * 256 + threadIdx.x;
        if (i == 0) g_maskflag = 0;
        const float* s;
        __half* d;
        int j;
        if (i < N8X)                  { s = x;  d = g_xh;    j = i; }
        else if (i < N8X + N8W)       { s = qw; d = g_qkvw;  j = i - N8X; }
        else if (i < N8T)             { s = pw; d = g_projw; j = i - N8X - N8W; }
        else return;
        const float4* sp = (const float4*)s + (size_t)j * 2;
        float4 a = sp[0], b = sp[1];
        uint4 o;
        o.x = pack_half2(a.x, a.y); o.y = pack_half2(a.z, a.w);
        o.z = pack_half2(b.x, b.y); o.w = pack_half2(b.z, b.w);
        ((uint4*)d)[j] = o;
    } else {
        int e = bx - NCVT_BLK;
        int h = threadIdx.x >> 5;
        int lane = threadIdx.x & 31;
        float r0 = rpb[e * 3 + 0], r1 = rpb[e * 3 + 1], r2 = rpb[e * 3 + 2];
        float sum = 0.f;
        for (int o = lane; o < 512; o += 32) {
            float hid = fmaf(r0, w1[o * 3 + 0],
                        fmaf(r1, w1[o * 3 + 1],
                        fmaf(r2, w1[o * 3 + 2], b1[o])));
            hid = fmaxf(hid, 0.f);
            sum = fmaf(hid, w2[h * 512 + o], sum);
        }
        #pragma unroll
        for (int off = 16; off; off >>= 1)
            sum += __shfl_xor_sync(0xffffffffu, sum, off);
        if (lane == 0) g_table[e * NH + h] = sum;
    }
}

// ---------------- prep1: maskF + biasF (fused) -----------------------------
__global__ void prep1(const float* __restrict__ mask,
                      const int* __restrict__ rpb_idx) {
    int bx = blockIdx.x;
    if (bx < 4096) {
        int w = bx >> 8;
        int i = (bx & 255) * 256 + threadIdx.x;
        int g = i & 7, t = (i >> 3) & 3, jn = (i >> 5) & 7, c = (i >> 8) & 7;
        int wid = (i >> 11) & 7, qt = i >> 14;
        int q0 = qt * 128 + wid * 16 + g;
        int k0 = c * 64 + jn * 8 + 2 * t;
        const float* mw = mask + (size_t)w * NN;
        float4 v;
        v.x = mw[q0 * NTOK + k0];
        v.y = mw[q0 * NTOK + k0 + 1];
        v.z = mw[(q0 + 8) * NTOK + k0];
        v.w = mw[(q0 + 8) * NTOK + k0 + 1];
        bool nz = (v.x != 0.f) | (v.y != 0.f) | (v.z != 0.f) | (v.w != 0.f);
        v.x *= LOG2E; v.y *= LOG2E; v.z *= LOG2E; v.w *= LOG2E;
        g_maskF[(size_t)w * NFRAG + i] = v;
        if (__syncthreads_or(nz) && threadIdx.x == 0)
            atomicOr(&g_maskflag, 1);
    } else {
        int i = (bx - 4096) * 256 + threadIdx.x;
        int g = i & 7, t = (i >> 3) & 3, jn = (i >> 5) & 7, c = (i >> 8) & 7;
        int wid = (i >> 11) & 7, qt = i >> 14;
        int q0 = qt * 128 + wid * 16 + g;
        int k0 = c * 64 + jn * 8 + 2 * t;
        int i00 = rpb_idx[q0 * NTOK + k0];
        int i10 = rpb_idx[q0 * NTOK + k0 + 1];
        int i01 = rpb_idx[(q0 + 8) * NTOK + k0];
        int i11 = rpb_idx[(q0 + 8) * NTOK + k0 + 1];
        const float S = 16.f * LOG2E;
        #pragma unroll
        for (int h = 0; h < NH; h++) {
            float4 v;
            v.x = S / (1.f + __expf(-g_table[i00 * NH + h]));
            v.y = S / (1.f + __expf(-g_table[i10 * NH + h]));
            v.z = S / (1.f + __expf(-g_table[i01 * NH + h]));
            v.w = S / (1.f + __expf(-g_table[i11 * NH + h]));
            g_biasF[h * NFRAG + i] = v;
        }
    }
}

// =====================  fp16 mma GEMM (NT), 64x64 warp tiles, BK=64  =====
#define GSMEM (4 * 16384)
__global__ __launch_bounds__(128, 2) void gemm_h(const __half* __restrict__ A,
                                                 const __half* __restrict__ B,
                                                 const float* __restrict__ bias,
                                                 void* __restrict__ Cv,
                                                 int M, int N, int K, int fp32out) {
    extern __shared__ __align__(16) char gsm[];
    const int tid = threadIdx.x, lane = tid & 31, wid = tid >> 5;
    const int g = lane >> 2, t = lane & 3;
    const int wm = wid & 1, wn = wid >> 1;
    const int row0 = blockIdx.y * 128, col0 = blockIdx.x * 128;

    const int lr0 = tid >> 3, lc = tid & 7;
    const __half* Ap = A + (size_t)(row0 + lr0) * K + lc * 8;
    const __half* Bp = B + (size_t)(col0 + lr0) * K + lc * 8;
    const size_t rstep = (size_t)16 * K;
    uint32_t aS[2] = { cvta_s(gsm), cvta_s(gsm) + 16384 };
    uint32_t bS[2] = { cvta_s(gsm) + 32768, cvta_s(gsm) + 49152 };
    uint32_t soffs[8];
    #pragma unroll
    for (int i = 0; i < 8; i++) soffs[i] = swz128(lr0 + i * 16, lc);

    float acc[4][8][4];
    #pragma unroll
    for (int mt = 0; mt < 4; mt++)
        #pragma unroll
        for (int jn = 0; jn < 8; jn++)
            #pragma unroll
            for (int r = 0; r < 4; r++) acc[mt][jn][r] = 0.f;

    #pragma unroll
    for (int i = 0; i < 8; i++) {
        cp16(aS[0] + soffs[i], Ap + i * rstep);
        cp16(bS[0] + soffs[i], Bp + i * rstep);
    }
    cp_commit();

    const int nk = K >> 6;
    for (int kt = 0; kt < nk; kt++) {
        const int s = kt & 1;
        cp_wait0();
        __syncthreads();
        if (kt + 1 < nk) {
            int ko = (kt + 1) * 64;
            #pragma unroll
            for (int i = 0; i < 8; i++) {
                cp16(aS[s ^ 1] + soffs[i], Ap + i * rstep + ko);
                cp16(bS[s ^ 1] + soffs[i], Bp + i * rstep + ko);
            }
            cp_commit();
        }
        #pragma unroll
        for (int ks = 0; ks < 4; ks++) {
            uint32_t af[4][4];
            #pragma unroll
            for (int mt = 0; mt < 4; mt++) {
                int row = wm * 64 + mt * 16 + (lane & 15);
                int kch = ks * 2 + (lane >> 4);
                ldsm4(af[mt], aS[s] + swz128(row, kch));
            }
            uint32_t bf[4][4];
            #pragma unroll
            for (int i = 0; i < 4; i++) {
                int rn = wn * 64 + i * 16 + ((lane >> 4) << 3) + (lane & 7);
                int kch = ks * 2 + ((lane & 8) >> 3);
                ldsm4(bf[i], bS[s] + swz128(rn, kch));
            }
            #pragma unroll
            for (int mt = 0; mt < 4; mt++)
                #pragma unroll
                for (int jn = 0; jn < 8; jn++)
                    mma_f16(acc[mt][jn], af[mt],
                            bf[jn >> 1][(jn & 1) * 2], bf[jn >> 1][(jn & 1) * 2 + 1]);
        }
        __syncthreads();
    }

    if (fp32out) {
        float* C = (float*)Cv;
        #pragma unroll
        for (int mt = 0; mt < 4; mt++) {
            int r = row0 + wm * 64 + mt * 16;
            #pragma unroll
            for (int jn = 0; jn < 8; jn++) {
                int cc = col0 + wn * 64 + jn * 8 + 2 * t;
                float bx = bias[cc], by = bias[cc + 1];
                float2 v0 = { acc[mt][jn][0] + bx, acc[mt][jn][1] + by };
                float2 v1 = { acc[mt][jn][2] + bx, acc[mt][jn][3] + by };
                *(float2*)(C + (size_t)(r + g) * N + cc) = v0;
                *(float2*)(C + (size_t)(r + g + 8) * N + cc) = v1;
            }
        }
    } else {
        __half* C = (__half*)Cv;
        #pragma unroll
        for (int mt = 0; mt < 4; mt++) {
            int r = row0 + wm * 64 + mt * 16;
            #pragma unroll
            for (int jn = 0; jn < 8; jn++) {
                int cc = col0 + wn * 64 + jn * 8 + 2 * t;
                *(uint32_t*)(C + (size_t)(r + g) * N + cc)
                    = pack_half2(acc[mt][jn][0], acc[mt][jn][1]);
                *(uint32_t*)(C + (size_t)(r + g + 8) * N + cc)
                    = pack_half2(acc[mt][jn][2], acc[mt][jn][3]);
            }
        }
    }
}

// =====================  fused fp16 mma attention: 4 warps x 32 q-rows  ======
__global__ __launch_bounds__(128, 2) void attn_h() {
    __shared__ __align__(16) __half Ks[2][64 * 32];
    __shared__ __align__(16) __half Vs[2][64 * 32];
    const int b = blockIdx.x, h = blockIdx.y, qt = blockIdx.z;
    const int tid = threadIdx.x, lane = tid & 31, w = tid >> 5;   // w in [0,4)
    const int g = lane >> 2, t = lane & 3;
    const int q0 = qt * 128 + w * 32;          // warp covers 32 q rows (2 m16)
    const __half* base = g_qkv + (size_t)b * NTOK * QKV_LD;
    const float SCALE2 = 0.17677669529663687f * LOG2E;
    const bool use_mask = (g_maskflag != 0);

    // staging: thread owns slots {tid, tid+128}: key = id>>2, ch = id&3
    const __half* kp0 = base + (size_t)(tid >> 2) * QKV_LD + DIM + h * HD + (tid & 3) * 8;
    const __half* kp1 = base + (size_t)((tid + 128) >> 2) * QKV_LD + DIM + h * HD
                             + ((tid + 128) & 3) * 8;
    const uint32_t sf0 = swz(tid >> 2, tid & 3);
    const uint32_t sf1 = swz((tid + 128) >> 2, (tid + 128) & 3);
    const uint32_t kS[2] = { cvta_s(Ks[0]), cvta_s(Ks[1]) };
    const uint32_t vS[2] = { cvta_s(Vs[0]), cvta_s(Vs[1]) };

    cp16(kS[0] + sf0, kp0);
    cp16(kS[0] + sf1, kp1);
    cp16(vS[0] + sf0, kp0 + DIM);
    cp16(vS[0] + sf1, kp1 + DIM);
    cp_commit();

    // Q fragments for 2 m-tiles
    uint32_t qa[2][2][4];   // [mt][ks][4]
    #pragma unroll
    for (int mt = 0; mt < 2; mt++) {
        const __half* qp0 = base + (size_t)(q0 + mt * 16 + g) * QKV_LD + h * HD;
        const __half* qp8 = qp0 + (size_t)8 * QKV_LD;
        #pragma unroll
        for (int ks = 0; ks < 2; ks++) {
            qa[mt][ks][0] = *(const uint32_t*)(qp0 + ks * 16 + 2 * t);
            qa[mt][ks][1] = *(const uint32_t*)(qp8 + ks * 16 + 2 * t);
            qa[mt][ks][2] = *(const uint32_t*)(qp0 + ks * 16 + 8 + 2 * t);
            qa[mt][ks][3] = *(const uint32_t*)(qp8 + ks * 16 + 8 + 2 * t);
        }
    }

    float o[2][4][4];
    #pragma unroll
    for (int mt = 0; mt < 2; mt++)
        #pragma unroll
        for (int nd = 0; nd < 4; nd++)
            #pragma unroll
            for (int r = 0; r < 4; r++) o[mt][nd][r] = 0.f;
    float m[2][2] = { { -1e30f, -1e30f }, { -1e30f, -1e30f } };
    float l[2][2] = { { 0.f, 0.f }, { 0.f, 0.f } };

    // fragment bias/mask ptrs per m-tile (wid_eff = w*2 + mt)
    const float4* bp4[2];
    const float4* mp4[2];
    #pragma unroll
    for (int mt = 0; mt < 2; mt++) {
        int we = w * 2 + mt;
        bp4[mt] = g_biasF + (((size_t)h * 4 + qt) * 8 + we) * 2048 + t * 8 + g;
        mp4[mt] = g_maskF + (((size_t)(b & (NWIN - 1)) * 4 + qt) * 8 + we) * 2048
                          + t * 8 + g;
    }

    for (int c = 0; c < 8; c++) {
        const int s = c & 1;
        cp_wait0();
        __syncthreads();
        if (c < 7) {
            const size_t nb = (size_t)(c + 1) * 64 * QKV_LD;
            cp16(kS[s ^ 1] + sf0, kp0 + nb);
            cp16(kS[s ^ 1] + sf1, kp1 + nb);
            cp16(vS[s ^ 1] + sf0, kp0 + nb + DIM);
            cp16(vS[s ^ 1] + sf1, kp1 + nb + DIM);
            cp_commit();
        }

        // ---- S = Q K^T  (both m-tiles share kb fragments) ----
        float sc[2][8][4];
        #pragma unroll
        for (int mt = 0; mt < 2; mt++)
            #pragma unroll
            for (int jn = 0; jn < 8; jn++)
                sc[mt][jn][0] = sc[mt][jn][1] = sc[mt][jn][2] = sc[mt][jn][3] = 0.f;
        #pragma unroll
        for (int ks = 0; ks < 2; ks++) {
            uint32_t kb[4][4];
            #pragma unroll
            for (int i = 0; i < 4; i++) {
                int rn = i * 16 + ((lane >> 4) << 3) + (lane & 7);
                int kch = ks * 2 + ((lane & 8) >> 3);
                ldsm4(kb[i], kS[s] + swz(rn, kch));
            }
            #pragma unroll
            for (int jn = 0; jn < 8; jn++) {
                uint32_t b0 = kb[jn >> 1][(jn & 1) * 2];
                uint32_t b1 = kb[jn >> 1][(jn & 1) * 2 + 1];
                mma_f16(sc[0][jn], qa[0][ks], b0, b1);
                mma_f16(sc[1][jn], qa[1][ks], b0, b1);
            }
        }
        // scale + fragment bias (+ mask)
        #pragma unroll
        for (int mt = 0; mt < 2; mt++) {
            const float4* bc = bp4[mt] + c * 256;
            const float4* mc = mp4[mt] + c * 256;
            #pragma unroll
            for (int jn = 0; jn < 8; jn++) {
                float4 bv = bc[jn * 32];
                if (use_mask) {
                    float4 mv = mc[jn * 32];
                    bv.x += mv.x; bv.y += mv.y; bv.z += mv.z; bv.w += mv.w;
                }
                sc[mt][jn][0] = fmaf(sc[mt][jn][0], SCALE2, bv.x);
                sc[mt][jn][1] = fmaf(sc[mt][jn][1], SCALE2, bv.y);
                sc[mt][jn][2] = fmaf(sc[mt][jn][2], SCALE2, bv.z);
                sc[mt][jn][3] = fmaf(sc[mt][jn][3], SCALE2, bv.w);
            }
        }

        // ---- online softmax (base 2) per m-tile ----
        uint32_t pa[2][4][4];
        #pragma unroll
        for (int mt = 0; mt < 2; mt++) {
            float mx0 = sc[mt][0][0], mx1 = sc[mt][0][2];
            #pragma unroll
            for (int jn = 0; jn < 8; jn++) {
                mx0 = fmaxf(mx0, fmaxf(sc[mt][jn][0], sc[mt][jn][1]));
                mx1 = fmaxf(mx1, fmaxf(sc[mt][jn][2], sc[mt][jn][3]));
            }
            mx0 = fmaxf(mx0, __shfl_xor_sync(0xffffffffu, mx0, 1));
            mx0 = fmaxf(mx0, __shfl_xor_sync(0xffffffffu, mx0, 2));
            mx1 = fmaxf(mx1, __shfl_xor_sync(0xffffffffu, mx1, 1));
            mx1 = fmaxf(mx1, __shfl_xor_sync(0xffffffffu, mx1, 2));
            float nm0 = fmaxf(m[mt][0], mx0), nm1 = fmaxf(m[mt][1], mx1);
            float c0 = exp2f(m[mt][0] - nm0), c1 = exp2f(m[mt][1] - nm1);
            m[mt][0] = nm0; m[mt][1] = nm1;
            l[mt][0] *= c0; l[mt][1] *= c1;
            #pragma unroll
            for (int nd = 0; nd < 4; nd++) {
                o[mt][nd][0] *= c0; o[mt][nd][1] *= c0;
                o[mt][nd][2] *= c1; o[mt][nd][3] *= c1;
            }
            #pragma unroll
            for (int kk = 0; kk < 4; kk++) {
                float pA0 = exp2f(sc[mt][2*kk][0] - nm0);
                float pA1 = exp2f(sc[mt][2*kk][1] - nm0);
                float pA2 = exp2f(sc[mt][2*kk][2] - nm1);
                float pA3 = exp2f(sc[mt][2*kk][3] - nm1);
                float pB0 = exp2f(sc[mt][2*kk+1][0] - nm0);
                float pB1 = exp2f(sc[mt][2*kk+1][1] - nm0);
                float pB2 = exp2f(sc[mt][2*kk+1][2] - nm1);
                float pB3 = exp2f(sc[mt][2*kk+1][3] - nm1);
                l[mt][0] += (pA0 + pA1) + (pB0 + pB1);
                l[mt][1] += (pA2 + pA3) + (pB2 + pB3);
                pa[mt][kk][0] = pack_half2(pA0, pA1);
                pa[mt][kk][1] = pack_half2(pA2, pA3);
                pa[mt][kk][2] = pack_half2(pB0, pB1);
                pa[mt][kk][3] = pack_half2(pB2, pB3);
            }
        }

        // ---- O += P V  (vb fragments shared across m-tiles) ----
        #pragma unroll
        for (int ndp = 0; ndp < 2; ndp++)
            #pragma unroll
            for (int kk = 0; kk < 4; kk++) {
                uint32_t vb[4];
                int key = kk * 16 + (lane & 15);
                int kch = ndp * 2 + (lane >> 4);
                ldsm4t(vb, vS[s] + swz(key, kch));
                #pragma unroll
                for (int mt = 0; mt < 2; mt++) {
                    mma_f16(o[mt][ndp * 2],     pa[mt][kk], vb[0], vb[1]);
                    mma_f16(o[mt][ndp * 2 + 1], pa[mt][kk], vb[2], vb[3]);
                }
            }
        __syncthreads();
    }

    // finalize
    #pragma unroll
    for (int mt = 0; mt < 2; mt++) {
        float l0 = l[mt][0], l1 = l[mt][1];
        l0 += __shfl_xor_sync(0xffffffffu, l0, 1);
        l0 += __shfl_xor_sync(0xffffffffu, l0, 2);
        l1 += __shfl_xor_sync(0xffffffffu, l1, 1);
        l1 += __shfl_xor_sync(0xffffffffu, l1, 2);
        float i0 = 1.f / l0, i1 = 1.f / l1;
        __half* op0 = g_att + ((size_t)b * NTOK + q0 + mt * 16 + g) * DIM + h * HD;
        __half* op8 = op0 + (size_t)8 * DIM;
        #pragma unroll
        for (int nd = 0; nd < 4; nd++) {
            *(uint32_t*)(op0 + nd * 8 + 2 * t)
                = pack_half2(o[mt][nd][0] * i0, o[mt][nd][1] * i0);
            *(uint32_t*)(op8 + nd * 8 + 2 * t)
                = pack_half2(o[mt][nd][2] * i1, o[mt][nd][3] * i1);
        }
    }
}

// ---------------- launch ----------------
extern "C" void kernel_launch(void* const* d_in, const int* in_sizes, int n_in,
                              void* d_out, int out_size) {
    const float* x      = (const float*)d_in[0];
    const float* mask   = (const float*)d_in[1];
    const float* qkv_w  = (const float*)d_in[2];
    const float* proj_w = (const float*)d_in[3];
    const float* proj_b = (const float*)d_in[4];
    const float* cpb_w1 = (const float*)d_in[5];
    const float* cpb_b1 = (const float*)d_in[6];
    const float* cpb_w2 = (const float*)d_in[7];
    const float* rpb    = (const float*)d_in[8];
    const int*   rpb_idx = (const int*)d_in[9];
    float* out = (float*)d_out;

    static __half *p_xh = nullptr, *p_qkvw = nullptr, *p_projw = nullptr,
                  *p_qkv = nullptr, *p_att = nullptr;
    if (!p_xh) {
        cudaGetSymbolAddress((void**)&p_xh, g_xh);
        cudaGetSymbolAddress((void**)&p_qkvw, g_qkvw);
        cudaGetSymbolAddress((void**)&p_projw, g_projw);
        cudaGetSymbolAddress((void**)&p_qkv, g_qkv);
        cudaGetSymbolAddress((void**)&p_att, g_att);
        cudaFuncSetAttribute(gemm_h,
                             cudaFuncAttributeMaxDynamicSharedMemorySize, GSMEM);
    }

    // 0) conversions + CPB table (fused)
    prep0<<<NCVT_BLK + TABLE_E, 256>>>(x, qkv_w, proj_w,
                                       rpb, cpb_w1, cpb_b1, cpb_w2);
    // 1) maskF + biasF (fused)
    prep1<<<4096 + NFRAG / 256, 256>>>(mask, rpb_idx);
    // 2) QKV projection
    {
        dim3 grid(QKV_LD / 128, (BATCH * NTOK) / 128);
        gemm_h<<<grid, 128, GSMEM>>>(p_xh, p_qkvw, nullptr, p_qkv,
                                     BATCH * NTOK, QKV_LD, DIM, 0);
    }
    // 3) fused attention  (stream index 3 -> ncu capture)
    attn_h<<<dim3(BATCH, NH, NTOK / 128), 128>>>();
    // 4) output projection
    {
        dim3 grid(DIM / 128, (BATCH * NTOK) / 128);
        gemm_h<<<grid, 128, GSMEM>>>(p_att, p_projw, proj_b, out,
                                     BATCH * NTOK, DIM, DIM, 1);
    }
}

// round 10
// speedup vs baseline: 5.3627x; 1.0361x over previous
#include <cuda_runtime.h>
#include <cuda_fp16.h>
#include <math.h>
#include <stdint.h>

#define BATCH   128
#define NWIN    16
#define NTOK    512
#define DIM     256
#define NH      8
#define HD      32
#define TABLE_E 3375
#define QKV_LD  768
#define NN      (NTOK*NTOK)
#define LOG2E   1.4426950408889634f
#define NFRAG   65536
#define ONES_H2 0x3C003C00u

// ---------------- scratch (device globals) ----------------
__device__ float  g_table[TABLE_E * NH];
__device__ float4 g_biasF[NH * NFRAG];
__device__ float4 g_maskF[NWIN * NFRAG];
__device__ int    g_maskflag;
__device__ __half g_xh[(size_t)BATCH * NTOK * DIM];
__device__ __half g_qkvw[QKV_LD * DIM];
__device__ __half g_projw[DIM * DIM];
__device__ __half g_qkv[(size_t)BATCH * NTOK * QKV_LD];
__device__ __half g_att[(size_t)BATCH * NTOK * DIM];

// =====================  helpers  =====================
__device__ __forceinline__ uint32_t pack_half2(float lo, float hi) {
    __half2 h = __floats2half2_rn(lo, hi);
    return *(uint32_t*)&h;
}
// 2^x for two packed halves in one MUFU op
__device__ __forceinline__ uint32_t ex2_h2(float lo, float hi) {
    uint32_t d = pack_half2(lo, hi), r;
    asm("ex2.approx.f16x2 %0, %1;" : "=r"(r) : "r"(d));
    return r;
}
__device__ __forceinline__ void mma_f16(float* d, const uint32_t* a,
                                        uint32_t b0, uint32_t b1) {
    asm volatile(
        "mma.sync.aligned.m16n8k16.row.col.f32.f16.f16.f32 "
        "{%0,%1,%2,%3}, {%4,%5,%6,%7}, {%8,%9}, {%0,%1,%2,%3};"
        : "+f"(d[0]), "+f"(d[1]), "+f"(d[2]), "+f"(d[3])
        : "r"(a[0]), "r"(a[1]), "r"(a[2]), "r"(a[3]), "r"(b0), "r"(b1));
}
__device__ __forceinline__ void ldsm4(uint32_t* r, uint32_t addr) {
    asm volatile("ldmatrix.sync.aligned.m8n8.x4.shared.b16 {%0,%1,%2,%3}, [%4];"
                 : "=r"(r[0]), "=r"(r[1]), "=r"(r[2]), "=r"(r[3]) : "r"(addr));
}
__device__ __forceinline__ void ldsm4t(uint32_t* r, uint32_t addr) {
    asm volatile("ldmatrix.sync.aligned.m8n8.x4.trans.shared.b16 {%0,%1,%2,%3}, [%4];"
                 : "=r"(r[0]), "=r"(r[1]), "=r"(r[2]), "=r"(r[3]) : "r"(addr));
}
__device__ __forceinline__ uint32_t cvta_s(const void* p) {
    return (uint32_t)__cvta_generic_to_shared(p);
}
__device__ __forceinline__ uint32_t swz(int r, int kchunk) {
    return (uint32_t)(r * 64 + ((kchunk ^ ((r >> 1) & 3)) << 4));
}
__device__ __forceinline__ uint32_t swz128(int r, int kchunk) {
    return (uint32_t)(r * 128 + ((kchunk ^ (r & 7)) << 4));
}
__device__ __forceinline__ void cp16(uint32_t smem, const void* g) {
    asm volatile("cp.async.cg.shared.global [%0], [%1], 16;"
                 :: "r"(smem), "l"(g) : "memory");
}
__device__ __forceinline__ void cp_commit() {
    asm volatile("cp.async.commit_group;" ::: "memory");
}
__device__ __forceinline__ void cp_wait0() {
    asm volatile("cp.async.wait_group 0;" ::: "memory");
}

// ---------------- prep0: fp32->fp16 conversions + CPB MLP ----------------
#define N8X ((BATCH * NTOK * DIM) / 8)
#define N8W ((QKV_LD * DIM) / 8)
#define N8P ((DIM * DIM) / 8)
#define N8T (N8X + N8W + N8P)
#define NCVT_BLK ((N8T + 255) / 256)
__global__ void prep0(const float* __restrict__ x,
                      const float* __restrict__ qw,
                      const float* __restrict__ pw,
                      const float* __restrict__ rpb,
                      const float* __restrict__ w1,
                      const float* __restrict__ b1,
                      const float* __restrict__ w2) {
    int bx = blockIdx.x;
    if (bx < NCVT_BLK) {
        int i = bx * 256 + threadIdx.x;
        if (i == 0) g_maskflag = 0;
        const float* s;
        __half* d;
        int j;
        if (i < N8X)                  { s = x;  d = g_xh;    j = i; }
        else if (i < N8X + N8W)       { s = qw; d = g_qkvw;  j = i - N8X; }
        else if (i < N8T)             { s = pw; d = g_projw; j = i - N8X - N8W; }
        else return;
        const float4* sp = (const float4*)s + (size_t)j * 2;
        float4 a = sp[0], b = sp[1];
        uint4 o;
        o.x = pack_half2(a.x, a.y); o.y = pack_half2(a.z, a.w);
        o.z = pack_half2(b.x, b.y); o.w = pack_half2(b.z, b.w);
        ((uint4*)d)[j] = o;
    } else {
        int e = bx - NCVT_BLK;
        int h = threadIdx.x >> 5;
        int lane = threadIdx.x & 31;
        float r0 = rpb[e * 3 + 0], r1 = rpb[e * 3 + 1], r2 = rpb[e * 3 + 2];
        float sum = 0.f;
        for (int o = lane; o < 512; o += 32) {
            float hid = fmaf(r0, w1[o * 3 + 0],
                        fmaf(r1, w1[o * 3 + 1],
                        fmaf(r2, w1[o * 3 + 2], b1[o])));
            hid = fmaxf(hid, 0.f);
            sum = fmaf(hid, w2[h * 512 + o], sum);
        }
        #pragma unroll
        for (int off = 16; off; off >>= 1)
            sum += __shfl_xor_sync(0xffffffffu, sum, off);
        if (lane == 0) g_table[e * NH + h] = sum;
    }
}

// ---------------- prep1: maskF + biasF (fused) -----------------------------
__global__ void prep1(const float* __restrict__ mask,
                      const int* __restrict__ rpb_idx) {
    int bx = blockIdx.x;
    if (bx < 4096) {
        int w = bx >> 8;
        int i = (bx & 255) * 256 + threadIdx.x;
        int g = i & 7, t = (i >> 3) & 3, jn = (i >> 5) & 7, c = (i >> 8) & 7;
        int wid = (i >> 11) & 7, qt = i >> 14;
        int q0 = qt * 128 + wid * 16 + g;
        int k0 = c * 64 + jn * 8 + 2 * t;
        const float* mw = mask + (size_t)w * NN;
        float4 v;
        v.x = mw[q0 * NTOK + k0];
        v.y = mw[q0 * NTOK + k0 + 1];
        v.z = mw[(q0 + 8) * NTOK + k0];
        v.w = mw[(q0 + 8) * NTOK + k0 + 1];
        bool nz = (v.x != 0.f) | (v.y != 0.f) | (v.z != 0.f) | (v.w != 0.f);
        v.x *= LOG2E; v.y *= LOG2E; v.z *= LOG2E; v.w *= LOG2E;
        g_maskF[(size_t)w * NFRAG + i] = v;
        if (__syncthreads_or(nz) && threadIdx.x == 0)
            atomicOr(&g_maskflag, 1);
    } else {
        int i = (bx - 4096) * 256 + threadIdx.x;
        int g = i & 7, t = (i >> 3) & 3, jn = (i >> 5) & 7, c = (i >> 8) & 7;
        int wid = (i >> 11) & 7, qt = i >> 14;
        int q0 = qt * 128 + wid * 16 + g;
        int k0 = c * 64 + jn * 8 + 2 * t;
        int i00 = rpb_idx[q0 * NTOK + k0];
        int i10 = rpb_idx[q0 * NTOK + k0 + 1];
        int i01 = rpb_idx[(q0 + 8) * NTOK + k0];
        int i11 = rpb_idx[(q0 + 8) * NTOK + k0 + 1];
        const float S = 16.f * LOG2E;
        #pragma unroll
        for (int h = 0; h < NH; h++) {
            float4 v;
            v.x = S / (1.f + __expf(-g_table[i00 * NH + h]));
            v.y = S / (1.f + __expf(-g_table[i10 * NH + h]));
            v.z = S / (1.f + __expf(-g_table[i01 * NH + h]));
            v.w = S / (1.f + __expf(-g_table[i11 * NH + h]));
            g_biasF[h * NFRAG + i] = v;
        }
    }
}

// =====================  fp16 mma GEMM (NT), 64x64 warp tiles, BK=64  =====
#define GSMEM (4 * 16384)
__global__ __launch_bounds__(128, 2) void gemm_h(const __half* __restrict__ A,
                                                 const __half* __restrict__ B,
                                                 const float* __restrict__ bias,
                                                 void* __restrict__ Cv,
                                                 int M, int N, int K, int fp32out) {
    extern __shared__ __align__(16) char gsm[];
    const int tid = threadIdx.x, lane = tid & 31, wid = tid >> 5;
    const int g = lane >> 2, t = lane & 3;
    const int wm = wid & 1, wn = wid >> 1;
    const int row0 = blockIdx.y * 128, col0 = blockIdx.x * 128;

    const int lr0 = tid >> 3, lc = tid & 7;
    const __half* Ap = A + (size_t)(row0 + lr0) * K + lc * 8;
    const __half* Bp = B + (size_t)(col0 + lr0) * K + lc * 8;
    const size_t rstep = (size_t)16 * K;
    uint32_t aS[2] = { cvta_s(gsm), cvta_s(gsm) + 16384 };
    uint32_t bS[2] = { cvta_s(gsm) + 32768, cvta_s(gsm) + 49152 };
    uint32_t soffs[8];
    #pragma unroll
    for (int i = 0; i < 8; i++) soffs[i] = swz128(lr0 + i * 16, lc);

    float acc[4][8][4];
    #pragma unroll
    for (int mt = 0; mt < 4; mt++)
        #pragma unroll
        for (int jn = 0; jn < 8; jn++)
            #pragma unroll
            for (int r = 0; r < 4; r++) acc[mt][jn][r] = 0.f;

    #pragma unroll
    for (int i = 0; i < 8; i++) {
        cp16(aS[0] + soffs[i], Ap + i * rstep);
        cp16(bS[0] + soffs[i], Bp + i * rstep);
    }
    cp_commit();

    const int nk = K >> 6;
    for (int kt = 0; kt < nk; kt++) {
        const int s = kt & 1;
        cp_wait0();
        __syncthreads();
        if (kt + 1 < nk) {
            int ko = (kt + 1) * 64;
            #pragma unroll
            for (int i = 0; i < 8; i++) {
                cp16(aS[s ^ 1] + soffs[i], Ap + i * rstep + ko);
                cp16(bS[s ^ 1] + soffs[i], Bp + i * rstep + ko);
            }
            cp_commit();
        }
        #pragma unroll
        for (int ks = 0; ks < 4; ks++) {
            uint32_t af[4][4];
            #pragma unroll
            for (int mt = 0; mt < 4; mt++) {
                int row = wm * 64 + mt * 16 + (lane & 15);
                int kch = ks * 2 + (lane >> 4);
                ldsm4(af[mt], aS[s] + swz128(row, kch));
            }
            uint32_t bf[4][4];
            #pragma unroll
            for (int i = 0; i < 4; i++) {
                int rn = wn * 64 + i * 16 + ((lane >> 4) << 3) + (lane & 7);
                int kch = ks * 2 + ((lane & 8) >> 3);
                ldsm4(bf[i], bS[s] + swz128(rn, kch));
            }
            #pragma unroll
            for (int mt = 0; mt < 4; mt++)
                #pragma unroll
                for (int jn = 0; jn < 8; jn++)
                    mma_f16(acc[mt][jn], af[mt],
                            bf[jn >> 1][(jn & 1) * 2], bf[jn >> 1][(jn & 1) * 2 + 1]);
        }
        __syncthreads();
    }

    if (fp32out) {
        float* C = (float*)Cv;
        #pragma unroll
        for (int mt = 0; mt < 4; mt++) {
            int r = row0 + wm * 64 + mt * 16;
            #pragma unroll
            for (int jn = 0; jn < 8; jn++) {
                int cc = col0 + wn * 64 + jn * 8 + 2 * t;
                float bx = bias[cc], by = bias[cc + 1];
                float2 v0 = { acc[mt][jn][0] + bx, acc[mt][jn][1] + by };
                float2 v1 = { acc[mt][jn][2] + bx, acc[mt][jn][3] + by };
                *(float2*)(C + (size_t)(r + g) * N + cc) = v0;
                *(float2*)(C + (size_t)(r + g + 8) * N + cc) = v1;
            }
        }
    } else {
        __half* C = (__half*)Cv;
        #pragma unroll
        for (int mt = 0; mt < 4; mt++) {
            int r = row0 + wm * 64 + mt * 16;
            #pragma unroll
            for (int jn = 0; jn < 8; jn++) {
                int cc = col0 + wn * 64 + jn * 8 + 2 * t;
                *(uint32_t*)(C + (size_t)(r + g) * N + cc)
                    = pack_half2(acc[mt][jn][0], acc[mt][jn][1]);
                *(uint32_t*)(C + (size_t)(r + g + 8) * N + cc)
                    = pack_half2(acc[mt][jn][2], acc[mt][jn][3]);
            }
        }
    }
}

// =====================  fused fp16 mma attention: 4 warps x 32 q-rows  ======
// f16x2 EX2 softmax; l accumulated via mma with ones-fragment
__global__ __launch_bounds__(128, 2) void attn_h() {
    __shared__ __align__(16) __half Ks[2][64 * 32];
    __shared__ __align__(16) __half Vs[2][64 * 32];
    const int b = blockIdx.x, h = blockIdx.y, qt = blockIdx.z;
    const int tid = threadIdx.x, lane = tid & 31, w = tid >> 5;
    const int g = lane >> 2, t = lane & 3;
    const int q0 = qt * 128 + w * 32;
    const __half* base = g_qkv + (size_t)b * NTOK * QKV_LD;
    const float SCALE2 = 0.17677669529663687f * LOG2E;
    const bool use_mask = (g_maskflag != 0);

    const __half* kp0 = base + (size_t)(tid >> 2) * QKV_LD + DIM + h * HD + (tid & 3) * 8;
    const __half* kp1 = base + (size_t)((tid + 128) >> 2) * QKV_LD + DIM + h * HD
                             + ((tid + 128) & 3) * 8;
    const uint32_t sf0 = swz(tid >> 2, tid & 3);
    const uint32_t sf1 = swz((tid + 128) >> 2, (tid + 128) & 3);
    const uint32_t kS[2] = { cvta_s(Ks[0]), cvta_s(Ks[1]) };
    const uint32_t vS[2] = { cvta_s(Vs[0]), cvta_s(Vs[1]) };

    cp16(kS[0] + sf0, kp0);
    cp16(kS[0] + sf1, kp1);
    cp16(vS[0] + sf0, kp0 + DIM);
    cp16(vS[0] + sf1, kp1 + DIM);
    cp_commit();

    uint32_t qa[2][2][4];
    #pragma unroll
    for (int mt = 0; mt < 2; mt++) {
        const __half* qp0 = base + (size_t)(q0 + mt * 16 + g) * QKV_LD + h * HD;
        const __half* qp8 = qp0 + (size_t)8 * QKV_LD;
        #pragma unroll
        for (int ks = 0; ks < 2; ks++) {
            qa[mt][ks][0] = *(const uint32_t*)(qp0 + ks * 16 + 2 * t);
            qa[mt][ks][1] = *(const uint32_t*)(qp8 + ks * 16 + 2 * t);
            qa[mt][ks][2] = *(const uint32_t*)(qp0 + ks * 16 + 8 + 2 * t);
            qa[mt][ks][3] = *(const uint32_t*)(qp8 + ks * 16 + 8 + 2 * t);
        }
    }

    float o[2][4][4];
    float lacc[2][4];
    #pragma unroll
    for (int mt = 0; mt < 2; mt++) {
        #pragma unroll
        for (int nd = 0; nd < 4; nd++)
            #pragma unroll
            for (int r = 0; r < 4; r++) o[mt][nd][r] = 0.f;
        #pragma unroll
        for (int r = 0; r < 4; r++) lacc[mt][r] = 0.f;
    }
    float m[2][2] = { { -1e30f, -1e30f }, { -1e30f, -1e30f } };

    const float4* bp4[2];
    const float4* mp4[2];
    #pragma unroll
    for (int mt = 0; mt < 2; mt++) {
        int we = w * 2 + mt;
        bp4[mt] = g_biasF + (((size_t)h * 4 + qt) * 8 + we) * 2048 + t * 8 + g;
        mp4[mt] = g_maskF + (((size_t)(b & (NWIN - 1)) * 4 + qt) * 8 + we) * 2048
                          + t * 8 + g;
    }

    for (int c = 0; c < 8; c++) {
        const int s = c & 1;
        cp_wait0();
        __syncthreads();
        if (c < 7) {
            const size_t nb = (size_t)(c + 1) * 64 * QKV_LD;
            cp16(kS[s ^ 1] + sf0, kp0 + nb);
            cp16(kS[s ^ 1] + sf1, kp1 + nb);
            cp16(vS[s ^ 1] + sf0, kp0 + nb + DIM);
            cp16(vS[s ^ 1] + sf1, kp1 + nb + DIM);
            cp_commit();
        }

        // ---- S = Q K^T ----
        float sc[2][8][4];
        #pragma unroll
        for (int mt = 0; mt < 2; mt++)
            #pragma unroll
            for (int jn = 0; jn < 8; jn++)
                sc[mt][jn][0] = sc[mt][jn][1] = sc[mt][jn][2] = sc[mt][jn][3] = 0.f;
        #pragma unroll
        for (int ks = 0; ks < 2; ks++) {
            uint32_t kb[4][4];
            #pragma unroll
            for (int i = 0; i < 4; i++) {
                int rn = i * 16 + ((lane >> 4) << 3) + (lane & 7);
                int kch = ks * 2 + ((lane & 8) >> 3);
                ldsm4(kb[i], kS[s] + swz(rn, kch));
            }
            #pragma unroll
            for (int jn = 0; jn < 8; jn++) {
                uint32_t b0 = kb[jn >> 1][(jn & 1) * 2];
                uint32_t b1 = kb[jn >> 1][(jn & 1) * 2 + 1];
                mma_f16(sc[0][jn], qa[0][ks], b0, b1);
                mma_f16(sc[1][jn], qa[1][ks], b0, b1);
            }
        }
        // scale + fragment bias (+ mask)
        #pragma unroll
        for (int mt = 0; mt < 2; mt++) {
            const float4* bc = bp4[mt] + c * 256;
            const float4* mc = mp4[mt] + c * 256;
            #pragma unroll
            for (int jn = 0; jn < 8; jn++) {
                float4 bv = bc[jn * 32];
                if (use_mask) {
                    float4 mv = mc[jn * 32];
                    bv.x += mv.x; bv.y += mv.y; bv.z += mv.z; bv.w += mv.w;
                }
                sc[mt][jn][0] = fmaf(sc[mt][jn][0], SCALE2, bv.x);
                sc[mt][jn][1] = fmaf(sc[mt][jn][1], SCALE2, bv.y);
                sc[mt][jn][2] = fmaf(sc[mt][jn][2], SCALE2, bv.z);
                sc[mt][jn][3] = fmaf(sc[mt][jn][3], SCALE2, bv.w);
            }
        }

        // ---- online softmax (base 2, f16x2 EX2) per m-tile ----
        uint32_t pa[2][4][4];
        #pragma unroll
        for (int mt = 0; mt < 2; mt++) {
            float mx0 = sc[mt][0][0], mx1 = sc[mt][0][2];
            #pragma unroll
            for (int jn = 0; jn < 8; jn++) {
                mx0 = fmaxf(mx0, fmaxf(sc[mt][jn][0], sc[mt][jn][1]));
                mx1 = fmaxf(mx1, fmaxf(sc[mt][jn][2], sc[mt][jn][3]));
            }
            mx0 = fmaxf(mx0, __shfl_xor_sync(0xffffffffu, mx0, 1));
            mx0 = fmaxf(mx0, __shfl_xor_sync(0xffffffffu, mx0, 2));
            mx1 = fmaxf(mx1, __shfl_xor_sync(0xffffffffu, mx1, 1));
            mx1 = fmaxf(mx1, __shfl_xor_sync(0xffffffffu, mx1, 2));
            float nm0 = fmaxf(m[mt][0], mx0), nm1 = fmaxf(m[mt][1], mx1);
            float c0 = exp2f(m[mt][0] - nm0), c1 = exp2f(m[mt][1] - nm1);
            m[mt][0] = nm0; m[mt][1] = nm1;
            #pragma unroll
            for (int nd = 0; nd < 4; nd++) {
                o[mt][nd][0] *= c0; o[mt][nd][1] *= c0;
                o[mt][nd][2] *= c1; o[mt][nd][3] *= c1;
            }
            lacc[mt][0] *= c0; lacc[mt][1] *= c0;
            lacc[mt][2] *= c1; lacc[mt][3] *= c1;
            #pragma unroll
            for (int kk = 0; kk < 4; kk++) {
                pa[mt][kk][0] = ex2_h2(sc[mt][2*kk][0]   - nm0, sc[mt][2*kk][1]   - nm0);
                pa[mt][kk][1] = ex2_h2(sc[mt][2*kk][2]   - nm1, sc[mt][2*kk][3]   - nm1);
                pa[mt][kk][2] = ex2_h2(sc[mt][2*kk+1][0] - nm0, sc[mt][2*kk+1][1] - nm0);
                pa[mt][kk][3] = ex2_h2(sc[mt][2*kk+1][2] - nm1, sc[mt][2*kk+1][3] - nm1);
            }
            // l += row-sum(P) via mma against all-ones B fragment
            #pragma unroll
            for (int kk = 0; kk < 4; kk++)
                mma_f16(lacc[mt], pa[mt][kk], ONES_H2, ONES_H2);
        }

        // ---- O += P V ----
        #pragma unroll
        for (int ndp = 0; ndp < 2; ndp++)
            #pragma unroll
            for (int kk = 0; kk < 4; kk++) {
                uint32_t vb[4];
                int key = kk * 16 + (lane & 15);
                int kch = ndp * 2 + (lane >> 4);
                ldsm4t(vb, vS[s] + swz(key, kch));
                #pragma unroll
                for (int mt = 0; mt < 2; mt++) {
                    mma_f16(o[mt][ndp * 2],     pa[mt][kk], vb[0], vb[1]);
                    mma_f16(o[mt][ndp * 2 + 1], pa[mt][kk], vb[2], vb[3]);
                }
            }
        __syncthreads();
    }

    // finalize: l = lacc col value (all 8 B-cols identical -> no shfl needed)
    #pragma unroll
    for (int mt = 0; mt < 2; mt++) {
        float i0 = 1.f / lacc[mt][0], i1 = 1.f / lacc[mt][2];
        __half* op0 = g_att + ((size_t)b * NTOK + q0 + mt * 16 + g) * DIM + h * HD;
        __half* op8 = op0 + (size_t)8 * DIM;
        #pragma unroll
        for (int nd = 0; nd < 4; nd++) {
            *(uint32_t*)(op0 + nd * 8 + 2 * t)
                = pack_half2(o[mt][nd][0] * i0, o[mt][nd][1] * i0);
            *(uint32_t*)(op8 + nd * 8 + 2 * t)
                = pack_half2(o[mt][nd][2] * i1, o[mt][nd][3] * i1);
        }
    }
}

// ---------------- launch ----------------
extern "C" void kernel_launch(void* const* d_in, const int* in_sizes, int n_in,
                              void* d_out, int out_size) {
    const float* x      = (const float*)d_in[0];
    const float* mask   = (const float*)d_in[1];
    const float* qkv_w  = (const float*)d_in[2];
    const float* proj_w = (const float*)d_in[3];
    const float* proj_b = (const float*)d_in[4];
    const float* cpb_w1 = (const float*)d_in[5];
    const float* cpb_b1 = (const float*)d_in[6];
    const float* cpb_w2 = (const float*)d_in[7];
    const float* rpb    = (const float*)d_in[8];
    const int*   rpb_idx = (const int*)d_in[9];
    float* out = (float*)d_out;

    static __half *p_xh = nullptr, *p_qkvw = nullptr, *p_projw = nullptr,
                  *p_qkv = nullptr, *p_att = nullptr;
    if (!p_xh) {
        cudaGetSymbolAddress((void**)&p_xh, g_xh);
        cudaGetSymbolAddress((void**)&p_qkvw, g_qkvw);
        cudaGetSymbolAddress((void**)&p_projw, g_projw);
        cudaGetSymbolAddress((void**)&p_qkv, g_qkv);
        cudaGetSymbolAddress((void**)&p_att, g_att);
        cudaFuncSetAttribute(gemm_h,
                             cudaFuncAttributeMaxDynamicSharedMemorySize, GSMEM);
    }

    prep0<<<NCVT_BLK + TABLE_E, 256>>>(x, qkv_w, proj_w,
                                       rpb, cpb_w1, cpb_b1, cpb_w2);
    prep1<<<4096 + NFRAG / 256, 256>>>(mask, rpb_idx);
    {
        dim3 grid(QKV_LD / 128, (BATCH * NTOK) / 128);
        gemm_h<<<grid, 128, GSMEM>>>(p_xh, p_qkvw, nullptr, p_qkv,
                                     BATCH * NTOK, QKV_LD, DIM, 0);
    }
    attn_h<<<dim3(BATCH, NH, NTOK / 128), 128>>>();
    {
        dim3 grid(DIM / 128, (BATCH * NTOK) / 128);
        gemm_h<<<grid, 128, GSMEM>>>(p_att, p_projw, proj_b, out,
                                     BATCH * NTOK, DIM, DIM, 1);
    }
}

// round 11
// speedup vs baseline: 5.5632x; 1.0374x over previous
#include <cuda_runtime.h>
#include <cuda_fp16.h>
#include <math.h>
#include <stdint.h>

#define BATCH   128
#define NWIN    16
#define NTOK    512
#define DIM     256
#define NH      8
#define HD      32
#define TABLE_E 3375
#define QKV_LD  768
#define NN      (NTOK*NTOK)
#define LOG2E   1.4426950408889634f
#define NFRAG   65536
#define ONES_H2 0x3C003C00u
#define SCALE2  (0.17677669529663687f * LOG2E)

// ---------------- scratch (device globals) ----------------
__device__ float  g_table[TABLE_E * NH];
__device__ float4 g_biasF[NH * NFRAG];
__device__ float4 g_maskF[NWIN * NFRAG];
__device__ int    g_maskflag;
__device__ __half g_xh[(size_t)BATCH * NTOK * DIM];
__device__ __half g_qkvw[QKV_LD * DIM];
__device__ __half g_projw[DIM * DIM];
__device__ __half g_qkv[(size_t)BATCH * NTOK * QKV_LD];   // Q part pre-scaled by SCALE2
__device__ __half g_att[(size_t)BATCH * NTOK * DIM];

// =====================  helpers  =====================
__device__ __forceinline__ uint32_t pack_half2(float lo, float hi) {
    __half2 h = __floats2half2_rn(lo, hi);
    return *(uint32_t*)&h;
}
__device__ __forceinline__ uint32_t ex2_h2(float lo, float hi) {
    uint32_t d = pack_half2(lo, hi), r;
    asm("ex2.approx.f16x2 %0, %1;" : "=r"(r) : "r"(d));
    return r;
}
__device__ __forceinline__ void mma_f16(float* d, const uint32_t* a,
                                        uint32_t b0, uint32_t b1) {
    asm volatile(
        "mma.sync.aligned.m16n8k16.row.col.f32.f16.f16.f32 "
        "{%0,%1,%2,%3}, {%4,%5,%6,%7}, {%8,%9}, {%0,%1,%2,%3};"
        : "+f"(d[0]), "+f"(d[1]), "+f"(d[2]), "+f"(d[3])
        : "r"(a[0]), "r"(a[1]), "r"(a[2]), "r"(a[3]), "r"(b0), "r"(b1));
}
__device__ __forceinline__ void ldsm4(uint32_t* r, uint32_t addr) {
    asm volatile("ldmatrix.sync.aligned.m8n8.x4.shared.b16 {%0,%1,%2,%3}, [%4];"
                 : "=r"(r[0]), "=r"(r[1]), "=r"(r[2]), "=r"(r[3]) : "r"(addr));
}
__device__ __forceinline__ void ldsm4t(uint32_t* r, uint32_t addr) {
    asm volatile("ldmatrix.sync.aligned.m8n8.x4.trans.shared.b16 {%0,%1,%2,%3}, [%4];"
                 : "=r"(r[0]), "=r"(r[1]), "=r"(r[2]), "=r"(r[3]) : "r"(addr));
}
__device__ __forceinline__ uint32_t cvta_s(const void* p) {
    return (uint32_t)__cvta_generic_to_shared(p);
}
__device__ __forceinline__ uint32_t swz(int r, int kchunk) {
    return (uint32_t)(r * 64 + ((kchunk ^ ((r >> 1) & 3)) << 4));
}
__device__ __forceinline__ uint32_t swz128(int r, int kchunk) {
    return (uint32_t)(r * 128 + ((kchunk ^ (r & 7)) << 4));
}
__device__ __forceinline__ void cp16(uint32_t smem, const void* g) {
    asm volatile("cp.async.cg.shared.global [%0], [%1], 16;"
                 :: "r"(smem), "l"(g) : "memory");
}
__device__ __forceinline__ void cp_commit() {
    asm volatile("cp.async.commit_group;" ::: "memory");
}
__device__ __forceinline__ void cp_wait0() {
    asm volatile("cp.async.wait_group 0;" ::: "memory");
}

// ---------------- prep0: fp32->fp16 conversions + CPB MLP ----------------
#define N8X ((BATCH * NTOK * DIM) / 8)
#define N8W ((QKV_LD * DIM) / 8)
#define N8P ((DIM * DIM) / 8)
#define N8T (N8X + N8W + N8P)
#define NCVT_BLK ((N8T + 255) / 256)
__global__ void prep0(const float* __restrict__ x,
                      const float* __restrict__ qw,
                      const float* __restrict__ pw,
                      const float* __restrict__ rpb,
                      const float* __restrict__ w1,
                      const float* __restrict__ b1,
                      const float* __restrict__ w2) {
    int bx = blockIdx.x;
    if (bx < NCVT_BLK) {
        int i = bx * 256 + threadIdx.x;
        if (i == 0) g_maskflag = 0;
        const float* s;
        __half* d;
        int j;
        if (i < N8X)                  { s = x;  d = g_xh;    j = i; }
        else if (i < N8X + N8W)       { s = qw; d = g_qkvw;  j = i - N8X; }
        else if (i < N8T)             { s = pw; d = g_projw; j = i - N8X - N8W; }
        else return;
        const float4* sp = (const float4*)s + (size_t)j * 2;
        float4 a = sp[0], b = sp[1];
        uint4 o;
        o.x = pack_half2(a.x, a.y); o.y = pack_half2(a.z, a.w);
        o.z = pack_half2(b.x, b.y); o.w = pack_half2(b.z, b.w);
        ((uint4*)d)[j] = o;
    } else {
        int e = bx - NCVT_BLK;
        int h = threadIdx.x >> 5;
        int lane = threadIdx.x & 31;
        float r0 = rpb[e * 3 + 0], r1 = rpb[e * 3 + 1], r2 = rpb[e * 3 + 2];
        float sum = 0.f;
        for (int o = lane; o < 512; o += 32) {
            float hid = fmaf(r0, w1[o * 3 + 0],
                        fmaf(r1, w1[o * 3 + 1],
                        fmaf(r2, w1[o * 3 + 2], b1[o])));
            hid = fmaxf(hid, 0.f);
            sum = fmaf(hid, w2[h * 512 + o], sum);
        }
        #pragma unroll
        for (int off = 16; off; off >>= 1)
            sum += __shfl_xor_sync(0xffffffffu, sum, off);
        if (lane == 0) g_table[e * NH + h] = sum;
    }
}

// ---------------- prep1: maskF + biasF (fused) -----------------------------
__global__ void prep1(const float* __restrict__ mask,
                      const int* __restrict__ rpb_idx) {
    int bx = blockIdx.x;
    if (bx < 4096) {
        int w = bx >> 8;
        int i = (bx & 255) * 256 + threadIdx.x;
        int g = i & 7, t = (i >> 3) & 3, jn = (i >> 5) & 7, c = (i >> 8) & 7;
        int wid = (i >> 11) & 7, qt = i >> 14;
        int q0 = qt * 128 + wid * 16 + g;
        int k0 = c * 64 + jn * 8 + 2 * t;
        const float* mw = mask + (size_t)w * NN;
        float4 v;
        v.x = mw[q0 * NTOK + k0];
        v.y = mw[q0 * NTOK + k0 + 1];
        v.z = mw[(q0 + 8) * NTOK + k0];
        v.w = mw[(q0 + 8) * NTOK + k0 + 1];
        bool nz = (v.x != 0.f) | (v.y != 0.f) | (v.z != 0.f) | (v.w != 0.f);
        v.x *= LOG2E; v.y *= LOG2E; v.z *= LOG2E; v.w *= LOG2E;
        g_maskF[(size_t)w * NFRAG + i] = v;
        if (__syncthreads_or(nz) && threadIdx.x == 0)
            atomicOr(&g_maskflag, 1);
    } else {
        int i = (bx - 4096) * 256 + threadIdx.x;
        int g = i & 7, t = (i >> 3) & 3, jn = (i >> 5) & 7, c = (i >> 8) & 7;
        int wid = (i >> 11) & 7, qt = i >> 14;
        int q0 = qt * 128 + wid * 16 + g;
        int k0 = c * 64 + jn * 8 + 2 * t;
        int i00 = rpb_idx[q0 * NTOK + k0];
        int i10 = rpb_idx[q0 * NTOK + k0 + 1];
        int i01 = rpb_idx[(q0 + 8) * NTOK + k0];
        int i11 = rpb_idx[(q0 + 8) * NTOK + k0 + 1];
        const float S = 16.f * LOG2E;
        #pragma unroll
        for (int h = 0; h < NH; h++) {
            float4 v;
            v.x = S / (1.f + __expf(-g_table[i00 * NH + h]));
            v.y = S / (1.f + __expf(-g_table[i10 * NH + h]));
            v.z = S / (1.f + __expf(-g_table[i01 * NH + h]));
            v.w = S / (1.f + __expf(-g_table[i11 * NH + h]));
            g_biasF[h * NFRAG + i] = v;
        }
    }
}

// =====================  fp16 mma GEMM (NT), 64x64 warp tiles, BK=64  =====
// fp16out path scales columns < qcols by qsc (used to pre-scale Q by SCALE2)
#define GSMEM (4 * 16384)
__global__ __launch_bounds__(128, 2) void gemm_h(const __half* __restrict__ A,
                                                 const __half* __restrict__ B,
                                                 const float* __restrict__ bias,
                                                 void* __restrict__ Cv,
                                                 int M, int N, int K, int fp32out,
                                                 int qcols, float qsc) {
    extern __shared__ __align__(16) char gsm[];
    const int tid = threadIdx.x, lane = tid & 31, wid = tid >> 5;
    const int g = lane >> 2, t = lane & 3;
    const int wm = wid & 1, wn = wid >> 1;
    const int row0 = blockIdx.y * 128, col0 = blockIdx.x * 128;

    const int lr0 = tid >> 3, lc = tid & 7;
    const __half* Ap = A + (size_t)(row0 + lr0) * K + lc * 8;
    const __half* Bp = B + (size_t)(col0 + lr0) * K + lc * 8;
    const size_t rstep = (size_t)16 * K;
    uint32_t aS[2] = { cvta_s(gsm), cvta_s(gsm) + 16384 };
    uint32_t bS[2] = { cvta_s(gsm) + 32768, cvta_s(gsm) + 49152 };
    uint32_t soffs[8];
    #pragma unroll
    for (int i = 0; i < 8; i++) soffs[i] = swz128(lr0 + i * 16, lc);

    float acc[4][8][4];
    #pragma unroll
    for (int mt = 0; mt < 4; mt++)
        #pragma unroll
        for (int jn = 0; jn < 8; jn++)
            #pragma unroll
            for (int r = 0; r < 4; r++) acc[mt][jn][r] = 0.f;

    #pragma unroll
    for (int i = 0; i < 8; i++) {
        cp16(aS[0] + soffs[i], Ap + i * rstep);
        cp16(bS[0] + soffs[i], Bp + i * rstep);
    }
    cp_commit();

    const int nk = K >> 6;
    for (int kt = 0; kt < nk; kt++) {
        const int s = kt & 1;
        cp_wait0();
        __syncthreads();
        if (kt + 1 < nk) {
            int ko = (kt + 1) * 64;
            #pragma unroll
            for (int i = 0; i < 8; i++) {
                cp16(aS[s ^ 1] + soffs[i], Ap + i * rstep + ko);
                cp16(bS[s ^ 1] + soffs[i], Bp + i * rstep + ko);
            }
            cp_commit();
        }
        #pragma unroll
        for (int ks = 0; ks < 4; ks++) {
            uint32_t af[4][4];
            #pragma unroll
            for (int mt = 0; mt < 4; mt++) {
                int row = wm * 64 + mt * 16 + (lane & 15);
                int kch = ks * 2 + (lane >> 4);
                ldsm4(af[mt], aS[s] + swz128(row, kch));
            }
            uint32_t bf[4][4];
            #pragma unroll
            for (int i = 0; i < 4; i++) {
                int rn = wn * 64 + i * 16 + ((lane >> 4) << 3) + (lane & 7);
                int kch = ks * 2 + ((lane & 8) >> 3);
                ldsm4(bf[i], bS[s] + swz128(rn, kch));
            }
            #pragma unroll
            for (int mt = 0; mt < 4; mt++)
                #pragma unroll
                for (int jn = 0; jn < 8; jn++)
                    mma_f16(acc[mt][jn], af[mt],
                            bf[jn >> 1][(jn & 1) * 2], bf[jn >> 1][(jn & 1) * 2 + 1]);
        }
        __syncthreads();
    }

    if (fp32out) {
        float* C = (float*)Cv;
        #pragma unroll
        for (int mt = 0; mt < 4; mt++) {
            int r = row0 + wm * 64 + mt * 16;
            #pragma unroll
            for (int jn = 0; jn < 8; jn++) {
                int cc = col0 + wn * 64 + jn * 8 + 2 * t;
                float bx = bias[cc], by = bias[cc + 1];
                float2 v0 = { acc[mt][jn][0] + bx, acc[mt][jn][1] + by };
                float2 v1 = { acc[mt][jn][2] + bx, acc[mt][jn][3] + by };
                *(float2*)(C + (size_t)(r + g) * N + cc) = v0;
                *(float2*)(C + (size_t)(r + g + 8) * N + cc) = v1;
            }
        }
    } else {
        __half* C = (__half*)Cv;
        #pragma unroll
        for (int mt = 0; mt < 4; mt++) {
            int r = row0 + wm * 64 + mt * 16;
            #pragma unroll
            for (int jn = 0; jn < 8; jn++) {
                int cc = col0 + wn * 64 + jn * 8 + 2 * t;
                float sc_ = (cc < qcols) ? qsc : 1.f;
                *(uint32_t*)(C + (size_t)(r + g) * N + cc)
                    = pack_half2(acc[mt][jn][0] * sc_, acc[mt][jn][1] * sc_);
                *(uint32_t*)(C + (size_t)(r + g + 8) * N + cc)
                    = pack_half2(acc[mt][jn][2] * sc_, acc[mt][jn][3] * sc_);
            }
        }
    }
}

// =====================  fused fp16 mma attention ============================
// 4 warps x 32 q-rows; 32-key sub-chunk softmax; bias as mma C-init;
// Q pre-scaled; f16x2 EX2; l via ones-mma. 3 blocks/SM.
__global__ __launch_bounds__(128, 3) void attn_h() {
    __shared__ __align__(16) __half Ks[2][64 * 32];
    __shared__ __align__(16) __half Vs[2][64 * 32];
    const int b = blockIdx.x, h = blockIdx.y, qt = blockIdx.z;
    const int tid = threadIdx.x, lane = tid & 31, w = tid >> 5;
    const int g = lane >> 2, t = lane & 3;
    const int q0 = qt * 128 + w * 32;
    const __half* base = g_qkv + (size_t)b * NTOK * QKV_LD;
    const bool use_mask = (g_maskflag != 0);

    const __half* kp0 = base + (size_t)(tid >> 2) * QKV_LD + DIM + h * HD + (tid & 3) * 8;
    const __half* kp1 = base + (size_t)((tid + 128) >> 2) * QKV_LD + DIM + h * HD
                             + ((tid + 128) & 3) * 8;
    const uint32_t sf0 = swz(tid >> 2, tid & 3);
    const uint32_t sf1 = swz((tid + 128) >> 2, (tid + 128) & 3);
    const uint32_t kS[2] = { cvta_s(Ks[0]), cvta_s(Ks[1]) };
    const uint32_t vS[2] = { cvta_s(Vs[0]), cvta_s(Vs[1]) };

    cp16(kS[0] + sf0, kp0);
    cp16(kS[0] + sf1, kp1);
    cp16(vS[0] + sf0, kp0 + DIM);
    cp16(vS[0] + sf1, kp1 + DIM);
    cp_commit();

    uint32_t qa[2][2][4];   // [mt][ks][4]  (Q already scaled by SCALE2)
    #pragma unroll
    for (int mt = 0; mt < 2; mt++) {
        const __half* qp0 = base + (size_t)(q0 + mt * 16 + g) * QKV_LD + h * HD;
        const __half* qp8 = qp0 + (size_t)8 * QKV_LD;
        #pragma unroll
        for (int ks = 0; ks < 2; ks++) {
            qa[mt][ks][0] = *(const uint32_t*)(qp0 + ks * 16 + 2 * t);
            qa[mt][ks][1] = *(const uint32_t*)(qp8 + ks * 16 + 2 * t);
            qa[mt][ks][2] = *(const uint32_t*)(qp0 + ks * 16 + 8 + 2 * t);
            qa[mt][ks][3] = *(const uint32_t*)(qp8 + ks * 16 + 8 + 2 * t);
        }
    }

    float o[2][4][4];
    float lacc[2][4];
    #pragma unroll
    for (int mt = 0; mt < 2; mt++) {
        #pragma unroll
        for (int nd = 0; nd < 4; nd++)
            #pragma unroll
            for (int r = 0; r < 4; r++) o[mt][nd][r] = 0.f;
        #pragma unroll
        for (int r = 0; r < 4; r++) lacc[mt][r] = 0.f;
    }
    float m[2][2] = { { -1e30f, -1e30f }, { -1e30f, -1e30f } };

    const float4* bp4[2];
    const float4* mp4[2];
    #pragma unroll
    for (int mt = 0; mt < 2; mt++) {
        int we = w * 2 + mt;
        bp4[mt] = g_biasF + (((size_t)h * 4 + qt) * 8 + we) * 2048 + t * 8 + g;
        mp4[mt] = g_maskF + (((size_t)(b & (NWIN - 1)) * 4 + qt) * 8 + we) * 2048
                          + t * 8 + g;
    }

    for (int c = 0; c < 8; c++) {
        const int s = c & 1;
        cp_wait0();
        __syncthreads();
        if (c < 7) {
            const size_t nb = (size_t)(c + 1) * 64 * QKV_LD;
            cp16(kS[s ^ 1] + sf0, kp0 + nb);
            cp16(kS[s ^ 1] + sf1, kp1 + nb);
            cp16(vS[s ^ 1] + sf0, kp0 + nb + DIM);
            cp16(vS[s ^ 1] + sf1, kp1 + nb + DIM);
            cp_commit();
        }

        // two 32-key sub-chunks
        #pragma unroll
        for (int sh = 0; sh < 2; sh++) {
            // ---- S = bias (+mask) + Q K^T ----
            float sc[2][4][4];
            #pragma unroll
            for (int mt = 0; mt < 2; mt++) {
                const float4* bc = bp4[mt] + c * 256 + sh * 128;
                const float4* mc = mp4[mt] + c * 256 + sh * 128;
                #pragma unroll
                for (int jn = 0; jn < 4; jn++) {
                    float4 bv = bc[jn * 32];
                    if (use_mask) {
                        float4 mv = mc[jn * 32];
                        bv.x += mv.x; bv.y += mv.y; bv.z += mv.z; bv.w += mv.w;
                    }
                    sc[mt][jn][0] = bv.x; sc[mt][jn][1] = bv.y;
                    sc[mt][jn][2] = bv.z; sc[mt][jn][3] = bv.w;
                }
            }
            #pragma unroll
            for (int ks = 0; ks < 2; ks++) {
                uint32_t kb[2][4];
                #pragma unroll
                for (int i = 0; i < 2; i++) {
                    int rn = sh * 32 + i * 16 + ((lane >> 4) << 3) + (lane & 7);
                    int kch = ks * 2 + ((lane & 8) >> 3);
                    ldsm4(kb[i], kS[s] + swz(rn, kch));
                }
                #pragma unroll
                for (int jn = 0; jn < 4; jn++) {
                    uint32_t b0 = kb[jn >> 1][(jn & 1) * 2];
                    uint32_t b1 = kb[jn >> 1][(jn & 1) * 2 + 1];
                    mma_f16(sc[0][jn], qa[0][ks], b0, b1);
                    mma_f16(sc[1][jn], qa[1][ks], b0, b1);
                }
            }

            // ---- online softmax (base 2) per m-tile ----
            uint32_t pa[2][2][4];
            #pragma unroll
            for (int mt = 0; mt < 2; mt++) {
                float mx0 = sc[mt][0][0], mx1 = sc[mt][0][2];
                #pragma unroll
                for (int jn = 0; jn < 4; jn++) {
                    mx0 = fmaxf(mx0, fmaxf(sc[mt][jn][0], sc[mt][jn][1]));
                    mx1 = fmaxf(mx1, fmaxf(sc[mt][jn][2], sc[mt][jn][3]));
                }
                mx0 = fmaxf(mx0, __shfl_xor_sync(0xffffffffu, mx0, 1));
                mx0 = fmaxf(mx0, __shfl_xor_sync(0xffffffffu, mx0, 2));
                mx1 = fmaxf(mx1, __shfl_xor_sync(0xffffffffu, mx1, 1));
                mx1 = fmaxf(mx1, __shfl_xor_sync(0xffffffffu, mx1, 2));
                float nm0 = fmaxf(m[mt][0], mx0), nm1 = fmaxf(m[mt][1], mx1);
                float c0 = exp2f(m[mt][0] - nm0), c1 = exp2f(m[mt][1] - nm1);
                m[mt][0] = nm0; m[mt][1] = nm1;
                #pragma unroll
                for (int nd = 0; nd < 4; nd++) {
                    o[mt][nd][0] *= c0; o[mt][nd][1] *= c0;
                    o[mt][nd][2] *= c1; o[mt][nd][3] *= c1;
                }
                lacc[mt][0] *= c0; lacc[mt][1] *= c0;
                lacc[mt][2] *= c1; lacc[mt][3] *= c1;
                #pragma unroll
                for (int kk = 0; kk < 2; kk++) {
                    pa[mt][kk][0] = ex2_h2(sc[mt][2*kk][0]   - nm0, sc[mt][2*kk][1]   - nm0);
                    pa[mt][kk][1] = ex2_h2(sc[mt][2*kk][2]   - nm1, sc[mt][2*kk][3]   - nm1);
                    pa[mt][kk][2] = ex2_h2(sc[mt][2*kk+1][0] - nm0, sc[mt][2*kk+1][1] - nm0);
                    pa[mt][kk][3] = ex2_h2(sc[mt][2*kk+1][2] - nm1, sc[mt][2*kk+1][3] - nm1);
                }
                #pragma unroll
                for (int kk = 0; kk < 2; kk++)
                    mma_f16(lacc[mt], pa[mt][kk], ONES_H2, ONES_H2);
            }

            // ---- O += P V ----
            #pragma unroll
            for (int ndp = 0; ndp < 2; ndp++)
                #pragma unroll
                for (int kk = 0; kk < 2; kk++) {
                    uint32_t vb[4];
                    int key = sh * 32 + kk * 16 + (lane & 15);
                    int kch = ndp * 2 + (lane >> 4);
                    ldsm4t(vb, vS[s] + swz(key, kch));
                    #pragma unroll
                    for (int mt = 0; mt < 2; mt++) {
                        mma_f16(o[mt][ndp * 2],     pa[mt][kk], vb[0], vb[1]);
                        mma_f16(o[mt][ndp * 2 + 1], pa[mt][kk], vb[2], vb[3]);
                    }
                }
        }
        __syncthreads();
    }

    // finalize
    #pragma unroll
    for (int mt = 0; mt < 2; mt++) {
        float i0 = 1.f / lacc[mt][0], i1 = 1.f / lacc[mt][2];
        __half* op0 = g_att + ((size_t)b * NTOK + q0 + mt * 16 + g) * DIM + h * HD;
        __half* op8 = op0 + (size_t)8 * DIM;
        #pragma unroll
        for (int nd = 0; nd < 4; nd++) {
            *(uint32_t*)(op0 + nd * 8 + 2 * t)
                = pack_half2(o[mt][nd][0] * i0, o[mt][nd][1] * i0);
            *(uint32_t*)(op8 + nd * 8 + 2 * t)
                = pack_half2(o[mt][nd][2] * i1, o[mt][nd][3] * i1);
        }
    }
}

// ---------------- launch ----------------
extern "C" void kernel_launch(void* const* d_in, const int* in_sizes, int n_in,
                              void* d_out, int out_size) {
    const float* x      = (const float*)d_in[0];
    const float* mask   = (const float*)d_in[1];
    const float* qkv_w  = (const float*)d_in[2];
    const float* proj_w = (const float*)d_in[3];
    const float* proj_b = (const float*)d_in[4];
    const float* cpb_w1 = (const float*)d_in[5];
    const float* cpb_b1 = (const float*)d_in[6];
    const float* cpb_w2 = (const float*)d_in[7];
    const float* rpb    = (const float*)d_in[8];
    const int*   rpb_idx = (const int*)d_in[9];
    float* out = (float*)d_out;

    static __half *p_xh = nullptr, *p_qkvw = nullptr, *p_projw = nullptr,
                  *p_qkv = nullptr, *p_att = nullptr;
    if (!p_xh) {
        cudaGetSymbolAddress((void**)&p_xh, g_xh);
        cudaGetSymbolAddress((void**)&p_qkvw, g_qkvw);
        cudaGetSymbolAddress((void**)&p_projw, g_projw);
        cudaGetSymbolAddress((void**)&p_qkv, g_qkv);
        cudaGetSymbolAddress((void**)&p_att, g_att);
        cudaFuncSetAttribute(gemm_h,
                             cudaFuncAttributeMaxDynamicSharedMemorySize, GSMEM);
    }

    prep0<<<NCVT_BLK + TABLE_E, 256>>>(x, qkv_w, proj_w,
                                       rpb, cpb_w1, cpb_b1, cpb_w2);
    prep1<<<4096 + NFRAG / 256, 256>>>(mask, rpb_idx);
    {
        dim3 grid(QKV_LD / 128, (BATCH * NTOK) / 128);
        gemm_h<<<grid, 128, GSMEM>>>(p_xh, p_qkvw, nullptr, p_qkv,
                                     BATCH * NTOK, QKV_LD, DIM, 0, DIM, SCALE2);
    }
    attn_h<<<dim3(BATCH, NH, NTOK / 128), 128>>>();
    {
        dim3 grid(DIM / 128, (BATCH * NTOK) / 128);
        gemm_h<<<grid, 128, GSMEM>>>(p_att, p_projw, proj_b, out,
                                     BATCH * NTOK, DIM, DIM, 1, 0, 1.f);
    }
}

// round 12
// speedup vs baseline: 6.1057x; 1.0975x over previous
#include <cuda_runtime.h>
#include <cuda_fp16.h>
#include <math.h>
#include <stdint.h>

#define BATCH   128
#define NWIN    16
#define NTOK    512
#define DIM     256
#define NH      8
#define HD      32
#define TABLE_E 3375
#define QKV_LD  768
#define NN      (NTOK*NTOK)
#define LOG2E   1.4426950408889634f
#define NFRAG   65536
#define ONES_H2 0x3C003C00u
#define SCALE2  (0.17677669529663687f * LOG2E)
#define RAWK    (65536.f / 24.f)         // raw units per log2-unit
#define KDEC    (24.f / 65536.f)         // log2-units per raw unit

// ---------------- scratch (device globals) ----------------
__device__ float  g_table[TABLE_E * NH];
__device__ uint4  g_biasU[NH * 32768];      // u16 fixed-point bias (raw units), 4 MB
__device__ float4 g_maskF[NWIN * NFRAG];    // fragment-layout mask (raw units)
__device__ int    g_maskflag;
__device__ __half g_xh[(size_t)BATCH * NTOK * DIM];
__device__ __half g_qkvw[QKV_LD * DIM];
__device__ __half g_projw[DIM * DIM];
__device__ __half g_qkv[(size_t)BATCH * NTOK * QKV_LD];   // Q pre-scaled to raw units
__device__ __half g_att[(size_t)BATCH * NTOK * DIM];

// =====================  helpers  =====================
__device__ __forceinline__ uint32_t pack_half2(float lo, float hi) {
    __half2 h = __floats2half2_rn(lo, hi);
    return *(uint32_t*)&h;
}
__device__ __forceinline__ uint32_t ex2_h2(float lo, float hi) {
    uint32_t d = pack_half2(lo, hi), r;
    asm("ex2.approx.f16x2 %0, %1;" : "=r"(r) : "r"(d));
    return r;
}
__device__ __forceinline__ void mma_f16(float* d, const uint32_t* a,
                                        uint32_t b0, uint32_t b1) {
    asm volatile(
        "mma.sync.aligned.m16n8k16.row.col.f32.f16.f16.f32 "
        "{%0,%1,%2,%3}, {%4,%5,%6,%7}, {%8,%9}, {%0,%1,%2,%3};"
        : "+f"(d[0]), "+f"(d[1]), "+f"(d[2]), "+f"(d[3])
        : "r"(a[0]), "r"(a[1]), "r"(a[2]), "r"(a[3]), "r"(b0), "r"(b1));
}
__device__ __forceinline__ void ldsm4(uint32_t* r, uint32_t addr) {
    asm volatile("ldmatrix.sync.aligned.m8n8.x4.shared.b16 {%0,%1,%2,%3}, [%4];"
                 : "=r"(r[0]), "=r"(r[1]), "=r"(r[2]), "=r"(r[3]) : "r"(addr));
}
__device__ __forceinline__ void ldsm4t(uint32_t* r, uint32_t addr) {
    asm volatile("ldmatrix.sync.aligned.m8n8.x4.trans.shared.b16 {%0,%1,%2,%3}, [%4];"
                 : "=r"(r[0]), "=r"(r[1]), "=r"(r[2]), "=r"(r[3]) : "r"(addr));
}
__device__ __forceinline__ uint32_t cvta_s(const void* p) {
    return (uint32_t)__cvta_generic_to_shared(p);
}
__device__ __forceinline__ uint32_t swz(int r, int kchunk) {
    return (uint32_t)(r * 64 + ((kchunk ^ ((r >> 1) & 3)) << 4));
}
__device__ __forceinline__ uint32_t swz128(int r, int kchunk) {
    return (uint32_t)(r * 128 + ((kchunk ^ (r & 7)) << 4));
}
__device__ __forceinline__ void cp16(uint32_t smem, const void* g) {
    asm volatile("cp.async.cg.shared.global [%0], [%1], 16;"
                 :: "r"(smem), "l"(g) : "memory");
}
__device__ __forceinline__ void cp_commit() {
    asm volatile("cp.async.commit_group;" ::: "memory");
}
__device__ __forceinline__ void cp_wait0() {
    asm volatile("cp.async.wait_group 0;" ::: "memory");
}

// ---------------- prep0: fp32->fp16 conversions + CPB MLP ----------------
#define N8X ((BATCH * NTOK * DIM) / 8)
#define N8W ((QKV_LD * DIM) / 8)
#define N8P ((DIM * DIM) / 8)
#define N8T (N8X + N8W + N8P)
#define NCVT_BLK ((N8T + 255) / 256)
__global__ void prep0(const float* __restrict__ x,
                      const float* __restrict__ qw,
                      const float* __restrict__ pw,
                      const float* __restrict__ rpb,
                      const float* __restrict__ w1,
                      const float* __restrict__ b1,
                      const float* __restrict__ w2) {
    int bx = blockIdx.x;
    if (bx < NCVT_BLK) {
        int i = bx * 256 + threadIdx.x;
        if (i == 0) g_maskflag = 0;
        const float* s;
        __half* d;
        int j;
        if (i < N8X)                  { s = x;  d = g_xh;    j = i; }
        else if (i < N8X + N8W)       { s = qw; d = g_qkvw;  j = i - N8X; }
        else if (i < N8T)             { s = pw; d = g_projw; j = i - N8X - N8W; }
        else return;
        const float4* sp = (const float4*)s + (size_t)j * 2;
        float4 a = sp[0], b = sp[1];
        uint4 o;
        o.x = pack_half2(a.x, a.y); o.y = pack_half2(a.z, a.w);
        o.z = pack_half2(b.x, b.y); o.w = pack_half2(b.z, b.w);
        ((uint4*)d)[j] = o;
    } else {
        int e = bx - NCVT_BLK;
        int h = threadIdx.x >> 5;
        int lane = threadIdx.x & 31;
        float r0 = rpb[e * 3 + 0], r1 = rpb[e * 3 + 1], r2 = rpb[e * 3 + 2];
        float sum = 0.f;
        for (int o = lane; o < 512; o += 32) {
            float hid = fmaf(r0, w1[o * 3 + 0],
                        fmaf(r1, w1[o * 3 + 1],
                        fmaf(r2, w1[o * 3 + 2], b1[o])));
            hid = fmaxf(hid, 0.f);
            sum = fmaf(hid, w2[h * 512 + o], sum);
        }
        #pragma unroll
        for (int off = 16; off; off >>= 1)
            sum += __shfl_xor_sync(0xffffffffu, sum, off);
        if (lane == 0) g_table[e * NH + h] = sum;
    }
}

// ---------------- prep1: maskF (raw units) + biasU (u16) -------------------
__global__ void prep1(const float* __restrict__ mask,
                      const int* __restrict__ rpb_idx) {
    int bx = blockIdx.x;
    if (bx < 4096) {
        int w = bx >> 8;
        int i = (bx & 255) * 256 + threadIdx.x;
        int g = i & 7, t = (i >> 3) & 3, jn = (i >> 5) & 7, c = (i >> 8) & 7;
        int wid = (i >> 11) & 7, qt = i >> 14;
        int q0 = qt * 128 + wid * 16 + g;
        int k0 = c * 64 + jn * 8 + 2 * t;
        const float* mw = mask + (size_t)w * NN;
        float4 v;
        v.x = mw[q0 * NTOK + k0];
        v.y = mw[q0 * NTOK + k0 + 1];
        v.z = mw[(q0 + 8) * NTOK + k0];
        v.w = mw[(q0 + 8) * NTOK + k0 + 1];
        bool nz = (v.x != 0.f) | (v.y != 0.f) | (v.z != 0.f) | (v.w != 0.f);
        const float MS = LOG2E * RAWK;       // mask in raw units
        v.x *= MS; v.y *= MS; v.z *= MS; v.w *= MS;
        g_maskF[(size_t)w * NFRAG + i] = v;
        if (__syncthreads_or(nz) && threadIdx.x == 0)
            atomicOr(&g_maskflag, 1);
    } else {
        int i = (bx - 4096) * 256 + threadIdx.x;    // 0..32767
        int g = i & 7, t = (i >> 3) & 3, jp = (i >> 5) & 1, sh = (i >> 6) & 1;
        int c = (i >> 7) & 7, we = (i >> 10) & 7, qt = i >> 13;
        int q0 = qt * 128 + we * 16 + g;
        int kbase = c * 64 + sh * 32 + jp * 16 + 2 * t;
        int idx[8];
        #pragma unroll
        for (int jj = 0; jj < 2; jj++) {
            int k0 = kbase + jj * 8;
            idx[jj * 4 + 0] = rpb_idx[q0 * NTOK + k0];
            idx[jj * 4 + 1] = rpb_idx[q0 * NTOK + k0 + 1];
            idx[jj * 4 + 2] = rpb_idx[(q0 + 8) * NTOK + k0];
            idx[jj * 4 + 3] = rpb_idx[(q0 + 8) * NTOK + k0 + 1];
        }
        const float KENC = 16.f * LOG2E * RAWK;
        size_t obase = (size_t)qt * 8192 + we * 1024 + c * 128 + sh * 64
                     + jp * 32 + t * 8 + g;
        #pragma unroll
        for (int h = 0; h < NH; h++) {
            uint32_t u[8];
            #pragma unroll
            for (int v = 0; v < 8; v++) {
                float val = KENC / (1.f + __expf(-g_table[idx[v] * NH + h]));
                u[v] = (uint32_t)(val + 0.5f);
            }
            uint4 o4;
            o4.x = u[0] | (u[1] << 16);
            o4.y = u[2] | (u[3] << 16);
            o4.z = u[4] | (u[5] << 16);
            o4.w = u[6] | (u[7] << 16);
            g_biasU[(size_t)h * 32768 + obase] = o4;
        }
    }
}

// =====================  fp16 mma GEMM (NT), 64x64 warp tiles, BK=64  =====
#define GSMEM (4 * 16384)
__global__ __launch_bounds__(128, 2) void gemm_h(const __half* __restrict__ A,
                                                 const __half* __restrict__ B,
                                                 const float* __restrict__ bias,
                                                 void* __restrict__ Cv,
                                                 int M, int N, int K, int fp32out,
                                                 int qcols, float qsc) {
    extern __shared__ __align__(16) char gsm[];
    const int tid = threadIdx.x, lane = tid & 31, wid = tid >> 5;
    const int g = lane >> 2, t = lane & 3;
    const int wm = wid & 1, wn = wid >> 1;
    const int row0 = blockIdx.y * 128, col0 = blockIdx.x * 128;

    const int lr0 = tid >> 3, lc = tid & 7;
    const __half* Ap = A + (size_t)(row0 + lr0) * K + lc * 8;
    const __half* Bp = B + (size_t)(col0 + lr0) * K + lc * 8;
    const size_t rstep = (size_t)16 * K;
    uint32_t aS[2] = { cvta_s(gsm), cvta_s(gsm) + 16384 };
    uint32_t bS[2] = { cvta_s(gsm) + 32768, cvta_s(gsm) + 49152 };
    uint32_t soffs[8];
    #pragma unroll
    for (int i = 0; i < 8; i++) soffs[i] = swz128(lr0 + i * 16, lc);

    float acc[4][8][4];
    #pragma unroll
    for (int mt = 0; mt < 4; mt++)
        #pragma unroll
        for (int jn = 0; jn < 8; jn++)
            #pragma unroll
            for (int r = 0; r < 4; r++) acc[mt][jn][r] = 0.f;

    #pragma unroll
    for (int i = 0; i < 8; i++) {
        cp16(aS[0] + soffs[i], Ap + i * rstep);
        cp16(bS[0] + soffs[i], Bp + i * rstep);
    }
    cp_commit();

    const int nk = K >> 6;
    for (int kt = 0; kt < nk; kt++) {
        const int s = kt & 1;
        cp_wait0();
        __syncthreads();
        if (kt + 1 < nk) {
            int ko = (kt + 1) * 64;
            #pragma unroll
            for (int i = 0; i < 8; i++) {
                cp16(aS[s ^ 1] + soffs[i], Ap + i * rstep + ko);
                cp16(bS[s ^ 1] + soffs[i], Bp + i * rstep + ko);
            }
            cp_commit();
        }
        #pragma unroll
        for (int ks = 0; ks < 4; ks++) {
            uint32_t af[4][4];
            #pragma unroll
            for (int mt = 0; mt < 4; mt++) {
                int row = wm * 64 + mt * 16 + (lane & 15);
                int kch = ks * 2 + (lane >> 4);
                ldsm4(af[mt], aS[s] + swz128(row, kch));
            }
            uint32_t bf[4][4];
            #pragma unroll
            for (int i = 0; i < 4; i++) {
                int rn = wn * 64 + i * 16 + ((lane >> 4) << 3) + (lane & 7);
                int kch = ks * 2 + ((lane & 8) >> 3);
                ldsm4(bf[i], bS[s] + swz128(rn, kch));
            }
            #pragma unroll
            for (int mt = 0; mt < 4; mt++)
                #pragma unroll
                for (int jn = 0; jn < 8; jn++)
                    mma_f16(acc[mt][jn], af[mt],
                            bf[jn >> 1][(jn & 1) * 2], bf[jn >> 1][(jn & 1) * 2 + 1]);
        }
        __syncthreads();
    }

    if (fp32out) {
        float* C = (float*)Cv;
        #pragma unroll
        for (int mt = 0; mt < 4; mt++) {
            int r = row0 + wm * 64 + mt * 16;
            #pragma unroll
            for (int jn = 0; jn < 8; jn++) {
                int cc = col0 + wn * 64 + jn * 8 + 2 * t;
                float bx = bias[cc], by = bias[cc + 1];
                float2 v0 = { acc[mt][jn][0] + bx, acc[mt][jn][1] + by };
                float2 v1 = { acc[mt][jn][2] + bx, acc[mt][jn][3] + by };
                *(float2*)(C + (size_t)(r + g) * N + cc) = v0;
                *(float2*)(C + (size_t)(r + g + 8) * N + cc) = v1;
            }
        }
    } else {
        __half* C = (__half*)Cv;
        #pragma unroll
        for (int mt = 0; mt < 4; mt++) {
            int r = row0 + wm * 64 + mt * 16;
            #pragma unroll
            for (int jn = 0; jn < 8; jn++) {
                int cc = col0 + wn * 64 + jn * 8 + 2 * t;
                float sc_ = (cc < qcols) ? qsc : 1.f;
                *(uint32_t*)(C + (size_t)(r + g) * N + cc)
                    = pack_half2(acc[mt][jn][0] * sc_, acc[mt][jn][1] * sc_);
                *(uint32_t*)(C + (size_t)(r + g + 8) * N + cc)
                    = pack_half2(acc[mt][jn][2] * sc_, acc[mt][jn][3] * sc_);
            }
        }
    }
}

// =====================  fused fp16 mma attention ============================
// raw-unit softmax (u16 bias, Q pre-scaled); grid (qt,h,b): qt-fastest for K/V L2 reuse
__global__ __launch_bounds__(128, 3) void attn_h() {
    __shared__ __align__(16) __half Ks[2][64 * 32];
    __shared__ __align__(16) __half Vs[2][64 * 32];
    const int qt = blockIdx.x, h = blockIdx.y, b = blockIdx.z;
    const int tid = threadIdx.x, lane = tid & 31, w = tid >> 5;
    const int g = lane >> 2, t = lane & 3;
    const int q0 = qt * 128 + w * 32;
    const __half* base = g_qkv + (size_t)b * NTOK * QKV_LD;
    const bool use_mask = (g_maskflag != 0);

    const __half* kp0 = base + (size_t)(tid >> 2) * QKV_LD + DIM + h * HD + (tid & 3) * 8;
    const __half* kp1 = base + (size_t)((tid + 128) >> 2) * QKV_LD + DIM + h * HD
                             + ((tid + 128) & 3) * 8;
    const uint32_t sf0 = swz(tid >> 2, tid & 3);
    const uint32_t sf1 = swz((tid + 128) >> 2, (tid + 128) & 3);
    const uint32_t kS[2] = { cvta_s(Ks[0]), cvta_s(Ks[1]) };
    const uint32_t vS[2] = { cvta_s(Vs[0]), cvta_s(Vs[1]) };

    cp16(kS[0] + sf0, kp0);
    cp16(kS[0] + sf1, kp1);
    cp16(vS[0] + sf0, kp0 + DIM);
    cp16(vS[0] + sf1, kp1 + DIM);
    cp_commit();

    uint32_t qa[2][2][4];   // Q already in raw units
    #pragma unroll
    for (int mt = 0; mt < 2; mt++) {
        const __half* qp0 = base + (size_t)(q0 + mt * 16 + g) * QKV_LD + h * HD;
        const __half* qp8 = qp0 + (size_t)8 * QKV_LD;
        #pragma unroll
        for (int ks = 0; ks < 2; ks++) {
            qa[mt][ks][0] = *(const uint32_t*)(qp0 + ks * 16 + 2 * t);
            qa[mt][ks][1] = *(const uint32_t*)(qp8 + ks * 16 + 2 * t);
            qa[mt][ks][2] = *(const uint32_t*)(qp0 + ks * 16 + 8 + 2 * t);
            qa[mt][ks][3] = *(const uint32_t*)(qp8 + ks * 16 + 8 + 2 * t);
        }
    }

    float o[2][4][4];
    float lacc[2][4];
    #pragma unroll
    for (int mt = 0; mt < 2; mt++) {
        #pragma unroll
        for (int nd = 0; nd < 4; nd++)
            #pragma unroll
            for (int r = 0; r < 4; r++) o[mt][nd][r] = 0.f;
        #pragma unroll
        for (int r = 0; r < 4; r++) lacc[mt][r] = 0.f;
    }
    float m[2][2] = { { -1e30f, -1e30f }, { -1e30f, -1e30f } };

    const uint4* bU[2];
    const float4* mp4[2];
    #pragma unroll
    for (int mt = 0; mt < 2; mt++) {
        int we = w * 2 + mt;
        bU[mt] = g_biasU + (size_t)h * 32768 + (size_t)qt * 8192 + we * 1024
               + t * 8 + g;
        mp4[mt] = g_maskF + (((size_t)(b & (NWIN - 1)) * 4 + qt) * 8 + we) * 2048
                + t * 8 + g;
    }

    for (int c = 0; c < 8; c++) {
        const int s = c & 1;
        cp_wait0();
        __syncthreads();
        if (c < 7) {
            const size_t nb = (size_t)(c + 1) * 64 * QKV_LD;
            cp16(kS[s ^ 1] + sf0, kp0 + nb);
            cp16(kS[s ^ 1] + sf1, kp1 + nb);
            cp16(vS[s ^ 1] + sf0, kp0 + nb + DIM);
            cp16(vS[s ^ 1] + sf1, kp1 + nb + DIM);
            cp_commit();
        }

        // two 32-key sub-chunks
        #pragma unroll
        for (int sh = 0; sh < 2; sh++) {
            // ---- S init = bias (u16 decode, raw units) (+ mask) ----
            float sc[2][4][4];
            #pragma unroll
            for (int mt = 0; mt < 2; mt++) {
                const uint4* bu = bU[mt] + c * 128 + sh * 64;
                uint4 U0 = bu[0];
                uint4 U1 = bu[32];
                sc[mt][0][0] = (float)(U0.x & 0xffffu); sc[mt][0][1] = (float)(U0.x >> 16);
                sc[mt][0][2] = (float)(U0.y & 0xffffu); sc[mt][0][3] = (float)(U0.y >> 16);
                sc[mt][1][0] = (float)(U0.z & 0xffffu); sc[mt][1][1] = (float)(U0.z >> 16);
                sc[mt][1][2] = (float)(U0.w & 0xffffu); sc[mt][1][3] = (float)(U0.w >> 16);
                sc[mt][2][0] = (float)(U1.x & 0xffffu); sc[mt][2][1] = (float)(U1.x >> 16);
                sc[mt][2][2] = (float)(U1.y & 0xffffu); sc[mt][2][3] = (float)(U1.y >> 16);
                sc[mt][3][0] = (float)(U1.z & 0xffffu); sc[mt][3][1] = (float)(U1.z >> 16);
                sc[mt][3][2] = (float)(U1.w & 0xffffu); sc[mt][3][3] = (float)(U1.w >> 16);
                if (use_mask) {
                    const float4* mc = mp4[mt] + c * 256 + sh * 128;
                    #pragma unroll
                    for (int jn = 0; jn < 4; jn++) {
                        float4 mv = mc[jn * 32];
                        sc[mt][jn][0] += mv.x; sc[mt][jn][1] += mv.y;
                        sc[mt][jn][2] += mv.z; sc[mt][jn][3] += mv.w;
                    }
                }
            }
            // ---- S += Q K^T (raw units) ----
            #pragma unroll
            for (int ks = 0; ks < 2; ks++) {
                uint32_t kb[2][4];
                #pragma unroll
                for (int i = 0; i < 2; i++) {
                    int rn = sh * 32 + i * 16 + ((lane >> 4) << 3) + (lane & 7);
                    int kch = ks * 2 + ((lane & 8) >> 3);
                    ldsm4(kb[i], kS[s] + swz(rn, kch));
                }
                #pragma unroll
                for (int jn = 0; jn < 4; jn++) {
                    uint32_t b0 = kb[jn >> 1][(jn & 1) * 2];
                    uint32_t b1 = kb[jn >> 1][(jn & 1) * 2 + 1];
                    mma_f16(sc[0][jn], qa[0][ks], b0, b1);
                    mma_f16(sc[1][jn], qa[1][ks], b0, b1);
                }
            }

            // ---- online softmax (raw units, KDEC folded into EX2 feed) ----
            uint32_t pa[2][2][4];
            #pragma unroll
            for (int mt = 0; mt < 2; mt++) {
                float mx0 = sc[mt][0][0], mx1 = sc[mt][0][2];
                #pragma unroll
                for (int jn = 0; jn < 4; jn++) {
                    mx0 = fmaxf(mx0, fmaxf(sc[mt][jn][0], sc[mt][jn][1]));
                    mx1 = fmaxf(mx1, fmaxf(sc[mt][jn][2], sc[mt][jn][3]));
                }
                mx0 = fmaxf(mx0, __shfl_xor_sync(0xffffffffu, mx0, 1));
                mx0 = fmaxf(mx0, __shfl_xor_sync(0xffffffffu, mx0, 2));
                mx1 = fmaxf(mx1, __shfl_xor_sync(0xffffffffu, mx1, 1));
                mx1 = fmaxf(mx1, __shfl_xor_sync(0xffffffffu, mx1, 2));
                float nm0 = fmaxf(m[mt][0], mx0), nm1 = fmaxf(m[mt][1], mx1);
                float c0 = exp2f((m[mt][0] - nm0) * KDEC);
                float c1 = exp2f((m[mt][1] - nm1) * KDEC);
                m[mt][0] = nm0; m[mt][1] = nm1;
                #pragma unroll
                for (int nd = 0; nd < 4; nd++) {
                    o[mt][nd][0] *= c0; o[mt][nd][1] *= c0;
                    o[mt][nd][2] *= c1; o[mt][nd][3] *= c1;
                }
                lacc[mt][0] *= c0; lacc[mt][2] *= c1;
                float mK0 = -nm0 * KDEC, mK1 = -nm1 * KDEC;
                #pragma unroll
                for (int kk = 0; kk < 2; kk++) {
                    pa[mt][kk][0] = ex2_h2(fmaf(sc[mt][2*kk][0],   KDEC, mK0),
                                           fmaf(sc[mt][2*kk][1],   KDEC, mK0));
                    pa[mt][kk][1] = ex2_h2(fmaf(sc[mt][2*kk][2],   KDEC, mK1),
                                           fmaf(sc[mt][2*kk][3],   KDEC, mK1));
                    pa[mt][kk][2] = ex2_h2(fmaf(sc[mt][2*kk+1][0], KDEC, mK0),
                                           fmaf(sc[mt][2*kk+1][1], KDEC, mK0));
                    pa[mt][kk][3] = ex2_h2(fmaf(sc[mt][2*kk+1][2], KDEC, mK1),
                                           fmaf(sc[mt][2*kk+1][3], KDEC, mK1));
                }
                #pragma unroll
                for (int kk = 0; kk < 2; kk++)
                    mma_f16(lacc[mt], pa[mt][kk], ONES_H2, ONES_H2);
            }

            // ---- O += P V ----
            #pragma unroll
            for (int ndp = 0; ndp < 2; ndp++)
                #pragma unroll
                for (int kk = 0; kk < 2; kk++) {
                    uint32_t vb[4];
                    int key = sh * 32 + kk * 16 + (lane & 15);
                    int kch = ndp * 2 + (lane >> 4);
                    ldsm4t(vb, vS[s] + swz(key, kch));
                    #pragma unroll
                    for (int mt = 0; mt < 2; mt++) {
                        mma_f16(o[mt][ndp * 2],     pa[mt][kk], vb[0], vb[1]);
                        mma_f16(o[mt][ndp * 2 + 1], pa[mt][kk], vb[2], vb[3]);
                    }
                }
        }
        __syncthreads();
    }

    // finalize
    #pragma unroll
    for (int mt = 0; mt < 2; mt++) {
        float i0 = 1.f / lacc[mt][0], i1 = 1.f / lacc[mt][2];
        __half* op0 = g_att + ((size_t)b * NTOK + q0 + mt * 16 + g) * DIM + h * HD;
        __half* op8 = op0 + (size_t)8 * DIM;
        #pragma unroll
        for (int nd = 0; nd < 4; nd++) {
            *(uint32_t*)(op0 + nd * 8 + 2 * t)
                = pack_half2(o[mt][nd][0] * i0, o[mt][nd][1] * i0);
            *(uint32_t*)(op8 + nd * 8 + 2 * t)
                = pack_half2(o[mt][nd][2] * i1, o[mt][nd][3] * i1);
        }
    }
}

// ---------------- launch ----------------
extern "C" void kernel_launch(void* const* d_in, const int* in_sizes, int n_in,
                              void* d_out, int out_size) {
    const float* x      = (const float*)d_in[0];
    const float* mask   = (const float*)d_in[1];
    const float* qkv_w  = (const float*)d_in[2];
    const float* proj_w = (const float*)d_in[3];
    const float* proj_b = (const float*)d_in[4];
    const float* cpb_w1 = (const float*)d_in[5];
    const float* cpb_b1 = (const float*)d_in[6];
    const float* cpb_w2 = (const float*)d_in[7];
    const float* rpb    = (const float*)d_in[8];
    const int*   rpb_idx = (const int*)d_in[9];
    float* out = (float*)d_out;

    static __half *p_xh = nullptr, *p_qkvw = nullptr, *p_projw = nullptr,
                  *p_qkv = nullptr, *p_att = nullptr;
    if (!p_xh) {
        cudaGetSymbolAddress((void**)&p_xh, g_xh);
        cudaGetSymbolAddress((void**)&p_qkvw, g_qkvw);
        cudaGetSymbolAddress((void**)&p_projw, g_projw);
        cudaGetSymbolAddress((void**)&p_qkv, g_qkv);
        cudaGetSymbolAddress((void**)&p_att, g_att);
        cudaFuncSetAttribute(gemm_h,
                             cudaFuncAttributeMaxDynamicSharedMemorySize, GSMEM);
    }

    prep0<<<NCVT_BLK + TABLE_E, 256>>>(x, qkv_w, proj_w,
                                       rpb, cpb_w1, cpb_b1, cpb_w2);
    prep1<<<4096 + 32768 / 256, 256>>>(mask, rpb_idx);
    {
        dim3 grid(QKV_LD / 128, (BATCH * NTOK) / 128);
        gemm_h<<<grid, 128, GSMEM>>>(p_xh, p_qkvw, nullptr, p_qkv,
                                     BATCH * NTOK, QKV_LD, DIM, 0,
                                     DIM, SCALE2 * RAWK);
    }
    attn_h<<<dim3(NTOK / 128, NH, BATCH), 128>>>();
    {
        dim3 grid(DIM / 128, (BATCH * NTOK) / 128);
        gemm_h<<<grid, 128, GSMEM>>>(p_att, p_projw, proj_b, out,
                                     BATCH * NTOK, DIM, DIM, 1, 0, 1.f);
    }
}